// round 1
// baseline (speedup 1.0000x reference)
#include <cuda_runtime.h>
#include <math.h>

#define NMAX 100000
#define KNBR 16
#define PPB 16

// Scratch (static __device__ — allocation-guard safe)
__device__ float g_bufA[NMAX * 384];   // up to N x 384
__device__ float g_bufB[NMAX * 256];   // up to N x 256
__device__ float g_bufC[NMAX * 512];   // up to N x 512

// ---------------------------------------------------------------------------
// Generic fused GEMM: C = act(A[M,K] @ W[K,O] + bias[O] (+ res))
// act: 0 = none, 1 = relu, 2 = leaky_relu(x + res, 0.01)
// Requires K % 16 == 0, O % 64 == 0.
// ---------------------------------------------------------------------------
#define BM 64
#define BN 64
#define BKT 16

__global__ __launch_bounds__(256) void gemm_kernel(
    const float* __restrict__ A, const float* __restrict__ W,
    const float* __restrict__ bias, const float* __restrict__ res,
    float* __restrict__ C, int M, int K, int O, int act)
{
    __shared__ float As[BKT][BM + 4];
    __shared__ float Bs[BKT][BN];

    int tid = threadIdx.x;
    int bm = blockIdx.x * BM, bn = blockIdx.y * BN;
    int tx = tid & 15, ty = tid >> 4;
    int arow = tid >> 2, acol = (tid & 3) * 4;
    int brow = tid >> 4, bcol = (tid & 15) * 4;
    bool aval = (bm + arow) < M;

    float acc[4][4];
#pragma unroll
    for (int i = 0; i < 4; i++)
#pragma unroll
        for (int j = 0; j < 4; j++) acc[i][j] = 0.f;

    for (int k0 = 0; k0 < K; k0 += BKT) {
        float4 av = make_float4(0.f, 0.f, 0.f, 0.f);
        if (aval)
            av = *(const float4*)(A + (size_t)(bm + arow) * K + k0 + acol);
        As[acol + 0][arow] = av.x;
        As[acol + 1][arow] = av.y;
        As[acol + 2][arow] = av.z;
        As[acol + 3][arow] = av.w;

        float4 bv = *(const float4*)(W + (size_t)(k0 + brow) * O + bn + bcol);
        *(float4*)&Bs[brow][bcol] = bv;
        __syncthreads();

#pragma unroll
        for (int kk = 0; kk < BKT; kk++) {
            float4 a = *(const float4*)&As[kk][ty * 4];
            float4 b = *(const float4*)&Bs[kk][tx * 4];
            acc[0][0] = fmaf(a.x, b.x, acc[0][0]);
            acc[0][1] = fmaf(a.x, b.y, acc[0][1]);
            acc[0][2] = fmaf(a.x, b.z, acc[0][2]);
            acc[0][3] = fmaf(a.x, b.w, acc[0][3]);
            acc[1][0] = fmaf(a.y, b.x, acc[1][0]);
            acc[1][1] = fmaf(a.y, b.y, acc[1][1]);
            acc[1][2] = fmaf(a.y, b.z, acc[1][2]);
            acc[1][3] = fmaf(a.y, b.w, acc[1][3]);
            acc[2][0] = fmaf(a.z, b.x, acc[2][0]);
            acc[2][1] = fmaf(a.z, b.y, acc[2][1]);
            acc[2][2] = fmaf(a.z, b.z, acc[2][2]);
            acc[2][3] = fmaf(a.z, b.w, acc[2][3]);
            acc[3][0] = fmaf(a.w, b.x, acc[3][0]);
            acc[3][1] = fmaf(a.w, b.y, acc[3][1]);
            acc[3][2] = fmaf(a.w, b.z, acc[3][2]);
            acc[3][3] = fmaf(a.w, b.w, acc[3][3]);
        }
        __syncthreads();
    }

    int col = bn + tx * 4;
    float4 b4 = *(const float4*)(bias + col);
#pragma unroll
    for (int i = 0; i < 4; i++) {
        int row = bm + ty * 4 + i;
        if (row >= M) continue;
        float4 v = make_float4(acc[i][0] + b4.x, acc[i][1] + b4.y,
                               acc[i][2] + b4.z, acc[i][3] + b4.w);
        if (act == 1) {
            v.x = fmaxf(v.x, 0.f); v.y = fmaxf(v.y, 0.f);
            v.z = fmaxf(v.z, 0.f); v.w = fmaxf(v.w, 0.f);
        } else if (act == 2) {
            float4 r = *(const float4*)(res + (size_t)row * O + col);
            v.x += r.x; v.y += r.y; v.z += r.z; v.w += r.w;
            v.x = (v.x > 0.f) ? v.x : 0.01f * v.x;
            v.y = (v.y > 0.f) ? v.y : 0.01f * v.y;
            v.z = (v.z > 0.f) ? v.z : 0.01f * v.z;
            v.w = (v.w > 0.f) ? v.w : 0.01f * v.w;
        }
        *(float4*)(C + (size_t)row * O + col) = v;
    }
}

// ---------------------------------------------------------------------------
// Fused LSE + attentive-pool stage 1 (everything up to the p-MLP):
// For each point n, each neighbor k:
//   concat10 = [orig(3), nbr(3), rel(3), |rel|] -> relu(@W1[10,64]+b1) -> @W2[64,128]+b2 = enc
//   row256 = [enc(128), feats(128)]; scores = softmax over 256 channels
//   f[n, c] = sum_k scores[k,c] * row256[k,c]          (output: N x 256)
// Block: 256 threads, PPB points; warp w handles k = w and k = w+8.
// ---------------------------------------------------------------------------
__global__ __launch_bounds__(256) void lse_kernel(
    const float* __restrict__ coords, const int* __restrict__ nidx,
    const float* __restrict__ feats,
    const float* __restrict__ W1, const float* __restrict__ B1,
    const float* __restrict__ W2, const float* __restrict__ B2,
    float* __restrict__ outF, int N)
{
    __shared__ float sW1[640];        // 10 x 64
    __shared__ float sB1[64];
    __shared__ float sW2[64 * 128];   // 32 KB
    __shared__ float sB2[128];
    __shared__ float sFeat[128];
    __shared__ float sFpart[8 * 256]; // per-warp partial f

    int tid = threadIdx.x, lane = tid & 31, wid = tid >> 5;

    for (int i = tid; i < 640; i += 256) sW1[i] = W1[i];
    if (tid < 64) sB1[tid] = B1[tid];
    for (int i = tid; i < 2048; i += 256)
        ((float4*)sW2)[i] = ((const float4*)W2)[i];
    if (tid < 128) sB2[tid] = B2[tid];
    __syncthreads();

    int n0 = blockIdx.x * PPB;
    for (int p = 0; p < PPB; p++) {
        int n = n0 + p;
        if (n >= N) break;
        if (tid < 32)
            ((float4*)sFeat)[tid] = ((const float4*)(feats + (size_t)n * 128))[tid];
        __syncthreads();

        float ox = coords[n * 3 + 0], oy = coords[n * 3 + 1], oz = coords[n * 3 + 2];
        float fAcc[8];
#pragma unroll
        for (int i = 0; i < 8; i++) fAcc[i] = 0.f;

        for (int kk2 = 0; kk2 < 2; kk2++) {
            int k = wid + kk2 * 8;
            int nb = nidx[(size_t)n * KNBR + k];
            float nx = coords[nb * 3 + 0], ny = coords[nb * 3 + 1], nz = coords[nb * 3 + 2];
            float rx = ox - nx, ry = oy - ny, rz = oz - nz;
            float d = sqrtf(rx * rx + ry * ry + rz * rz);
            float c10[10] = {ox, oy, oz, nx, ny, nz, rx, ry, rz, d};

            // hidden: h[j] for j = lane, lane+32
            float h0 = sB1[lane], h1 = sB1[lane + 32];
#pragma unroll
            for (int i = 0; i < 10; i++) {
                float ci = c10[i];
                h0 = fmaf(ci, sW1[i * 64 + lane], h0);
                h1 = fmaf(ci, sW1[i * 64 + 32 + lane], h1);
            }
            h0 = fmaxf(h0, 0.f);
            h1 = fmaxf(h1, 0.f);

            // enc channels 4*lane .. 4*lane+3
            float4 acc = ((const float4*)sB2)[lane];
            const float4* W2v = (const float4*)sW2;
#pragma unroll
            for (int j = 0; j < 32; j++) {
                float hj = __shfl_sync(0xffffffffu, h0, j);
                float4 w = W2v[j * 32 + lane];
                acc.x = fmaf(hj, w.x, acc.x);
                acc.y = fmaf(hj, w.y, acc.y);
                acc.z = fmaf(hj, w.z, acc.z);
                acc.w = fmaf(hj, w.w, acc.w);
            }
#pragma unroll
            for (int j = 0; j < 32; j++) {
                float hj = __shfl_sync(0xffffffffu, h1, j);
                float4 w = W2v[(j + 32) * 32 + lane];
                acc.x = fmaf(hj, w.x, acc.x);
                acc.y = fmaf(hj, w.y, acc.y);
                acc.z = fmaf(hj, w.z, acc.z);
                acc.w = fmaf(hj, w.w, acc.w);
            }

            float4 fv = ((const float4*)sFeat)[lane];
            float v[8] = {acc.x, acc.y, acc.z, acc.w, fv.x, fv.y, fv.z, fv.w};

            float m = v[0];
#pragma unroll
            for (int i = 1; i < 8; i++) m = fmaxf(m, v[i]);
#pragma unroll
            for (int o = 16; o > 0; o >>= 1)
                m = fmaxf(m, __shfl_xor_sync(0xffffffffu, m, o));

            float e[8], s = 0.f;
#pragma unroll
            for (int i = 0; i < 8; i++) { e[i] = __expf(v[i] - m); s += e[i]; }
#pragma unroll
            for (int o = 16; o > 0; o >>= 1)
                s += __shfl_xor_sync(0xffffffffu, s, o);
            float inv = 1.f / s;
#pragma unroll
            for (int i = 0; i < 8; i++)
                fAcc[i] = fmaf(e[i] * inv, v[i], fAcc[i]);
        }

        ((float4*)(sFpart + wid * 256))[lane] =
            make_float4(fAcc[0], fAcc[1], fAcc[2], fAcc[3]);
        ((float4*)(sFpart + wid * 256))[32 + lane] =
            make_float4(fAcc[4], fAcc[5], fAcc[6], fAcc[7]);
        __syncthreads();

        float s = 0.f;
#pragma unroll
        for (int w = 0; w < 8; w++) s += sFpart[w * 256 + tid];
        outF[(size_t)n * 256 + tid] = s;
        __syncthreads();
    }
}

// ---------------------------------------------------------------------------
extern "C" void kernel_launch(void* const* d_in, const int* in_sizes, int n_in,
                              void* d_out, int out_size)
{
    const float* coords   = (const float*)d_in[0];
    const float* features = (const float*)d_in[1];
    const int*   nidx     = (const int*)d_in[2];
    const float* m1W1 = (const float*)d_in[3];  const float* m1b1 = (const float*)d_in[4];
    const float* m1W2 = (const float*)d_in[5];  const float* m1b2 = (const float*)d_in[6];
    const float* m2W1 = (const float*)d_in[7];  const float* m2b1 = (const float*)d_in[8];
    const float* m2W2 = (const float*)d_in[9];  const float* m2b2 = (const float*)d_in[10];
    const float* m3W1 = (const float*)d_in[11]; const float* m3b1 = (const float*)d_in[12];
    const float* m3W2 = (const float*)d_in[13]; const float* m3b2 = (const float*)d_in[14];
    const float* l1W1 = (const float*)d_in[15]; const float* l1b1 = (const float*)d_in[16];
    const float* l1W2 = (const float*)d_in[17]; const float* l1b2 = (const float*)d_in[18];
    const float* l2W1 = (const float*)d_in[19]; const float* l2b1 = (const float*)d_in[20];
    const float* l2W2 = (const float*)d_in[21]; const float* l2b2 = (const float*)d_in[22];
    const float* p1W1 = (const float*)d_in[23]; const float* p1b1 = (const float*)d_in[24];
    const float* p1W2 = (const float*)d_in[25]; const float* p1b2 = (const float*)d_in[26];
    const float* p2W1 = (const float*)d_in[27]; const float* p2b1 = (const float*)d_in[28];
    const float* p2W2 = (const float*)d_in[29]; const float* p2b2 = (const float*)d_in[30];
    float* out = (float*)d_out;

    int N = in_sizes[0] / 3;

    float *bufA, *bufB, *bufC;
    cudaGetSymbolAddress((void**)&bufA, g_bufA);
    cudaGetSymbolAddress((void**)&bufB, g_bufB);
    cudaGetSymbolAddress((void**)&bufC, g_bufC);

    dim3 blk(256);
    auto grid = [&](int M, int O) { return dim3((M + BM - 1) / BM, O / BN); };
    int lse_grid = (N + PPB - 1) / PPB;

    // x = mlp1(features): 128 -> 128 -> 128
    gemm_kernel<<<grid(N, 128), blk>>>(features, m1W1, m1b1, nullptr, bufA, N, 128, 128, 1);
    gemm_kernel<<<grid(N, 128), blk>>>(bufA,     m1W2, m1b2, nullptr, bufB, N, 128, 128, 0);
    // lse1 + channel-softmax pool -> f1 (N,256)
    lse_kernel<<<lse_grid, blk>>>(coords, nidx, bufB, l1W1, l1b1, l1W2, l1b2, bufA, N);
    // p1: 256 -> 256 -> 128
    gemm_kernel<<<grid(N, 256), blk>>>(bufA, p1W1, p1b1, nullptr, bufC, N, 256, 256, 1);
    gemm_kernel<<<grid(N, 128), blk>>>(bufC, p1W2, p1b2, nullptr, bufB, N, 256, 128, 0);
    // lse2 -> f2 (N,256)
    lse_kernel<<<lse_grid, blk>>>(coords, nidx, bufB, l2W1, l2b1, l2W2, l2b2, bufA, N);
    // p2: 256 -> 256 -> 256
    gemm_kernel<<<grid(N, 256), blk>>>(bufA, p2W1, p2b1, nullptr, bufC, N, 256, 256, 1);
    gemm_kernel<<<grid(N, 256), blk>>>(bufC, p2W2, p2b2, nullptr, bufB, N, 256, 256, 0);
    // m3(features): 128 -> 256 -> 512
    gemm_kernel<<<grid(N, 256), blk>>>(features, m3W1, m3b1, nullptr, bufA, N, 128, 256, 1);
    gemm_kernel<<<grid(N, 512), blk>>>(bufA,     m3W2, m3b2, nullptr, bufC, N, 256, 512, 0);
    // m2(x): 256 -> 384 -> 512, fused residual(+m3) + leaky_relu
    gemm_kernel<<<grid(N, 384), blk>>>(bufB, m2W1, m2b1, nullptr, bufA, N, 256, 384, 1);
    gemm_kernel<<<grid(N, 512), blk>>>(bufA, m2W2, m2b2, bufC,    out,  N, 384, 512, 2);
}

// round 2
// speedup vs baseline: 2.5572x; 2.5572x over previous
#include <cuda_runtime.h>
#include <math.h>

#define NMAX 100000
#define KNBR 16
#define PPB 16

// Scratch (static __device__ — allocation-guard safe)
__device__ float g_bufA[NMAX * 384];
__device__ float g_bufB[NMAX * 256];
__device__ float g_bufC[NMAX * 512];

// ---------------------------------------------------------------------------
// GEMM: C = act(A[M,K] @ W[K,O] + bias[O] (+ res))
// act: 0 = none, 1 = relu, 2 = leaky_relu(x + res, 0.01)
// 128x128x16 tile, 8x8 per thread, 256 threads, register-staged prefetch.
// Requires K % 16 == 0, O % 128 == 0.
// ---------------------------------------------------------------------------
#define BM2 128
#define BN2 128
#define BK2 16

__global__ __launch_bounds__(256) void gemm_kernel(
    const float* __restrict__ A, const float* __restrict__ W,
    const float* __restrict__ bias, const float* __restrict__ res,
    float* __restrict__ C, int M, int K, int O, int act)
{
    __shared__ float As[BK2][BM2 + 4];
    __shared__ float Bs[BK2][BN2];

    int tid = threadIdx.x;
    int bm = blockIdx.x * BM2, bn = blockIdx.y * BN2;
    int tx = tid & 15, ty = tid >> 4;

    // A loader: rows ar, ar+64; cols ac..ac+3
    int ar = tid >> 2;
    int ac = (tid & 3) * 4;
    // B loader: rows br, br+8; cols bc..bc+3
    int br = tid >> 5;
    int bc = (tid & 31) * 4;

    const float* Aptr = A + (size_t)(bm + ar) * K + ac;
    const float* Bptr = W + (size_t)br * O + bn + bc;
    bool av0 = (bm + ar) < M;
    bool av1 = (bm + ar + 64) < M;

    float acc[8][8];
#pragma unroll
    for (int i = 0; i < 8; i++)
#pragma unroll
        for (int j = 0; j < 8; j++) acc[i][j] = 0.f;

    float4 ra0 = make_float4(0.f, 0.f, 0.f, 0.f), ra1 = ra0, rb0, rb1;
    if (av0) ra0 = *(const float4*)Aptr;
    if (av1) ra1 = *(const float4*)(Aptr + (size_t)64 * K);
    rb0 = *(const float4*)Bptr;
    rb1 = *(const float4*)(Bptr + (size_t)8 * O);

    int nk = K / BK2;
    for (int kt = 0; kt < nk; kt++) {
        As[ac + 0][ar] = ra0.x; As[ac + 1][ar] = ra0.y;
        As[ac + 2][ar] = ra0.z; As[ac + 3][ar] = ra0.w;
        As[ac + 0][ar + 64] = ra1.x; As[ac + 1][ar + 64] = ra1.y;
        As[ac + 2][ar + 64] = ra1.z; As[ac + 3][ar + 64] = ra1.w;
        *(float4*)&Bs[br][bc] = rb0;
        *(float4*)&Bs[br + 8][bc] = rb1;
        __syncthreads();

        if (kt + 1 < nk) {
            const float* An = Aptr + (kt + 1) * BK2;
            ra0 = make_float4(0.f, 0.f, 0.f, 0.f); ra1 = ra0;
            if (av0) ra0 = *(const float4*)An;
            if (av1) ra1 = *(const float4*)(An + (size_t)64 * K);
            const float* Bn = Bptr + (size_t)(kt + 1) * BK2 * O;
            rb0 = *(const float4*)Bn;
            rb1 = *(const float4*)(Bn + (size_t)8 * O);
        }

#pragma unroll
        for (int kk = 0; kk < BK2; kk++) {
            float4 xa0 = *(const float4*)&As[kk][ty * 4];
            float4 xa1 = *(const float4*)&As[kk][64 + ty * 4];
            float4 xb0 = *(const float4*)&Bs[kk][tx * 4];
            float4 xb1 = *(const float4*)&Bs[kk][64 + tx * 4];
            float a[8] = {xa0.x, xa0.y, xa0.z, xa0.w, xa1.x, xa1.y, xa1.z, xa1.w};
            float b[8] = {xb0.x, xb0.y, xb0.z, xb0.w, xb1.x, xb1.y, xb1.z, xb1.w};
#pragma unroll
            for (int i = 0; i < 8; i++)
#pragma unroll
                for (int j = 0; j < 8; j++)
                    acc[i][j] = fmaf(a[i], b[j], acc[i][j]);
        }
        __syncthreads();
    }

    // epilogue
#pragma unroll
    for (int jh = 0; jh < 2; jh++) {
        int col = bn + jh * 64 + tx * 4;
        float4 b4 = *(const float4*)(bias + col);
#pragma unroll
        for (int i = 0; i < 8; i++) {
            int row = bm + ty * 4 + (i & 3) + (i >> 2) * 64;
            if (row >= M) continue;
            float4 v = make_float4(acc[i][jh * 4 + 0] + b4.x,
                                   acc[i][jh * 4 + 1] + b4.y,
                                   acc[i][jh * 4 + 2] + b4.z,
                                   acc[i][jh * 4 + 3] + b4.w);
            if (act == 1) {
                v.x = fmaxf(v.x, 0.f); v.y = fmaxf(v.y, 0.f);
                v.z = fmaxf(v.z, 0.f); v.w = fmaxf(v.w, 0.f);
            } else if (act == 2) {
                float4 r = *(const float4*)(res + (size_t)row * O + col);
                v.x += r.x; v.y += r.y; v.z += r.z; v.w += r.w;
                v.x = (v.x > 0.f) ? v.x : 0.01f * v.x;
                v.y = (v.y > 0.f) ? v.y : 0.01f * v.y;
                v.z = (v.z > 0.f) ? v.z : 0.01f * v.z;
                v.w = (v.w > 0.f) ? v.w : 0.01f * v.w;
            }
            *(float4*)(C + (size_t)row * O + col) = v;
        }
    }
}

// ---------------------------------------------------------------------------
// Fused LSE + attentive pool. Block = 256 threads (8 warps), PPB points,
// processed 2 points at a time; warp w owns pairs:
//   (pA, w), (pA, w+8), (pB, w), (pB, w+8)
// so each W2 shared float4 read is reused by 16 FMAs.
// ---------------------------------------------------------------------------
#define LSE_SMEM_FLOATS (640 + 64 + 8192 + 128 + 256 + 2048 + 2048)
#define LSE_SMEM_BYTES  (LSE_SMEM_FLOATS * 4)

__global__ __launch_bounds__(256) void lse_kernel(
    const float* __restrict__ coords, const int* __restrict__ nidx,
    const float* __restrict__ feats,
    const float* __restrict__ W1, const float* __restrict__ B1,
    const float* __restrict__ W2, const float* __restrict__ B2,
    float* __restrict__ outF, int N)
{
    extern __shared__ float sm[];
    float* sW1   = sm;               // 640   (10 x 64)
    float* sB1   = sW1 + 640;        // 64
    float* sW2   = sB1 + 64;         // 8192  (64 x 128)
    float* sB2   = sW2 + 8192;       // 128
    float* sFeat = sB2 + 128;        // 256   (2 points x 128)
    float* sH    = sFeat + 256;      // 2048  (8 warps x 4 pairs x 64)
    float* sFp   = sH + 2048;        // 2048  (8 warps x 256)

    int tid = threadIdx.x, lane = tid & 31, wid = tid >> 5;

    for (int i = tid; i < 640; i += 256) sW1[i] = W1[i];
    if (tid < 64) sB1[tid] = B1[tid];
    for (int i = tid; i < 2048; i += 256)
        ((float4*)sW2)[i] = ((const float4*)W2)[i];
    if (tid < 128) sB2[tid] = B2[tid];
    __syncthreads();

    const float4* W2v = (const float4*)sW2;
    float* sHw = sH + wid * 256;
    const float4* Hv = (const float4*)sHw;

    int n0 = blockIdx.x * PPB;
    for (int p = 0; p < PPB; p += 2) {
        int nA = n0 + p, nB = nA + 1;
        bool vA = nA < N, vB = nB < N;

        if (tid < 64) {
            int pt = tid >> 5, q = tid & 31;
            int nn = pt ? nB : nA;
            float4 f = make_float4(0.f, 0.f, 0.f, 0.f);
            if (pt ? vB : vA)
                f = ((const float4*)(feats + (size_t)nn * 128))[q];
            ((float4*)sFeat)[tid] = f;
        }
        __syncthreads();

        // hidden layer for 4 pairs -> shared h
#pragma unroll
        for (int pr = 0; pr < 4; pr++) {
            int pt = pr >> 1;
            int n = pt ? nB : nA;
            bool vv = pt ? vB : vA;
            int nsafe = vv ? n : 0;
            int k = wid + (pr & 1) * 8;
            int nb = nidx[(size_t)nsafe * KNBR + k];
            float ox = coords[nsafe * 3 + 0], oy = coords[nsafe * 3 + 1], oz = coords[nsafe * 3 + 2];
            float nx = coords[nb * 3 + 0], ny = coords[nb * 3 + 1], nz = coords[nb * 3 + 2];
            float rx = ox - nx, ry = oy - ny, rz = oz - nz;
            float d = sqrtf(rx * rx + ry * ry + rz * rz);
            float c10[10] = {ox, oy, oz, nx, ny, nz, rx, ry, rz, d};
            float h0 = sB1[lane], h1 = sB1[lane + 32];
#pragma unroll
            for (int i = 0; i < 10; i++) {
                float ci = c10[i];
                h0 = fmaf(ci, sW1[i * 64 + lane], h0);
                h1 = fmaf(ci, sW1[i * 64 + 32 + lane], h1);
            }
            sHw[pr * 64 + lane] = fmaxf(h0, 0.f);
            sHw[pr * 64 + 32 + lane] = fmaxf(h1, 0.f);
        }
        __syncwarp();

        // second layer: 4 pairs share every W2 read
        float4 bi = ((const float4*)sB2)[lane];
        float4 acc[4];
        acc[0] = bi; acc[1] = bi; acc[2] = bi; acc[3] = bi;
#pragma unroll
        for (int jj = 0; jj < 16; jj++) {
            float4 w0 = W2v[(jj * 4 + 0) * 32 + lane];
            float4 w1 = W2v[(jj * 4 + 1) * 32 + lane];
            float4 w2 = W2v[(jj * 4 + 2) * 32 + lane];
            float4 w3 = W2v[(jj * 4 + 3) * 32 + lane];
#pragma unroll
            for (int pr = 0; pr < 4; pr++) {
                float4 h = Hv[pr * 16 + jj];
                acc[pr].x = fmaf(h.x, w0.x, acc[pr].x);
                acc[pr].y = fmaf(h.x, w0.y, acc[pr].y);
                acc[pr].z = fmaf(h.x, w0.z, acc[pr].z);
                acc[pr].w = fmaf(h.x, w0.w, acc[pr].w);
                acc[pr].x = fmaf(h.y, w1.x, acc[pr].x);
                acc[pr].y = fmaf(h.y, w1.y, acc[pr].y);
                acc[pr].z = fmaf(h.y, w1.z, acc[pr].z);
                acc[pr].w = fmaf(h.y, w1.w, acc[pr].w);
                acc[pr].x = fmaf(h.z, w2.x, acc[pr].x);
                acc[pr].y = fmaf(h.z, w2.y, acc[pr].y);
                acc[pr].z = fmaf(h.z, w2.z, acc[pr].z);
                acc[pr].w = fmaf(h.z, w2.w, acc[pr].w);
                acc[pr].x = fmaf(h.w, w3.x, acc[pr].x);
                acc[pr].y = fmaf(h.w, w3.y, acc[pr].y);
                acc[pr].z = fmaf(h.w, w3.z, acc[pr].z);
                acc[pr].w = fmaf(h.w, w3.w, acc[pr].w);
            }
        }

        // softmax over 256 channels per pair + weighted pool
        float fAcc[2][8];
#pragma unroll
        for (int pt = 0; pt < 2; pt++)
#pragma unroll
            for (int q = 0; q < 8; q++) fAcc[pt][q] = 0.f;

#pragma unroll
        for (int pr = 0; pr < 4; pr++) {
            int pt = pr >> 1;
            float4 fv = ((const float4*)sFeat)[pt * 32 + lane];
            float v[8] = {acc[pr].x, acc[pr].y, acc[pr].z, acc[pr].w,
                          fv.x, fv.y, fv.z, fv.w};
            float m = v[0];
#pragma unroll
            for (int i = 1; i < 8; i++) m = fmaxf(m, v[i]);
#pragma unroll
            for (int o = 16; o > 0; o >>= 1)
                m = fmaxf(m, __shfl_xor_sync(0xffffffffu, m, o));
            float e[8], s = 0.f;
#pragma unroll
            for (int i = 0; i < 8; i++) { e[i] = __expf(v[i] - m); s += e[i]; }
#pragma unroll
            for (int o = 16; o > 0; o >>= 1)
                s += __shfl_xor_sync(0xffffffffu, s, o);
            float inv = 1.f / s;
#pragma unroll
            for (int i = 0; i < 8; i++)
                fAcc[pt][i] = fmaf(e[i] * inv, v[i], fAcc[pt][i]);
        }

        // block reduce per point
#pragma unroll
        for (int pt = 0; pt < 2; pt++) {
            __syncthreads();
            ((float4*)(sFp + wid * 256))[lane] =
                make_float4(fAcc[pt][0], fAcc[pt][1], fAcc[pt][2], fAcc[pt][3]);
            ((float4*)(sFp + wid * 256))[32 + lane] =
                make_float4(fAcc[pt][4], fAcc[pt][5], fAcc[pt][6], fAcc[pt][7]);
            __syncthreads();
            float s = 0.f;
#pragma unroll
            for (int w = 0; w < 8; w++) s += sFp[w * 256 + tid];
            int n = pt ? nB : nA;
            if (pt ? vB : vA)
                outF[(size_t)n * 256 + tid] = s;
        }
        __syncthreads();
    }
}

// ---------------------------------------------------------------------------
extern "C" void kernel_launch(void* const* d_in, const int* in_sizes, int n_in,
                              void* d_out, int out_size)
{
    const float* coords   = (const float*)d_in[0];
    const float* features = (const float*)d_in[1];
    const int*   nidx     = (const int*)d_in[2];
    const float* m1W1 = (const float*)d_in[3];  const float* m1b1 = (const float*)d_in[4];
    const float* m1W2 = (const float*)d_in[5];  const float* m1b2 = (const float*)d_in[6];
    const float* m2W1 = (const float*)d_in[7];  const float* m2b1 = (const float*)d_in[8];
    const float* m2W2 = (const float*)d_in[9];  const float* m2b2 = (const float*)d_in[10];
    const float* m3W1 = (const float*)d_in[11]; const float* m3b1 = (const float*)d_in[12];
    const float* m3W2 = (const float*)d_in[13]; const float* m3b2 = (const float*)d_in[14];
    const float* l1W1 = (const float*)d_in[15]; const float* l1b1 = (const float*)d_in[16];
    const float* l1W2 = (const float*)d_in[17]; const float* l1b2 = (const float*)d_in[18];
    const float* l2W1 = (const float*)d_in[19]; const float* l2b1 = (const float*)d_in[20];
    const float* l2W2 = (const float*)d_in[21]; const float* l2b2 = (const float*)d_in[22];
    const float* p1W1 = (const float*)d_in[23]; const float* p1b1 = (const float*)d_in[24];
    const float* p1W2 = (const float*)d_in[25]; const float* p1b2 = (const float*)d_in[26];
    const float* p2W1 = (const float*)d_in[27]; const float* p2b1 = (const float*)d_in[28];
    const float* p2W2 = (const float*)d_in[29]; const float* p2b2 = (const float*)d_in[30];
    float* out = (float*)d_out;

    int N = in_sizes[0] / 3;

    float *bufA, *bufB, *bufC;
    cudaGetSymbolAddress((void**)&bufA, g_bufA);
    cudaGetSymbolAddress((void**)&bufB, g_bufB);
    cudaGetSymbolAddress((void**)&bufC, g_bufC);

    static int attr_set = 0;
    if (!attr_set) {
        cudaFuncSetAttribute(lse_kernel,
                             cudaFuncAttributeMaxDynamicSharedMemorySize,
                             LSE_SMEM_BYTES);
        attr_set = 1;
    }

    dim3 blk(256);
    auto grid = [&](int M, int O) { return dim3((M + BM2 - 1) / BM2, O / BN2); };
    int lse_grid = (N + PPB - 1) / PPB;

    // x = mlp1(features): 128 -> 128 -> 128
    gemm_kernel<<<grid(N, 128), blk>>>(features, m1W1, m1b1, nullptr, bufA, N, 128, 128, 1);
    gemm_kernel<<<grid(N, 128), blk>>>(bufA,     m1W2, m1b2, nullptr, bufB, N, 128, 128, 0);
    // lse1 + channel-softmax pool -> (N,256)
    lse_kernel<<<lse_grid, blk, LSE_SMEM_BYTES>>>(coords, nidx, bufB, l1W1, l1b1, l1W2, l1b2, bufA, N);
    // p1: 256 -> 256 -> 128
    gemm_kernel<<<grid(N, 256), blk>>>(bufA, p1W1, p1b1, nullptr, bufC, N, 256, 256, 1);
    gemm_kernel<<<grid(N, 128), blk>>>(bufC, p1W2, p1b2, nullptr, bufB, N, 256, 128, 0);
    // lse2 -> (N,256)
    lse_kernel<<<lse_grid, blk, LSE_SMEM_BYTES>>>(coords, nidx, bufB, l2W1, l2b1, l2W2, l2b2, bufA, N);
    // p2: 256 -> 256 -> 256
    gemm_kernel<<<grid(N, 256), blk>>>(bufA, p2W1, p2b1, nullptr, bufC, N, 256, 256, 1);
    gemm_kernel<<<grid(N, 256), blk>>>(bufC, p2W2, p2b2, nullptr, bufB, N, 256, 256, 0);
    // m3(features): 128 -> 256 -> 512
    gemm_kernel<<<grid(N, 256), blk>>>(features, m3W1, m3b1, nullptr, bufA, N, 128, 256, 1);
    gemm_kernel<<<grid(N, 512), blk>>>(bufA,     m3W2, m3b2, nullptr, bufC, N, 256, 512, 0);
    // m2(x): 256 -> 384 -> 512, fused residual(+m3) + leaky_relu
    gemm_kernel<<<grid(N, 384), blk>>>(bufB, m2W1, m2b1, nullptr, bufA, N, 256, 384, 1);
    gemm_kernel<<<grid(N, 512), blk>>>(bufA, m2W2, m2b2, bufC,    out,  N, 384, 512, 2);
}

// round 3
// speedup vs baseline: 4.0275x; 1.5750x over previous
#include <cuda_runtime.h>
#include <math.h>
#include <stdint.h>

#define NMAX 100000
#define KNBR 16
#define PPB 16

// Scratch (static __device__ — allocation-guard safe)
__device__ float g_bufA[NMAX * 384];
__device__ float g_bufB[NMAX * 256];
__device__ float g_bufC[NMAX * 512];

__device__ __forceinline__ float to_tf32(float x) {
    float y;
    asm("cvt.rna.tf32.f32 %0, %1;" : "=f"(y) : "f"(x));
    return y;
}

// ---------------------------------------------------------------------------
// Tensor-core GEMM (tf32 mma.sync): C = act(A[M,K] @ W[K,O] + bias (+ res))
// act: 0 = none, 1 = relu, 2 = leaky_relu(x + res, 0.01)
// Block tile 128x128xBK16, 8 warps (4x2), warp tile 32x64 (2x8 m16n8k8 tiles).
// Requires K % 16 == 0, O % 128 == 0.
// ---------------------------------------------------------------------------
#define TBM 128
#define TBN 128
#define TBK 16
#define SSTR 136   // smem row stride (mod 32 == 8 -> conflict-free quad loads)

__global__ __launch_bounds__(256) void tgemm_kernel(
    const float* __restrict__ A, const float* __restrict__ W,
    const float* __restrict__ bias, const float* __restrict__ res,
    float* __restrict__ C, int M, int K, int O, int act)
{
    __shared__ float As[TBK][SSTR];   // [k][m]
    __shared__ float Bs[TBK][SSTR];   // [k][n]

    int tid = threadIdx.x, lane = tid & 31, wid = tid >> 5;
    int bm = blockIdx.x * TBM, bn = blockIdx.y * TBN;
    int wm = wid & 3, wn = wid >> 2;          // warp grid 4 (M) x 2 (N)
    int gid = lane >> 2, tig = lane & 3;

    // A loader: rows ar, ar+64; k-cols ac..ac+3
    int ar = tid >> 2, ac = (tid & 3) * 4;
    // B loader: k-rows br, br+8; n-cols bc..bc+3
    int br = tid >> 5, bc = (tid & 31) * 4;

    const float* Aptr = A + (size_t)(bm + ar) * K + ac;
    const float* Bptr = W + (size_t)br * O + bn + bc;
    bool av0 = (bm + ar) < M;
    bool av1 = (bm + ar + 64) < M;

    float c[2][8][4];
#pragma unroll
    for (int mt = 0; mt < 2; mt++)
#pragma unroll
        for (int nt = 0; nt < 8; nt++)
#pragma unroll
            for (int q = 0; q < 4; q++) c[mt][nt][q] = 0.f;

    float4 ra0 = make_float4(0.f, 0.f, 0.f, 0.f), ra1 = ra0, rb0, rb1;
    if (av0) ra0 = *(const float4*)Aptr;
    if (av1) ra1 = *(const float4*)(Aptr + (size_t)64 * K);
    rb0 = *(const float4*)Bptr;
    rb1 = *(const float4*)(Bptr + (size_t)8 * O);

    int nk = K / TBK;
    for (int kt = 0; kt < nk; kt++) {
        As[ac + 0][ar] = to_tf32(ra0.x);
        As[ac + 1][ar] = to_tf32(ra0.y);
        As[ac + 2][ar] = to_tf32(ra0.z);
        As[ac + 3][ar] = to_tf32(ra0.w);
        As[ac + 0][ar + 64] = to_tf32(ra1.x);
        As[ac + 1][ar + 64] = to_tf32(ra1.y);
        As[ac + 2][ar + 64] = to_tf32(ra1.z);
        As[ac + 3][ar + 64] = to_tf32(ra1.w);
        float4 w0 = make_float4(to_tf32(rb0.x), to_tf32(rb0.y),
                                to_tf32(rb0.z), to_tf32(rb0.w));
        float4 w1 = make_float4(to_tf32(rb1.x), to_tf32(rb1.y),
                                to_tf32(rb1.z), to_tf32(rb1.w));
        *(float4*)&Bs[br][bc] = w0;
        *(float4*)&Bs[br + 8][bc] = w1;
        __syncthreads();

        if (kt + 1 < nk) {
            const float* An = Aptr + (kt + 1) * TBK;
            ra0 = make_float4(0.f, 0.f, 0.f, 0.f); ra1 = ra0;
            if (av0) ra0 = *(const float4*)An;
            if (av1) ra1 = *(const float4*)(An + (size_t)64 * K);
            const float* Bn = Bptr + (size_t)(kt + 1) * TBK * O;
            rb0 = *(const float4*)Bn;
            rb1 = *(const float4*)(Bn + (size_t)8 * O);
        }

#pragma unroll
        for (int ks = 0; ks < 2; ks++) {
            int k0 = ks * 8;
            uint32_t af[2][4];
            int mbase = wm * 32;
#pragma unroll
            for (int mt = 0; mt < 2; mt++) {
                int m = mbase + mt * 16 + gid;
                af[mt][0] = __float_as_uint(As[k0 + tig][m]);
                af[mt][1] = __float_as_uint(As[k0 + tig][m + 8]);
                af[mt][2] = __float_as_uint(As[k0 + tig + 4][m]);
                af[mt][3] = __float_as_uint(As[k0 + tig + 4][m + 8]);
            }
            uint32_t bf[8][2];
            int nbase = wn * 64;
#pragma unroll
            for (int nt = 0; nt < 8; nt++) {
                int n = nbase + nt * 8 + gid;
                bf[nt][0] = __float_as_uint(Bs[k0 + tig][n]);
                bf[nt][1] = __float_as_uint(Bs[k0 + tig + 4][n]);
            }
#pragma unroll
            for (int mt = 0; mt < 2; mt++)
#pragma unroll
                for (int nt = 0; nt < 8; nt++) {
                    asm volatile(
                        "mma.sync.aligned.m16n8k8.row.col.f32.tf32.tf32.f32 "
                        "{%0,%1,%2,%3}, {%4,%5,%6,%7}, {%8,%9}, {%0,%1,%2,%3};"
                        : "+f"(c[mt][nt][0]), "+f"(c[mt][nt][1]),
                          "+f"(c[mt][nt][2]), "+f"(c[mt][nt][3])
                        : "r"(af[mt][0]), "r"(af[mt][1]),
                          "r"(af[mt][2]), "r"(af[mt][3]),
                          "r"(bf[nt][0]), "r"(bf[nt][1]));
                }
        }
        __syncthreads();
    }

    // Epilogue: c frag (mt,nt): rows r0=base+gid, r1=r0+8; cols 2*tig, 2*tig+1
#pragma unroll
    for (int mt = 0; mt < 2; mt++) {
        int r0 = bm + wm * 32 + mt * 16 + gid;
        int r1 = r0 + 8;
        bool v0 = r0 < M, v1 = r1 < M;
#pragma unroll
        for (int nt = 0; nt < 8; nt++) {
            int col = bn + wn * 64 + nt * 8 + tig * 2;
            float2 bb = *(const float2*)(bias + col);
            float2 o0 = make_float2(c[mt][nt][0] + bb.x, c[mt][nt][1] + bb.y);
            float2 o1 = make_float2(c[mt][nt][2] + bb.x, c[mt][nt][3] + bb.y);
            if (act == 1) {
                o0.x = fmaxf(o0.x, 0.f); o0.y = fmaxf(o0.y, 0.f);
                o1.x = fmaxf(o1.x, 0.f); o1.y = fmaxf(o1.y, 0.f);
            } else if (act == 2) {
                if (v0) {
                    float2 r = *(const float2*)(res + (size_t)r0 * O + col);
                    o0.x += r.x; o0.y += r.y;
                }
                if (v1) {
                    float2 r = *(const float2*)(res + (size_t)r1 * O + col);
                    o1.x += r.x; o1.y += r.y;
                }
                o0.x = (o0.x > 0.f) ? o0.x : 0.01f * o0.x;
                o0.y = (o0.y > 0.f) ? o0.y : 0.01f * o0.y;
                o1.x = (o1.x > 0.f) ? o1.x : 0.01f * o1.x;
                o1.y = (o1.y > 0.f) ? o1.y : 0.01f * o1.y;
            }
            if (v0) *(float2*)(C + (size_t)r0 * O + col) = o0;
            if (v1) *(float2*)(C + (size_t)r1 * O + col) = o1;
        }
    }
}

// ---------------------------------------------------------------------------
// Fused LSE + attentive pool (unchanged from R2).
// ---------------------------------------------------------------------------
#define LSE_SMEM_FLOATS (640 + 64 + 8192 + 128 + 256 + 2048 + 2048)
#define LSE_SMEM_BYTES  (LSE_SMEM_FLOATS * 4)

__global__ __launch_bounds__(256) void lse_kernel(
    const float* __restrict__ coords, const int* __restrict__ nidx,
    const float* __restrict__ feats,
    const float* __restrict__ W1, const float* __restrict__ B1,
    const float* __restrict__ W2, const float* __restrict__ B2,
    float* __restrict__ outF, int N)
{
    extern __shared__ float sm[];
    float* sW1   = sm;
    float* sB1   = sW1 + 640;
    float* sW2   = sB1 + 64;
    float* sB2   = sW2 + 8192;
    float* sFeat = sB2 + 128;
    float* sH    = sFeat + 256;
    float* sFp   = sH + 2048;

    int tid = threadIdx.x, lane = tid & 31, wid = tid >> 5;

    for (int i = tid; i < 640; i += 256) sW1[i] = W1[i];
    if (tid < 64) sB1[tid] = B1[tid];
    for (int i = tid; i < 2048; i += 256)
        ((float4*)sW2)[i] = ((const float4*)W2)[i];
    if (tid < 128) sB2[tid] = B2[tid];
    __syncthreads();

    const float4* W2v = (const float4*)sW2;
    float* sHw = sH + wid * 256;
    const float4* Hv = (const float4*)sHw;

    int n0 = blockIdx.x * PPB;
    for (int p = 0; p < PPB; p += 2) {
        int nA = n0 + p, nB = nA + 1;
        bool vA = nA < N, vB = nB < N;

        if (tid < 64) {
            int pt = tid >> 5, q = tid & 31;
            int nn = pt ? nB : nA;
            float4 f = make_float4(0.f, 0.f, 0.f, 0.f);
            if (pt ? vB : vA)
                f = ((const float4*)(feats + (size_t)nn * 128))[q];
            ((float4*)sFeat)[tid] = f;
        }
        __syncthreads();

#pragma unroll
        for (int pr = 0; pr < 4; pr++) {
            int pt = pr >> 1;
            int n = pt ? nB : nA;
            bool vv = pt ? vB : vA;
            int nsafe = vv ? n : 0;
            int k = wid + (pr & 1) * 8;
            int nb = nidx[(size_t)nsafe * KNBR + k];
            float ox = coords[nsafe * 3 + 0], oy = coords[nsafe * 3 + 1], oz = coords[nsafe * 3 + 2];
            float nx = coords[nb * 3 + 0], ny = coords[nb * 3 + 1], nz = coords[nb * 3 + 2];
            float rx = ox - nx, ry = oy - ny, rz = oz - nz;
            float d = sqrtf(rx * rx + ry * ry + rz * rz);
            float c10[10] = {ox, oy, oz, nx, ny, nz, rx, ry, rz, d};
            float h0 = sB1[lane], h1 = sB1[lane + 32];
#pragma unroll
            for (int i = 0; i < 10; i++) {
                float ci = c10[i];
                h0 = fmaf(ci, sW1[i * 64 + lane], h0);
                h1 = fmaf(ci, sW1[i * 64 + 32 + lane], h1);
            }
            sHw[pr * 64 + lane] = fmaxf(h0, 0.f);
            sHw[pr * 64 + 32 + lane] = fmaxf(h1, 0.f);
        }
        __syncwarp();

        float4 bi = ((const float4*)sB2)[lane];
        float4 acc[4];
        acc[0] = bi; acc[1] = bi; acc[2] = bi; acc[3] = bi;
#pragma unroll
        for (int jj = 0; jj < 16; jj++) {
            float4 w0 = W2v[(jj * 4 + 0) * 32 + lane];
            float4 w1 = W2v[(jj * 4 + 1) * 32 + lane];
            float4 w2 = W2v[(jj * 4 + 2) * 32 + lane];
            float4 w3 = W2v[(jj * 4 + 3) * 32 + lane];
#pragma unroll
            for (int pr = 0; pr < 4; pr++) {
                float4 h = Hv[pr * 16 + jj];
                acc[pr].x = fmaf(h.x, w0.x, acc[pr].x);
                acc[pr].y = fmaf(h.x, w0.y, acc[pr].y);
                acc[pr].z = fmaf(h.x, w0.z, acc[pr].z);
                acc[pr].w = fmaf(h.x, w0.w, acc[pr].w);
                acc[pr].x = fmaf(h.y, w1.x, acc[pr].x);
                acc[pr].y = fmaf(h.y, w1.y, acc[pr].y);
                acc[pr].z = fmaf(h.y, w1.z, acc[pr].z);
                acc[pr].w = fmaf(h.y, w1.w, acc[pr].w);
                acc[pr].x = fmaf(h.z, w2.x, acc[pr].x);
                acc[pr].y = fmaf(h.z, w2.y, acc[pr].y);
                acc[pr].z = fmaf(h.z, w2.z, acc[pr].z);
                acc[pr].w = fmaf(h.z, w2.w, acc[pr].w);
                acc[pr].x = fmaf(h.w, w3.x, acc[pr].x);
                acc[pr].y = fmaf(h.w, w3.y, acc[pr].y);
                acc[pr].z = fmaf(h.w, w3.z, acc[pr].z);
                acc[pr].w = fmaf(h.w, w3.w, acc[pr].w);
            }
        }

        float fAcc[2][8];
#pragma unroll
        for (int pt = 0; pt < 2; pt++)
#pragma unroll
            for (int q = 0; q < 8; q++) fAcc[pt][q] = 0.f;

#pragma unroll
        for (int pr = 0; pr < 4; pr++) {
            int pt = pr >> 1;
            float4 fv = ((const float4*)sFeat)[pt * 32 + lane];
            float v[8] = {acc[pr].x, acc[pr].y, acc[pr].z, acc[pr].w,
                          fv.x, fv.y, fv.z, fv.w};
            float m = v[0];
#pragma unroll
            for (int i = 1; i < 8; i++) m = fmaxf(m, v[i]);
#pragma unroll
            for (int o = 16; o > 0; o >>= 1)
                m = fmaxf(m, __shfl_xor_sync(0xffffffffu, m, o));
            float e[8], s = 0.f;
#pragma unroll
            for (int i = 0; i < 8; i++) { e[i] = __expf(v[i] - m); s += e[i]; }
#pragma unroll
            for (int o = 16; o > 0; o >>= 1)
                s += __shfl_xor_sync(0xffffffffu, s, o);
            float inv = 1.f / s;
#pragma unroll
            for (int i = 0; i < 8; i++)
                fAcc[pt][i] = fmaf(e[i] * inv, v[i], fAcc[pt][i]);
        }

#pragma unroll
        for (int pt = 0; pt < 2; pt++) {
            __syncthreads();
            ((float4*)(sFp + wid * 256))[lane] =
                make_float4(fAcc[pt][0], fAcc[pt][1], fAcc[pt][2], fAcc[pt][3]);
            ((float4*)(sFp + wid * 256))[32 + lane] =
                make_float4(fAcc[pt][4], fAcc[pt][5], fAcc[pt][6], fAcc[pt][7]);
            __syncthreads();
            float s = 0.f;
#pragma unroll
            for (int w = 0; w < 8; w++) s += sFp[w * 256 + tid];
            int n = pt ? nB : nA;
            if (pt ? vB : vA)
                outF[(size_t)n * 256 + tid] = s;
        }
        __syncthreads();
    }
}

// ---------------------------------------------------------------------------
extern "C" void kernel_launch(void* const* d_in, const int* in_sizes, int n_in,
                              void* d_out, int out_size)
{
    const float* coords   = (const float*)d_in[0];
    const float* features = (const float*)d_in[1];
    const int*   nidx     = (const int*)d_in[2];
    const float* m1W1 = (const float*)d_in[3];  const float* m1b1 = (const float*)d_in[4];
    const float* m1W2 = (const float*)d_in[5];  const float* m1b2 = (const float*)d_in[6];
    const float* m2W1 = (const float*)d_in[7];  const float* m2b1 = (const float*)d_in[8];
    const float* m2W2 = (const float*)d_in[9];  const float* m2b2 = (const float*)d_in[10];
    const float* m3W1 = (const float*)d_in[11]; const float* m3b1 = (const float*)d_in[12];
    const float* m3W2 = (const float*)d_in[13]; const float* m3b2 = (const float*)d_in[14];
    const float* l1W1 = (const float*)d_in[15]; const float* l1b1 = (const float*)d_in[16];
    const float* l1W2 = (const float*)d_in[17]; const float* l1b2 = (const float*)d_in[18];
    const float* l2W1 = (const float*)d_in[19]; const float* l2b1 = (const float*)d_in[20];
    const float* l2W2 = (const float*)d_in[21]; const float* l2b2 = (const float*)d_in[22];
    const float* p1W1 = (const float*)d_in[23]; const float* p1b1 = (const float*)d_in[24];
    const float* p1W2 = (const float*)d_in[25]; const float* p1b2 = (const float*)d_in[26];
    const float* p2W1 = (const float*)d_in[27]; const float* p2b1 = (const float*)d_in[28];
    const float* p2W2 = (const float*)d_in[29]; const float* p2b2 = (const float*)d_in[30];
    float* out = (float*)d_out;

    int N = in_sizes[0] / 3;

    float *bufA, *bufB, *bufC;
    cudaGetSymbolAddress((void**)&bufA, g_bufA);
    cudaGetSymbolAddress((void**)&bufB, g_bufB);
    cudaGetSymbolAddress((void**)&bufC, g_bufC);

    static int attr_set = 0;
    if (!attr_set) {
        cudaFuncSetAttribute(lse_kernel,
                             cudaFuncAttributeMaxDynamicSharedMemorySize,
                             LSE_SMEM_BYTES);
        attr_set = 1;
    }

    dim3 blk(256);
    auto grid = [&](int M, int O) { return dim3((M + TBM - 1) / TBM, O / TBN); };
    int lse_grid = (N + PPB - 1) / PPB;

    // x = mlp1(features): 128 -> 128 -> 128
    tgemm_kernel<<<grid(N, 128), blk>>>(features, m1W1, m1b1, nullptr, bufA, N, 128, 128, 1);
    tgemm_kernel<<<grid(N, 128), blk>>>(bufA,     m1W2, m1b2, nullptr, bufB, N, 128, 128, 0);
    // lse1 + channel-softmax pool -> (N,256)
    lse_kernel<<<lse_grid, blk, LSE_SMEM_BYTES>>>(coords, nidx, bufB, l1W1, l1b1, l1W2, l1b2, bufA, N);
    // p1: 256 -> 256 -> 128
    tgemm_kernel<<<grid(N, 256), blk>>>(bufA, p1W1, p1b1, nullptr, bufC, N, 256, 256, 1);
    tgemm_kernel<<<grid(N, 128), blk>>>(bufC, p1W2, p1b2, nullptr, bufB, N, 256, 128, 0);
    // lse2 -> (N,256)
    lse_kernel<<<lse_grid, blk, LSE_SMEM_BYTES>>>(coords, nidx, bufB, l2W1, l2b1, l2W2, l2b2, bufA, N);
    // p2: 256 -> 256 -> 256
    tgemm_kernel<<<grid(N, 256), blk>>>(bufA, p2W1, p2b1, nullptr, bufC, N, 256, 256, 1);
    tgemm_kernel<<<grid(N, 256), blk>>>(bufC, p2W2, p2b2, nullptr, bufB, N, 256, 256, 0);
    // m3(features): 128 -> 256 -> 512
    tgemm_kernel<<<grid(N, 256), blk>>>(features, m3W1, m3b1, nullptr, bufA, N, 128, 256, 1);
    tgemm_kernel<<<grid(N, 512), blk>>>(bufA,     m3W2, m3b2, nullptr, bufC, N, 256, 512, 0);
    // m2(x): 256 -> 384 -> 512, fused residual(+m3) + leaky_relu
    tgemm_kernel<<<grid(N, 384), blk>>>(bufB, m2W1, m2b1, nullptr, bufA, N, 256, 384, 1);
    tgemm_kernel<<<grid(N, 512), blk>>>(bufA, m2W2, m2b2, bufC,    out,  N, 384, 512, 2);
}

// round 4
// speedup vs baseline: 5.8558x; 1.4540x over previous
#include <cuda_runtime.h>
#include <math.h>
#include <stdint.h>

#define NMAX 100000
#define KNBR 16

// Scratch (static __device__ — allocation-guard safe)
__device__ float g_bufA[NMAX * 384];
__device__ float g_bufB[NMAX * 256];
__device__ float g_bufC[NMAX * 512];

__device__ __forceinline__ float to_tf32(float x) {
    float y;
    asm("cvt.rna.tf32.f32 %0, %1;" : "=f"(y) : "f"(x));
    return y;
}

#define MMA_TF32(C, a0, a1, a2, a3, b0, b1)                                   \
    asm volatile(                                                             \
        "mma.sync.aligned.m16n8k8.row.col.f32.tf32.tf32.f32 "                 \
        "{%0,%1,%2,%3}, {%4,%5,%6,%7}, {%8,%9}, {%0,%1,%2,%3};"               \
        : "+f"((C)[0]), "+f"((C)[1]), "+f"((C)[2]), "+f"((C)[3])              \
        : "r"(a0), "r"(a1), "r"(a2), "r"(a3), "r"(b0), "r"(b1))

// ---------------------------------------------------------------------------
// Tensor-core GEMM (tf32 mma.sync) — unchanged from R3.
// ---------------------------------------------------------------------------
#define TBM 128
#define TBN 128
#define TBK 16
#define SSTR 136

__global__ __launch_bounds__(256) void tgemm_kernel(
    const float* __restrict__ A, const float* __restrict__ W,
    const float* __restrict__ bias, const float* __restrict__ res,
    float* __restrict__ C, int M, int K, int O, int act)
{
    __shared__ float As[TBK][SSTR];
    __shared__ float Bs[TBK][SSTR];

    int tid = threadIdx.x, lane = tid & 31, wid = tid >> 5;
    int bm = blockIdx.x * TBM, bn = blockIdx.y * TBN;
    int wm = wid & 3, wn = wid >> 2;
    int gid = lane >> 2, tig = lane & 3;

    int ar = tid >> 2, ac = (tid & 3) * 4;
    int br = tid >> 5, bc = (tid & 31) * 4;

    const float* Aptr = A + (size_t)(bm + ar) * K + ac;
    const float* Bptr = W + (size_t)br * O + bn + bc;
    bool av0 = (bm + ar) < M;
    bool av1 = (bm + ar + 64) < M;

    float c[2][8][4];
#pragma unroll
    for (int mt = 0; mt < 2; mt++)
#pragma unroll
        for (int nt = 0; nt < 8; nt++)
#pragma unroll
            for (int q = 0; q < 4; q++) c[mt][nt][q] = 0.f;

    float4 ra0 = make_float4(0.f, 0.f, 0.f, 0.f), ra1 = ra0, rb0, rb1;
    if (av0) ra0 = *(const float4*)Aptr;
    if (av1) ra1 = *(const float4*)(Aptr + (size_t)64 * K);
    rb0 = *(const float4*)Bptr;
    rb1 = *(const float4*)(Bptr + (size_t)8 * O);

    int nk = K / TBK;
    for (int kt = 0; kt < nk; kt++) {
        As[ac + 0][ar] = to_tf32(ra0.x);
        As[ac + 1][ar] = to_tf32(ra0.y);
        As[ac + 2][ar] = to_tf32(ra0.z);
        As[ac + 3][ar] = to_tf32(ra0.w);
        As[ac + 0][ar + 64] = to_tf32(ra1.x);
        As[ac + 1][ar + 64] = to_tf32(ra1.y);
        As[ac + 2][ar + 64] = to_tf32(ra1.z);
        As[ac + 3][ar + 64] = to_tf32(ra1.w);
        float4 w0 = make_float4(to_tf32(rb0.x), to_tf32(rb0.y),
                                to_tf32(rb0.z), to_tf32(rb0.w));
        float4 w1 = make_float4(to_tf32(rb1.x), to_tf32(rb1.y),
                                to_tf32(rb1.z), to_tf32(rb1.w));
        *(float4*)&Bs[br][bc] = w0;
        *(float4*)&Bs[br + 8][bc] = w1;
        __syncthreads();

        if (kt + 1 < nk) {
            const float* An = Aptr + (kt + 1) * TBK;
            ra0 = make_float4(0.f, 0.f, 0.f, 0.f); ra1 = ra0;
            if (av0) ra0 = *(const float4*)An;
            if (av1) ra1 = *(const float4*)(An + (size_t)64 * K);
            const float* Bn = Bptr + (size_t)(kt + 1) * TBK * O;
            rb0 = *(const float4*)Bn;
            rb1 = *(const float4*)(Bn + (size_t)8 * O);
        }

#pragma unroll
        for (int ks = 0; ks < 2; ks++) {
            int k0 = ks * 8;
            uint32_t af[2][4];
            int mbase = wm * 32;
#pragma unroll
            for (int mt = 0; mt < 2; mt++) {
                int m = mbase + mt * 16 + gid;
                af[mt][0] = __float_as_uint(As[k0 + tig][m]);
                af[mt][1] = __float_as_uint(As[k0 + tig][m + 8]);
                af[mt][2] = __float_as_uint(As[k0 + tig + 4][m]);
                af[mt][3] = __float_as_uint(As[k0 + tig + 4][m + 8]);
            }
            uint32_t bf[8][2];
            int nbase = wn * 64;
#pragma unroll
            for (int nt = 0; nt < 8; nt++) {
                int n = nbase + nt * 8 + gid;
                bf[nt][0] = __float_as_uint(Bs[k0 + tig][n]);
                bf[nt][1] = __float_as_uint(Bs[k0 + tig + 4][n]);
            }
#pragma unroll
            for (int mt = 0; mt < 2; mt++)
#pragma unroll
                for (int nt = 0; nt < 8; nt++)
                    MMA_TF32(c[mt][nt], af[mt][0], af[mt][1], af[mt][2],
                             af[mt][3], bf[nt][0], bf[nt][1]);
        }
        __syncthreads();
    }

#pragma unroll
    for (int mt = 0; mt < 2; mt++) {
        int r0 = bm + wm * 32 + mt * 16 + gid;
        int r1 = r0 + 8;
        bool v0 = r0 < M, v1 = r1 < M;
#pragma unroll
        for (int nt = 0; nt < 8; nt++) {
            int col = bn + wn * 64 + nt * 8 + tig * 2;
            float2 bb = *(const float2*)(bias + col);
            float2 o0 = make_float2(c[mt][nt][0] + bb.x, c[mt][nt][1] + bb.y);
            float2 o1 = make_float2(c[mt][nt][2] + bb.x, c[mt][nt][3] + bb.y);
            if (act == 1) {
                o0.x = fmaxf(o0.x, 0.f); o0.y = fmaxf(o0.y, 0.f);
                o1.x = fmaxf(o1.x, 0.f); o1.y = fmaxf(o1.y, 0.f);
            } else if (act == 2) {
                if (v0) {
                    float2 r = *(const float2*)(res + (size_t)r0 * O + col);
                    o0.x += r.x; o0.y += r.y;
                }
                if (v1) {
                    float2 r = *(const float2*)(res + (size_t)r1 * O + col);
                    o1.x += r.x; o1.y += r.y;
                }
                o0.x = (o0.x > 0.f) ? o0.x : 0.01f * o0.x;
                o0.y = (o0.y > 0.f) ? o0.y : 0.01f * o0.y;
                o1.x = (o1.x > 0.f) ? o1.x : 0.01f * o1.x;
                o1.y = (o1.y > 0.f) ? o1.y : 0.01f * o1.y;
            }
            if (v0) *(float2*)(C + (size_t)r0 * O + col) = o0;
            if (v1) *(float2*)(C + (size_t)r1 * O + col) = o1;
        }
    }
}

// ---------------------------------------------------------------------------
// LSE + attentive pool, tensor-core version. One point per warp.
// enc^T[128 x 16] = W2^T[128 x 64] @ H^T[64 x 16] via mma.m16n8k8 tf32.
// C layout: channels on gid (M dim), neighbors on tig (N dim).
// Hidden layer fp32; each lane computes exactly its B-fragment h-values.
// ---------------------------------------------------------------------------
#define LSTR 136

__global__ __launch_bounds__(256) void lse_mma_kernel(
    const float* __restrict__ coords, const int* __restrict__ nidx,
    const float* __restrict__ feats,
    const float* __restrict__ W1, const float* __restrict__ B1,
    const float* __restrict__ W2, const float* __restrict__ B2,
    float* __restrict__ outF, int N)
{
    __shared__ float sW1[640];        // [10][64]
    __shared__ float sB1[64];
    __shared__ float sB2[128];
    __shared__ float sW2[64 * LSTR];  // [k][ch], tf32-rounded

    int tid = threadIdx.x, lane = tid & 31, wid = tid >> 5;
    int gid = lane >> 2, tig = lane & 3;

    for (int i = tid; i < 640; i += 256) sW1[i] = W1[i];
    if (tid < 64) sB1[tid] = B1[tid];
    if (tid < 128) sB2[tid] = B2[tid];
    for (int i = tid; i < 8192; i += 256) {
        int k = i >> 7, ch = i & 127;
        sW2[k * LSTR + ch] = to_tf32(W2[i]);
    }
    __syncthreads();

    int nbase = blockIdx.x * 64 + wid * 8;
    for (int p = 0; p < 8; p++) {
        int n = nbase + p;
        if (n >= N) break;   // uniform per warp

        // ---- hidden layer (fp32) -> B-fragments ----
        int ib0 = nidx[n * KNBR + gid];
        int ib1 = nidx[n * KNBR + gid + 8];
        float ox = coords[n * 3], oy = coords[n * 3 + 1], oz = coords[n * 3 + 2];
        float ax = coords[ib0 * 3], ay = coords[ib0 * 3 + 1], az = coords[ib0 * 3 + 2];
        float bx = coords[ib1 * 3], by = coords[ib1 * 3 + 1], bz = coords[ib1 * 3 + 2];
        float arx = ox - ax, ary = oy - ay, arz = oz - az;
        float brx = ox - bx, bry = oy - by, brz = oz - bz;
        float ad = sqrtf(arx * arx + ary * ary + arz * arz);
        float bd = sqrtf(brx * brx + bry * bry + brz * brz);
        float ca[10] = {ox, oy, oz, ax, ay, az, arx, ary, arz, ad};
        float cb[10] = {ox, oy, oz, bx, by, bz, brx, bry, brz, bd};

        uint32_t hb0[16], hb1[16];  // h[nbr gid][tig+4j], h[nbr gid+8][tig+4j]
#pragma unroll
        for (int j = 0; j < 16; j++) {
            int c = tig + 4 * j;
            float h0 = sB1[c], h1 = h0;
#pragma unroll
            for (int i = 0; i < 10; i++) {
                float w = sW1[i * 64 + c];
                h0 = fmaf(ca[i], w, h0);
                h1 = fmaf(cb[i], w, h1);
            }
            hb0[j] = __float_as_uint(to_tf32(fmaxf(h0, 0.f)));
            hb1[j] = __float_as_uint(to_tf32(fmaxf(h1, 0.f)));
        }

        // ---- mma: enc^T = W2^T @ H^T ----
        float c_[8][2][4];
#pragma unroll
        for (int mt = 0; mt < 8; mt++)
#pragma unroll
            for (int nt = 0; nt < 2; nt++)
#pragma unroll
                for (int q = 0; q < 4; q++) c_[mt][nt][q] = 0.f;

#pragma unroll
        for (int s = 0; s < 8; s++) {
            uint32_t b00 = hb0[2 * s], b01 = hb0[2 * s + 1];
            uint32_t b10 = hb1[2 * s], b11 = hb1[2 * s + 1];
            const float* r0 = &sW2[(8 * s + tig) * LSTR];
            const float* r1 = &sW2[(8 * s + tig + 4) * LSTR];
#pragma unroll
            for (int mt = 0; mt < 8; mt++) {
                int cb0 = 16 * mt + gid;
                uint32_t a0 = __float_as_uint(r0[cb0]);
                uint32_t a1 = __float_as_uint(r0[cb0 + 8]);
                uint32_t a2 = __float_as_uint(r1[cb0]);
                uint32_t a3 = __float_as_uint(r1[cb0 + 8]);
                MMA_TF32(c_[mt][0], a0, a1, a2, a3, b00, b01);
                MMA_TF32(c_[mt][1], a0, a1, a2, a3, b10, b11);
            }
        }

        // bias: q0,q1 -> channel 16mt+gid ; q2,q3 -> +8
#pragma unroll
        for (int mt = 0; mt < 8; mt++) {
            float bb0 = sB2[16 * mt + gid], bb1 = sB2[16 * mt + gid + 8];
#pragma unroll
            for (int nt = 0; nt < 2; nt++) {
                c_[mt][nt][0] += bb0; c_[mt][nt][1] += bb0;
                c_[mt][nt][2] += bb1; c_[mt][nt][3] += bb1;
            }
        }

        // ---- feats stats ----
        float4 f4 = *(const float4*)(feats + (size_t)n * 128 + 4 * lane);
        float mf = fmaxf(fmaxf(f4.x, f4.y), fmaxf(f4.z, f4.w));
#pragma unroll
        for (int o = 16; o > 0; o >>= 1)
            mf = fmaxf(mf, __shfl_xor_sync(0xffffffffu, mf, o));
        float sf = __expf(f4.x - mf) + __expf(f4.y - mf) +
                   __expf(f4.z - mf) + __expf(f4.w - mf);
#pragma unroll
        for (int o = 16; o > 0; o >>= 1)
            sf += __shfl_xor_sync(0xffffffffu, sf, o);

        // ---- per-neighbor softmax stats ----
        // lane's 4 local neighbors: j0=2tig, j1=2tig+1, j2=2tig+8, j3=2tig+9
        float mrow[4], inv[4];
#pragma unroll
        for (int j = 0; j < 4; j++) {
            int nt = j >> 1, q = j & 1;
            float m = c_[0][nt][q];
#pragma unroll
            for (int mt = 0; mt < 8; mt++) {
                m = fmaxf(m, c_[mt][nt][q]);
                m = fmaxf(m, c_[mt][nt][q + 2]);
            }
#pragma unroll
            for (int o = 4; o <= 16; o <<= 1)
                m = fmaxf(m, __shfl_xor_sync(0xffffffffu, m, o));
            mrow[j] = fmaxf(m, mf);
        }
#pragma unroll
        for (int j = 0; j < 4; j++) {
            int nt = j >> 1, q = j & 1;
            float s = 0.f;
#pragma unroll
            for (int mt = 0; mt < 8; mt++) {
                s += __expf(c_[mt][nt][q] - mrow[j]);
                s += __expf(c_[mt][nt][q + 2] - mrow[j]);
            }
#pragma unroll
            for (int o = 4; o <= 16; o <<= 1)
                s += __shfl_xor_sync(0xffffffffu, s, o);
            inv[j] = 1.f / (s + __expf(mf - mrow[j]) * sf);
        }

        float Tl = 0.f;
#pragma unroll
        for (int j = 0; j < 4; j++) Tl += __expf(mf - mrow[j]) * inv[j];
        Tl += __shfl_xor_sync(0xffffffffu, Tl, 1);
        Tl += __shfl_xor_sync(0xffffffffu, Tl, 2);

        // ---- pooled enc output ----
        float ov[8][2];
#pragma unroll
        for (int mt = 0; mt < 8; mt++) { ov[mt][0] = 0.f; ov[mt][1] = 0.f; }
#pragma unroll
        for (int j = 0; j < 4; j++) {
            int nt = j >> 1, q = j & 1;
            float w = inv[j], mr = mrow[j];
#pragma unroll
            for (int mt = 0; mt < 8; mt++) {
                float v0 = c_[mt][nt][q];
                float v1 = c_[mt][nt][q + 2];
                ov[mt][0] = fmaf(__expf(v0 - mr) * w, v0, ov[mt][0]);
                ov[mt][1] = fmaf(__expf(v1 - mr) * w, v1, ov[mt][1]);
            }
        }
#pragma unroll
        for (int mt = 0; mt < 8; mt++) {
#pragma unroll
            for (int cs = 0; cs < 2; cs++) {
                ov[mt][cs] += __shfl_xor_sync(0xffffffffu, ov[mt][cs], 1);
                ov[mt][cs] += __shfl_xor_sync(0xffffffffu, ov[mt][cs], 2);
            }
        }

        float* po = outF + (size_t)n * 256;
#pragma unroll
        for (int t = 0; t < 2; t++) {
            int mt = 2 * tig + t;
            po[16 * mt + gid]     = ov[mt][0];
            po[16 * mt + gid + 8] = ov[mt][1];
        }
        float4 g;
        g.x = f4.x * __expf(f4.x - mf) * Tl;
        g.y = f4.y * __expf(f4.y - mf) * Tl;
        g.z = f4.z * __expf(f4.z - mf) * Tl;
        g.w = f4.w * __expf(f4.w - mf) * Tl;
        *(float4*)(po + 128 + 4 * lane) = g;
    }
}

// ---------------------------------------------------------------------------
extern "C" void kernel_launch(void* const* d_in, const int* in_sizes, int n_in,
                              void* d_out, int out_size)
{
    const float* coords   = (const float*)d_in[0];
    const float* features = (const float*)d_in[1];
    const int*   nidx     = (const int*)d_in[2];
    const float* m1W1 = (const float*)d_in[3];  const float* m1b1 = (const float*)d_in[4];
    const float* m1W2 = (const float*)d_in[5];  const float* m1b2 = (const float*)d_in[6];
    const float* m2W1 = (const float*)d_in[7];  const float* m2b1 = (const float*)d_in[8];
    const float* m2W2 = (const float*)d_in[9];  const float* m2b2 = (const float*)d_in[10];
    const float* m3W1 = (const float*)d_in[11]; const float* m3b1 = (const float*)d_in[12];
    const float* m3W2 = (const float*)d_in[13]; const float* m3b2 = (const float*)d_in[14];
    const float* l1W1 = (const float*)d_in[15]; const float* l1b1 = (const float*)d_in[16];
    const float* l1W2 = (const float*)d_in[17]; const float* l1b2 = (const float*)d_in[18];
    const float* l2W1 = (const float*)d_in[19]; const float* l2b1 = (const float*)d_in[20];
    const float* l2W2 = (const float*)d_in[21]; const float* l2b2 = (const float*)d_in[22];
    const float* p1W1 = (const float*)d_in[23]; const float* p1b1 = (const float*)d_in[24];
    const float* p1W2 = (const float*)d_in[25]; const float* p1b2 = (const float*)d_in[26];
    const float* p2W1 = (const float*)d_in[27]; const float* p2b1 = (const float*)d_in[28];
    const float* p2W2 = (const float*)d_in[29]; const float* p2b2 = (const float*)d_in[30];
    float* out = (float*)d_out;

    int N = in_sizes[0] / 3;

    float *bufA, *bufB, *bufC;
    cudaGetSymbolAddress((void**)&bufA, g_bufA);
    cudaGetSymbolAddress((void**)&bufB, g_bufB);
    cudaGetSymbolAddress((void**)&bufC, g_bufC);

    dim3 blk(256);
    auto grid = [&](int M, int O) { return dim3((M + TBM - 1) / TBM, O / TBN); };
    int lse_grid = (N + 63) / 64;

    // x = mlp1(features): 128 -> 128 -> 128
    tgemm_kernel<<<grid(N, 128), blk>>>(features, m1W1, m1b1, nullptr, bufA, N, 128, 128, 1);
    tgemm_kernel<<<grid(N, 128), blk>>>(bufA,     m1W2, m1b2, nullptr, bufB, N, 128, 128, 0);
    // lse1 + channel-softmax pool -> (N,256)
    lse_mma_kernel<<<lse_grid, blk>>>(coords, nidx, bufB, l1W1, l1b1, l1W2, l1b2, bufA, N);
    // p1: 256 -> 256 -> 128
    tgemm_kernel<<<grid(N, 256), blk>>>(bufA, p1W1, p1b1, nullptr, bufC, N, 256, 256, 1);
    tgemm_kernel<<<grid(N, 128), blk>>>(bufC, p1W2, p1b2, nullptr, bufB, N, 256, 128, 0);
    // lse2 -> (N,256)
    lse_mma_kernel<<<lse_grid, blk>>>(coords, nidx, bufB, l2W1, l2b1, l2W2, l2b2, bufA, N);
    // p2: 256 -> 256 -> 256
    tgemm_kernel<<<grid(N, 256), blk>>>(bufA, p2W1, p2b1, nullptr, bufC, N, 256, 256, 1);
    tgemm_kernel<<<grid(N, 256), blk>>>(bufC, p2W2, p2b2, nullptr, bufB, N, 256, 256, 0);
    // m3(features): 128 -> 256 -> 512
    tgemm_kernel<<<grid(N, 256), blk>>>(features, m3W1, m3b1, nullptr, bufA, N, 128, 256, 1);
    tgemm_kernel<<<grid(N, 512), blk>>>(bufA,     m3W2, m3b2, nullptr, bufC, N, 256, 512, 0);
    // m2(x): 256 -> 384 -> 512, fused residual(+m3) + leaky_relu
    tgemm_kernel<<<grid(N, 384), blk>>>(bufB, m2W1, m2b1, nullptr, bufA, N, 256, 384, 1);
    tgemm_kernel<<<grid(N, 512), blk>>>(bufA, m2W2, m2b2, bufC,    out,  N, 384, 512, 2);
}

// round 5
// speedup vs baseline: 6.1315x; 1.0471x over previous
#include <cuda_runtime.h>
#include <math.h>
#include <stdint.h>

#define NMAX 100000
#define KNBR 16

// Scratch (static __device__ — allocation-guard safe)
__device__ float g_bufA[NMAX * 384];
__device__ float g_bufB[NMAX * 256];
__device__ float g_bufC[NMAX * 512];

__device__ __forceinline__ float to_tf32(float x) {
    float y;
    asm("cvt.rna.tf32.f32 %0, %1;" : "=f"(y) : "f"(x));
    return y;
}

#define MMA_TF32(C, a0, a1, a2, a3, b0, b1)                                   \
    asm volatile(                                                             \
        "mma.sync.aligned.m16n8k8.row.col.f32.tf32.tf32.f32 "                 \
        "{%0,%1,%2,%3}, {%4,%5,%6,%7}, {%8,%9}, {%0,%1,%2,%3};"               \
        : "+f"((C)[0]), "+f"((C)[1]), "+f"((C)[2]), "+f"((C)[3])              \
        : "r"(a0), "r"(a1), "r"(a2), "r"(a3), "r"(b0), "r"(b1))

// ---------------------------------------------------------------------------
// Tensor-core GEMM (tf32 mma.sync): C = act(A[M,K] @ W[K,O] + bias (+ res))
// act: 0 none, 1 relu, 2 leaky(x+res).
// Block 128x128xk16, 4 warps (2x2), warp tile 64x64 (4x8 m16n8k8).
// 128 threads. Requires K % 16 == 0, O % 128 == 0.
// ---------------------------------------------------------------------------
#define TBM 128
#define TBN 128
#define TBK 16
#define SSTR 136

__global__ __launch_bounds__(128, 2) void tgemm_kernel(
    const float* __restrict__ A, const float* __restrict__ W,
    const float* __restrict__ bias, const float* __restrict__ res,
    float* __restrict__ C, int M, int K, int O, int act)
{
    __shared__ float As[TBK][SSTR];
    __shared__ float Bs[TBK][SSTR];

    int tid = threadIdx.x, lane = tid & 31, wid = tid >> 5;
    int bm = blockIdx.x * TBM, bn = blockIdx.y * TBN;
    int wm = wid & 1, wn = wid >> 1;          // warp grid 2 (M) x 2 (N)
    int gid = lane >> 2, tig = lane & 3;

    // A loader: 128 thr -> rows ar+32i (i=0..3), k-cols ac..ac+3
    int ar = tid >> 2, ac = (tid & 3) * 4;
    // B loader: k-rows br+4i (i=0..3), n-cols bc..bc+3
    int br = tid >> 5, bc = (tid & 31) * 4;

    const float* Aptr = A + (size_t)(bm + ar) * K + ac;
    const float* Bptr = W + (size_t)br * O + bn + bc;
    bool av[4];
#pragma unroll
    for (int i = 0; i < 4; i++) av[i] = (bm + ar + 32 * i) < M;

    float c[4][8][4];
#pragma unroll
    for (int mt = 0; mt < 4; mt++)
#pragma unroll
        for (int nt = 0; nt < 8; nt++)
#pragma unroll
            for (int q = 0; q < 4; q++) c[mt][nt][q] = 0.f;

    float4 ra[4], rb[4];
#pragma unroll
    for (int i = 0; i < 4; i++) {
        ra[i] = make_float4(0.f, 0.f, 0.f, 0.f);
        if (av[i]) ra[i] = *(const float4*)(Aptr + (size_t)(32 * i) * K);
        rb[i] = *(const float4*)(Bptr + (size_t)(4 * i) * O);
    }

    int nk = K / TBK;
    for (int kt = 0; kt < nk; kt++) {
#pragma unroll
        for (int i = 0; i < 4; i++) {
            int row = ar + 32 * i;
            As[ac + 0][row] = to_tf32(ra[i].x);
            As[ac + 1][row] = to_tf32(ra[i].y);
            As[ac + 2][row] = to_tf32(ra[i].z);
            As[ac + 3][row] = to_tf32(ra[i].w);
            float4 w = make_float4(to_tf32(rb[i].x), to_tf32(rb[i].y),
                                   to_tf32(rb[i].z), to_tf32(rb[i].w));
            *(float4*)&Bs[br + 4 * i][bc] = w;
        }
        __syncthreads();

        if (kt + 1 < nk) {
            const float* An = Aptr + (kt + 1) * TBK;
            const float* Bn = Bptr + (size_t)(kt + 1) * TBK * O;
#pragma unroll
            for (int i = 0; i < 4; i++) {
                ra[i] = make_float4(0.f, 0.f, 0.f, 0.f);
                if (av[i]) ra[i] = *(const float4*)(An + (size_t)(32 * i) * K);
                rb[i] = *(const float4*)(Bn + (size_t)(4 * i) * O);
            }
        }

#pragma unroll
        for (int ks = 0; ks < 2; ks++) {
            int k0 = ks * 8;
            uint32_t af[4][4];
            int mbase = wm * 64;
#pragma unroll
            for (int mt = 0; mt < 4; mt++) {
                int m = mbase + mt * 16 + gid;
                af[mt][0] = __float_as_uint(As[k0 + tig][m]);
                af[mt][1] = __float_as_uint(As[k0 + tig][m + 8]);
                af[mt][2] = __float_as_uint(As[k0 + tig + 4][m]);
                af[mt][3] = __float_as_uint(As[k0 + tig + 4][m + 8]);
            }
            uint32_t bf[8][2];
            int nbase = wn * 64;
#pragma unroll
            for (int nt = 0; nt < 8; nt++) {
                int n = nbase + nt * 8 + gid;
                bf[nt][0] = __float_as_uint(Bs[k0 + tig][n]);
                bf[nt][1] = __float_as_uint(Bs[k0 + tig + 4][n]);
            }
#pragma unroll
            for (int mt = 0; mt < 4; mt++)
#pragma unroll
                for (int nt = 0; nt < 8; nt++)
                    MMA_TF32(c[mt][nt], af[mt][0], af[mt][1], af[mt][2],
                             af[mt][3], bf[nt][0], bf[nt][1]);
        }
        __syncthreads();
    }

#pragma unroll
    for (int mt = 0; mt < 4; mt++) {
        int r0 = bm + wm * 64 + mt * 16 + gid;
        int r1 = r0 + 8;
        bool v0 = r0 < M, v1 = r1 < M;
#pragma unroll
        for (int nt = 0; nt < 8; nt++) {
            int col = bn + wn * 64 + nt * 8 + tig * 2;
            float2 bb = *(const float2*)(bias + col);
            float2 o0 = make_float2(c[mt][nt][0] + bb.x, c[mt][nt][1] + bb.y);
            float2 o1 = make_float2(c[mt][nt][2] + bb.x, c[mt][nt][3] + bb.y);
            if (act == 1) {
                o0.x = fmaxf(o0.x, 0.f); o0.y = fmaxf(o0.y, 0.f);
                o1.x = fmaxf(o1.x, 0.f); o1.y = fmaxf(o1.y, 0.f);
            } else if (act == 2) {
                if (v0) {
                    float2 r = *(const float2*)(res + (size_t)r0 * O + col);
                    o0.x += r.x; o0.y += r.y;
                }
                if (v1) {
                    float2 r = *(const float2*)(res + (size_t)r1 * O + col);
                    o1.x += r.x; o1.y += r.y;
                }
                o0.x = (o0.x > 0.f) ? o0.x : 0.01f * o0.x;
                o0.y = (o0.y > 0.f) ? o0.y : 0.01f * o0.y;
                o1.x = (o1.x > 0.f) ? o1.x : 0.01f * o1.x;
                o1.y = (o1.y > 0.f) ? o1.y : 0.01f * o1.y;
            }
            if (v0) *(float2*)(C + (size_t)r0 * O + col) = o0;
            if (v1) *(float2*)(C + (size_t)r1 * O + col) = o1;
        }
    }
}

// ---------------------------------------------------------------------------
// LSE + attentive pool, tensor-core version (unchanged from R4).
// ---------------------------------------------------------------------------
#define LSTR 136

__global__ __launch_bounds__(256) void lse_mma_kernel(
    const float* __restrict__ coords, const int* __restrict__ nidx,
    const float* __restrict__ feats,
    const float* __restrict__ W1, const float* __restrict__ B1,
    const float* __restrict__ W2, const float* __restrict__ B2,
    float* __restrict__ outF, int N)
{
    __shared__ float sW1[640];
    __shared__ float sB1[64];
    __shared__ float sB2[128];
    __shared__ float sW2[64 * LSTR];

    int tid = threadIdx.x, lane = tid & 31, wid = tid >> 5;
    int gid = lane >> 2, tig = lane & 3;

    for (int i = tid; i < 640; i += 256) sW1[i] = W1[i];
    if (tid < 64) sB1[tid] = B1[tid];
    if (tid < 128) sB2[tid] = B2[tid];
    for (int i = tid; i < 8192; i += 256) {
        int k = i >> 7, ch = i & 127;
        sW2[k * LSTR + ch] = to_tf32(W2[i]);
    }
    __syncthreads();

    int nbase = blockIdx.x * 64 + wid * 8;
    for (int p = 0; p < 8; p++) {
        int n = nbase + p;
        if (n >= N) break;

        int ib0 = nidx[n * KNBR + gid];
        int ib1 = nidx[n * KNBR + gid + 8];
        float ox = coords[n * 3], oy = coords[n * 3 + 1], oz = coords[n * 3 + 2];
        float ax = coords[ib0 * 3], ay = coords[ib0 * 3 + 1], az = coords[ib0 * 3 + 2];
        float bx = coords[ib1 * 3], by = coords[ib1 * 3 + 1], bz = coords[ib1 * 3 + 2];
        float arx = ox - ax, ary = oy - ay, arz = oz - az;
        float brx = ox - bx, bry = oy - by, brz = oz - bz;
        float ad = sqrtf(arx * arx + ary * ary + arz * arz);
        float bd = sqrtf(brx * brx + bry * bry + brz * brz);
        float ca[10] = {ox, oy, oz, ax, ay, az, arx, ary, arz, ad};
        float cb[10] = {ox, oy, oz, bx, by, bz, brx, bry, brz, bd};

        uint32_t hb0[16], hb1[16];
#pragma unroll
        for (int j = 0; j < 16; j++) {
            int c = tig + 4 * j;
            float h0 = sB1[c], h1 = h0;
#pragma unroll
            for (int i = 0; i < 10; i++) {
                float w = sW1[i * 64 + c];
                h0 = fmaf(ca[i], w, h0);
                h1 = fmaf(cb[i], w, h1);
            }
            hb0[j] = __float_as_uint(to_tf32(fmaxf(h0, 0.f)));
            hb1[j] = __float_as_uint(to_tf32(fmaxf(h1, 0.f)));
        }

        float c_[8][2][4];
#pragma unroll
        for (int mt = 0; mt < 8; mt++)
#pragma unroll
            for (int nt = 0; nt < 2; nt++)
#pragma unroll
                for (int q = 0; q < 4; q++) c_[mt][nt][q] = 0.f;

#pragma unroll
        for (int s = 0; s < 8; s++) {
            uint32_t b00 = hb0[2 * s], b01 = hb0[2 * s + 1];
            uint32_t b10 = hb1[2 * s], b11 = hb1[2 * s + 1];
            const float* r0 = &sW2[(8 * s + tig) * LSTR];
            const float* r1 = &sW2[(8 * s + tig + 4) * LSTR];
#pragma unroll
            for (int mt = 0; mt < 8; mt++) {
                int cb0 = 16 * mt + gid;
                uint32_t a0 = __float_as_uint(r0[cb0]);
                uint32_t a1 = __float_as_uint(r0[cb0 + 8]);
                uint32_t a2 = __float_as_uint(r1[cb0]);
                uint32_t a3 = __float_as_uint(r1[cb0 + 8]);
                MMA_TF32(c_[mt][0], a0, a1, a2, a3, b00, b01);
                MMA_TF32(c_[mt][1], a0, a1, a2, a3, b10, b11);
            }
        }

#pragma unroll
        for (int mt = 0; mt < 8; mt++) {
            float bb0 = sB2[16 * mt + gid], bb1 = sB2[16 * mt + gid + 8];
#pragma unroll
            for (int nt = 0; nt < 2; nt++) {
                c_[mt][nt][0] += bb0; c_[mt][nt][1] += bb0;
                c_[mt][nt][2] += bb1; c_[mt][nt][3] += bb1;
            }
        }

        float4 f4 = *(const float4*)(feats + (size_t)n * 128 + 4 * lane);
        float mf = fmaxf(fmaxf(f4.x, f4.y), fmaxf(f4.z, f4.w));
#pragma unroll
        for (int o = 16; o > 0; o >>= 1)
            mf = fmaxf(mf, __shfl_xor_sync(0xffffffffu, mf, o));
        float sf = __expf(f4.x - mf) + __expf(f4.y - mf) +
                   __expf(f4.z - mf) + __expf(f4.w - mf);
#pragma unroll
        for (int o = 16; o > 0; o >>= 1)
            sf += __shfl_xor_sync(0xffffffffu, sf, o);

        float mrow[4], inv[4];
#pragma unroll
        for (int j = 0; j < 4; j++) {
            int nt = j >> 1, q = j & 1;
            float m = c_[0][nt][q];
#pragma unroll
            for (int mt = 0; mt < 8; mt++) {
                m = fmaxf(m, c_[mt][nt][q]);
                m = fmaxf(m, c_[mt][nt][q + 2]);
            }
#pragma unroll
            for (int o = 4; o <= 16; o <<= 1)
                m = fmaxf(m, __shfl_xor_sync(0xffffffffu, m, o));
            mrow[j] = fmaxf(m, mf);
        }
#pragma unroll
        for (int j = 0; j < 4; j++) {
            int nt = j >> 1, q = j & 1;
            float s = 0.f;
#pragma unroll
            for (int mt = 0; mt < 8; mt++) {
                s += __expf(c_[mt][nt][q] - mrow[j]);
                s += __expf(c_[mt][nt][q + 2] - mrow[j]);
            }
#pragma unroll
            for (int o = 4; o <= 16; o <<= 1)
                s += __shfl_xor_sync(0xffffffffu, s, o);
            inv[j] = 1.f / (s + __expf(mf - mrow[j]) * sf);
        }

        float Tl = 0.f;
#pragma unroll
        for (int j = 0; j < 4; j++) Tl += __expf(mf - mrow[j]) * inv[j];
        Tl += __shfl_xor_sync(0xffffffffu, Tl, 1);
        Tl += __shfl_xor_sync(0xffffffffu, Tl, 2);

        float ov[8][2];
#pragma unroll
        for (int mt = 0; mt < 8; mt++) { ov[mt][0] = 0.f; ov[mt][1] = 0.f; }
#pragma unroll
        for (int j = 0; j < 4; j++) {
            int nt = j >> 1, q = j & 1;
            float w = inv[j], mr = mrow[j];
#pragma unroll
            for (int mt = 0; mt < 8; mt++) {
                float v0 = c_[mt][nt][q];
                float v1 = c_[mt][nt][q + 2];
                ov[mt][0] = fmaf(__expf(v0 - mr) * w, v0, ov[mt][0]);
                ov[mt][1] = fmaf(__expf(v1 - mr) * w, v1, ov[mt][1]);
            }
        }
#pragma unroll
        for (int mt = 0; mt < 8; mt++) {
#pragma unroll
            for (int cs = 0; cs < 2; cs++) {
                ov[mt][cs] += __shfl_xor_sync(0xffffffffu, ov[mt][cs], 1);
                ov[mt][cs] += __shfl_xor_sync(0xffffffffu, ov[mt][cs], 2);
            }
        }

        float* po = outF + (size_t)n * 256;
#pragma unroll
        for (int t = 0; t < 2; t++) {
            int mt = 2 * tig + t;
            po[16 * mt + gid]     = ov[mt][0];
            po[16 * mt + gid + 8] = ov[mt][1];
        }
        float4 g;
        g.x = f4.x * __expf(f4.x - mf) * Tl;
        g.y = f4.y * __expf(f4.y - mf) * Tl;
        g.z = f4.z * __expf(f4.z - mf) * Tl;
        g.w = f4.w * __expf(f4.w - mf) * Tl;
        *(float4*)(po + 128 + 4 * lane) = g;
    }
}

// ---------------------------------------------------------------------------
extern "C" void kernel_launch(void* const* d_in, const int* in_sizes, int n_in,
                              void* d_out, int out_size)
{
    const float* coords   = (const float*)d_in[0];
    const float* features = (const float*)d_in[1];
    const int*   nidx     = (const int*)d_in[2];
    const float* m1W1 = (const float*)d_in[3];  const float* m1b1 = (const float*)d_in[4];
    const float* m1W2 = (const float*)d_in[5];  const float* m1b2 = (const float*)d_in[6];
    const float* m2W1 = (const float*)d_in[7];  const float* m2b1 = (const float*)d_in[8];
    const float* m2W2 = (const float*)d_in[9];  const float* m2b2 = (const float*)d_in[10];
    const float* m3W1 = (const float*)d_in[11]; const float* m3b1 = (const float*)d_in[12];
    const float* m3W2 = (const float*)d_in[13]; const float* m3b2 = (const float*)d_in[14];
    const float* l1W1 = (const float*)d_in[15]; const float* l1b1 = (const float*)d_in[16];
    const float* l1W2 = (const float*)d_in[17]; const float* l1b2 = (const float*)d_in[18];
    const float* l2W1 = (const float*)d_in[19]; const float* l2b1 = (const float*)d_in[20];
    const float* l2W2 = (const float*)d_in[21]; const float* l2b2 = (const float*)d_in[22];
    const float* p1W1 = (const float*)d_in[23]; const float* p1b1 = (const float*)d_in[24];
    const float* p1W2 = (const float*)d_in[25]; const float* p1b2 = (const float*)d_in[26];
    const float* p2W1 = (const float*)d_in[27]; const float* p2b1 = (const float*)d_in[28];
    const float* p2W2 = (const float*)d_in[29]; const float* p2b2 = (const float*)d_in[30];
    float* out = (float*)d_out;

    int N = in_sizes[0] / 3;

    float *bufA, *bufB, *bufC;
    cudaGetSymbolAddress((void**)&bufA, g_bufA);
    cudaGetSymbolAddress((void**)&bufB, g_bufB);
    cudaGetSymbolAddress((void**)&bufC, g_bufC);

    dim3 gblk(128), lblk(256);
    auto grid = [&](int M, int O) { return dim3((M + TBM - 1) / TBM, O / TBN); };
    int lse_grid = (N + 63) / 64;

    // x = mlp1(features): 128 -> 128 -> 128
    tgemm_kernel<<<grid(N, 128), gblk>>>(features, m1W1, m1b1, nullptr, bufA, N, 128, 128, 1);
    tgemm_kernel<<<grid(N, 128), gblk>>>(bufA,     m1W2, m1b2, nullptr, bufB, N, 128, 128, 0);
    // lse1 + channel-softmax pool -> (N,256)
    lse_mma_kernel<<<lse_grid, lblk>>>(coords, nidx, bufB, l1W1, l1b1, l1W2, l1b2, bufA, N);
    // p1: 256 -> 256 -> 128
    tgemm_kernel<<<grid(N, 256), gblk>>>(bufA, p1W1, p1b1, nullptr, bufC, N, 256, 256, 1);
    tgemm_kernel<<<grid(N, 128), gblk>>>(bufC, p1W2, p1b2, nullptr, bufB, N, 256, 128, 0);
    // lse2 -> (N,256)
    lse_mma_kernel<<<lse_grid, lblk>>>(coords, nidx, bufB, l2W1, l2b1, l2W2, l2b2, bufA, N);
    // p2: 256 -> 256 -> 256
    tgemm_kernel<<<grid(N, 256), gblk>>>(bufA, p2W1, p2b1, nullptr, bufC, N, 256, 256, 1);
    tgemm_kernel<<<grid(N, 256), gblk>>>(bufC, p2W2, p2b2, nullptr, bufB, N, 256, 256, 0);
    // m3(features): 128 -> 256 -> 512
    tgemm_kernel<<<grid(N, 256), gblk>>>(features, m3W1, m3b1, nullptr, bufA, N, 128, 256, 1);
    tgemm_kernel<<<grid(N, 512), gblk>>>(bufA,     m3W2, m3b2, nullptr, bufC, N, 256, 512, 0);
    // m2(x): 256 -> 384 -> 512, fused residual(+m3) + leaky_relu
    tgemm_kernel<<<grid(N, 384), gblk>>>(bufB, m2W1, m2b1, nullptr, bufA, N, 256, 384, 1);
    tgemm_kernel<<<grid(N, 512), gblk>>>(bufA, m2W2, m2b2, bufC,    out,  N, 384, 512, 2);
}

// round 6
// speedup vs baseline: 6.7868x; 1.1069x over previous
#include <cuda_runtime.h>
#include <math.h>
#include <stdint.h>

#define NMAX 100000
#define KNBR 16

// Scratch (static __device__ — allocation-guard safe)
__device__ float g_bufA[NMAX * 384];
__device__ float g_bufB[NMAX * 256];
__device__ float g_bufC[NMAX * 512];
__device__ float g_bufF[NMAX * 128];   // tf32-rounded features
__device__ float g_bufW[720896];       // tf32-rounded weights

__device__ __forceinline__ float to_tf32(float x) {
    float y;
    asm("cvt.rna.tf32.f32 %0, %1;" : "=f"(y) : "f"(x));
    return y;
}

__device__ __forceinline__ uint32_t smem_u32(const void* p) {
    uint32_t a;
    asm("{ .reg .u64 t; cvta.to.shared.u64 t, %1; cvt.u32.u64 %0, t; }"
        : "=r"(a) : "l"(p));
    return a;
}

__device__ __forceinline__ void cp_async16(uint32_t dst, const void* src, int szb) {
    asm volatile("cp.async.cg.shared.global [%0], [%1], 16, %2;"
                 :: "r"(dst), "l"(src), "r"(szb));
}

#define MMA_TF32(C, a0, a1, a2, a3, b0, b1)                                   \
    asm volatile(                                                             \
        "mma.sync.aligned.m16n8k8.row.col.f32.tf32.tf32.f32 "                 \
        "{%0,%1,%2,%3}, {%4,%5,%6,%7}, {%8,%9}, {%0,%1,%2,%3};"               \
        : "+f"((C)[0]), "+f"((C)[1]), "+f"((C)[2]), "+f"((C)[3])              \
        : "r"(a0), "r"(a1), "r"(a2), "r"(a3), "r"(b0), "r"(b1))

// ---------------------------------------------------------------------------
// Pre-rounding kernels (weights + features -> tf32-rounded copies).
// ---------------------------------------------------------------------------
struct WPack {
    const float* s[10];
    int n[10];
    int off[10];
};

__global__ void round_weights_kernel(WPack p, float* dst) {
    int m = blockIdx.y;
    int i = blockIdx.x * blockDim.x + threadIdx.x;
    if (i < p.n[m]) dst[p.off[m] + i] = to_tf32(p.s[m][i]);
}

__global__ void round_feat_kernel(const float* __restrict__ src,
                                  float* __restrict__ dst, int n) {
    int i = blockIdx.x * blockDim.x + threadIdx.x;
    if (i < n) dst[i] = to_tf32(src[i]);
}

// ---------------------------------------------------------------------------
// Tensor-core GEMM (tf32 mma.sync), cp.async double-buffered, TBK=32.
// C = act(A[M,K] @ W[K,O] + bias (+ res));  A and W must be tf32-pre-rounded.
// act low bits: 0 none, 1 relu, 2 leaky(x+res). Bit 2 (4): round output to tf32.
// Block 128x128, 4 warps (2x2), warp tile 64x64. K % 32 == 0, O % 128 == 0.
// ---------------------------------------------------------------------------
#define TBM 128
#define TBN 128
#define ASTR 36          // As [m][k] stride (4m+k bank bijection)
#define BSTR 136         // Bs [k][n] stride
#define AS_FL (128 * ASTR)        // 4608 floats per stage
#define BS_FL (32 * BSTR)         // 4352 floats per stage
#define GEMM_SMEM_BYTES ((2 * AS_FL + 2 * BS_FL) * 4)   // 71680

__device__ __forceinline__ void gemm_issue_tile(
    const float* __restrict__ A, const float* __restrict__ W,
    int M, int K, int O, int bm, int bn, int tid,
    uint32_t as_u32, uint32_t bs_u32, int stage, int kt)
{
    int k0 = kt * 32;
    int arow0 = tid >> 3, acol = (tid & 7) * 4;
    int brow0 = tid >> 5, bcol = (tid & 31) * 4;
#pragma unroll
    for (int i = 0; i < 8; i++) {
        int row = arow0 + 16 * i;
        const float* src = A + (size_t)(bm + row) * K + k0 + acol;
        uint32_t dst = as_u32 + ((stage * AS_FL + row * ASTR + acol) << 2);
        cp_async16(dst, src, (bm + row) < M ? 16 : 0);
    }
#pragma unroll
    for (int i = 0; i < 8; i++) {
        int kr = brow0 + 4 * i;
        const float* src = W + (size_t)(k0 + kr) * O + bn + bcol;
        uint32_t dst = bs_u32 + ((stage * BS_FL + kr * BSTR + bcol) << 2);
        cp_async16(dst, src, 16);
    }
    asm volatile("cp.async.commit_group;");
}

__global__ __launch_bounds__(128, 2) void tgemm_kernel(
    const float* __restrict__ A, const float* __restrict__ W,
    const float* __restrict__ bias, const float* __restrict__ res,
    float* __restrict__ C, int M, int K, int O, int act)
{
    extern __shared__ float sm[];
    float* Asm = sm;                       // [2][128][ASTR]
    float* Bsm = sm + 2 * AS_FL;           // [2][32][BSTR]
    uint32_t as_u32 = smem_u32(Asm);
    uint32_t bs_u32 = smem_u32(Bsm);

    int tid = threadIdx.x, lane = tid & 31, wid = tid >> 5;
    int bm = blockIdx.x * TBM, bn = blockIdx.y * TBN;
    int wm = wid & 1, wn = wid >> 1;
    int gid = lane >> 2, tig = lane & 3;
    bool rnd = (act & 4) != 0;
    int actv = act & 3;

    float c[4][8][4];
#pragma unroll
    for (int mt = 0; mt < 4; mt++)
#pragma unroll
        for (int nt = 0; nt < 8; nt++)
#pragma unroll
            for (int q = 0; q < 4; q++) c[mt][nt][q] = 0.f;

    int nk = K / 32;
    gemm_issue_tile(A, W, M, K, O, bm, bn, tid, as_u32, bs_u32, 0, 0);

    for (int kt = 0; kt < nk; kt++) {
        int s = kt & 1;
        if (kt + 1 < nk) {
            gemm_issue_tile(A, W, M, K, O, bm, bn, tid, as_u32, bs_u32, s ^ 1, kt + 1);
            asm volatile("cp.async.wait_group 1;");
        } else {
            asm volatile("cp.async.wait_group 0;");
        }
        __syncthreads();

        const float* Ast = Asm + s * AS_FL;
        const float* Bst = Bsm + s * BS_FL;
#pragma unroll
        for (int ks = 0; ks < 4; ks++) {
            int k0 = ks * 8;
            uint32_t af[4][4];
            int mbase = wm * 64;
#pragma unroll
            for (int mt = 0; mt < 4; mt++) {
                int m = mbase + mt * 16 + gid;
                af[mt][0] = __float_as_uint(Ast[m * ASTR + k0 + tig]);
                af[mt][1] = __float_as_uint(Ast[(m + 8) * ASTR + k0 + tig]);
                af[mt][2] = __float_as_uint(Ast[m * ASTR + k0 + tig + 4]);
                af[mt][3] = __float_as_uint(Ast[(m + 8) * ASTR + k0 + tig + 4]);
            }
            uint32_t bf[8][2];
            int nbase = wn * 64;
#pragma unroll
            for (int nt = 0; nt < 8; nt++) {
                int n = nbase + nt * 8 + gid;
                bf[nt][0] = __float_as_uint(Bst[(k0 + tig) * BSTR + n]);
                bf[nt][1] = __float_as_uint(Bst[(k0 + tig + 4) * BSTR + n]);
            }
#pragma unroll
            for (int mt = 0; mt < 4; mt++)
#pragma unroll
                for (int nt = 0; nt < 8; nt++)
                    MMA_TF32(c[mt][nt], af[mt][0], af[mt][1], af[mt][2],
                             af[mt][3], bf[nt][0], bf[nt][1]);
        }
        __syncthreads();
    }

#pragma unroll
    for (int mt = 0; mt < 4; mt++) {
        int r0 = bm + wm * 64 + mt * 16 + gid;
        int r1 = r0 + 8;
        bool v0 = r0 < M, v1 = r1 < M;
#pragma unroll
        for (int nt = 0; nt < 8; nt++) {
            int col = bn + wn * 64 + nt * 8 + tig * 2;
            float2 bb = *(const float2*)(bias + col);
            float2 o0 = make_float2(c[mt][nt][0] + bb.x, c[mt][nt][1] + bb.y);
            float2 o1 = make_float2(c[mt][nt][2] + bb.x, c[mt][nt][3] + bb.y);
            if (actv == 1) {
                o0.x = fmaxf(o0.x, 0.f); o0.y = fmaxf(o0.y, 0.f);
                o1.x = fmaxf(o1.x, 0.f); o1.y = fmaxf(o1.y, 0.f);
            } else if (actv == 2) {
                if (v0) {
                    float2 r = *(const float2*)(res + (size_t)r0 * O + col);
                    o0.x += r.x; o0.y += r.y;
                }
                if (v1) {
                    float2 r = *(const float2*)(res + (size_t)r1 * O + col);
                    o1.x += r.x; o1.y += r.y;
                }
                o0.x = (o0.x > 0.f) ? o0.x : 0.01f * o0.x;
                o0.y = (o0.y > 0.f) ? o0.y : 0.01f * o0.y;
                o1.x = (o1.x > 0.f) ? o1.x : 0.01f * o1.x;
                o1.y = (o1.y > 0.f) ? o1.y : 0.01f * o1.y;
            }
            if (rnd) {
                o0.x = to_tf32(o0.x); o0.y = to_tf32(o0.y);
                o1.x = to_tf32(o1.x); o1.y = to_tf32(o1.y);
            }
            if (v0) *(float2*)(C + (size_t)r0 * O + col) = o0;
            if (v1) *(float2*)(C + (size_t)r1 * O + col) = o1;
        }
    }
}

// ---------------------------------------------------------------------------
// LSE + attentive pool, tensor-core version (R4 layout, outputs tf32-rounded).
// ---------------------------------------------------------------------------
#define LSTR 136

__global__ __launch_bounds__(256) void lse_mma_kernel(
    const float* __restrict__ coords, const int* __restrict__ nidx,
    const float* __restrict__ feats,
    const float* __restrict__ W1, const float* __restrict__ B1,
    const float* __restrict__ W2, const float* __restrict__ B2,
    float* __restrict__ outF, int N)
{
    __shared__ float sW1[640];
    __shared__ float sB1[64];
    __shared__ float sB2[128];
    __shared__ float sW2[64 * LSTR];

    int tid = threadIdx.x, lane = tid & 31, wid = tid >> 5;
    int gid = lane >> 2, tig = lane & 3;

    for (int i = tid; i < 640; i += 256) sW1[i] = W1[i];
    if (tid < 64) sB1[tid] = B1[tid];
    if (tid < 128) sB2[tid] = B2[tid];
    for (int i = tid; i < 8192; i += 256) {
        int k = i >> 7, ch = i & 127;
        sW2[k * LSTR + ch] = to_tf32(W2[i]);
    }
    __syncthreads();

    int nbase = blockIdx.x * 64 + wid * 8;
    for (int p = 0; p < 8; p++) {
        int n = nbase + p;
        if (n >= N) break;

        int ib0 = nidx[n * KNBR + gid];
        int ib1 = nidx[n * KNBR + gid + 8];
        float ox = coords[n * 3], oy = coords[n * 3 + 1], oz = coords[n * 3 + 2];
        float ax = coords[ib0 * 3], ay = coords[ib0 * 3 + 1], az = coords[ib0 * 3 + 2];
        float bx = coords[ib1 * 3], by = coords[ib1 * 3 + 1], bz = coords[ib1 * 3 + 2];
        float arx = ox - ax, ary = oy - ay, arz = oz - az;
        float brx = ox - bx, bry = oy - by, brz = oz - bz;
        float ad = sqrtf(arx * arx + ary * ary + arz * arz);
        float bd = sqrtf(brx * brx + bry * bry + brz * brz);
        float ca[10] = {ox, oy, oz, ax, ay, az, arx, ary, arz, ad};
        float cb[10] = {ox, oy, oz, bx, by, bz, brx, bry, brz, bd};

        uint32_t hb0[16], hb1[16];
#pragma unroll
        for (int j = 0; j < 16; j++) {
            int ch = tig + 4 * j;
            float h0 = sB1[ch], h1 = h0;
#pragma unroll
            for (int i = 0; i < 10; i++) {
                float w = sW1[i * 64 + ch];
                h0 = fmaf(ca[i], w, h0);
                h1 = fmaf(cb[i], w, h1);
            }
            hb0[j] = __float_as_uint(to_tf32(fmaxf(h0, 0.f)));
            hb1[j] = __float_as_uint(to_tf32(fmaxf(h1, 0.f)));
        }

        float c_[8][2][4];
#pragma unroll
        for (int mt = 0; mt < 8; mt++)
#pragma unroll
            for (int nt = 0; nt < 2; nt++)
#pragma unroll
                for (int q = 0; q < 4; q++) c_[mt][nt][q] = 0.f;

#pragma unroll
        for (int s = 0; s < 8; s++) {
            uint32_t b00 = hb0[2 * s], b01 = hb0[2 * s + 1];
            uint32_t b10 = hb1[2 * s], b11 = hb1[2 * s + 1];
            const float* r0 = &sW2[(8 * s + tig) * LSTR];
            const float* r1 = &sW2[(8 * s + tig + 4) * LSTR];
#pragma unroll
            for (int mt = 0; mt < 8; mt++) {
                int cb0 = 16 * mt + gid;
                uint32_t a0 = __float_as_uint(r0[cb0]);
                uint32_t a1 = __float_as_uint(r0[cb0 + 8]);
                uint32_t a2 = __float_as_uint(r1[cb0]);
                uint32_t a3 = __float_as_uint(r1[cb0 + 8]);
                MMA_TF32(c_[mt][0], a0, a1, a2, a3, b00, b01);
                MMA_TF32(c_[mt][1], a0, a1, a2, a3, b10, b11);
            }
        }

#pragma unroll
        for (int mt = 0; mt < 8; mt++) {
            float bb0 = sB2[16 * mt + gid], bb1 = sB2[16 * mt + gid + 8];
#pragma unroll
            for (int nt = 0; nt < 2; nt++) {
                c_[mt][nt][0] += bb0; c_[mt][nt][1] += bb0;
                c_[mt][nt][2] += bb1; c_[mt][nt][3] += bb1;
            }
        }

        float4 f4 = *(const float4*)(feats + (size_t)n * 128 + 4 * lane);
        float mf = fmaxf(fmaxf(f4.x, f4.y), fmaxf(f4.z, f4.w));
#pragma unroll
        for (int o = 16; o > 0; o >>= 1)
            mf = fmaxf(mf, __shfl_xor_sync(0xffffffffu, mf, o));
        float sf = __expf(f4.x - mf) + __expf(f4.y - mf) +
                   __expf(f4.z - mf) + __expf(f4.w - mf);
#pragma unroll
        for (int o = 16; o > 0; o >>= 1)
            sf += __shfl_xor_sync(0xffffffffu, sf, o);

        float mrow[4], inv[4];
#pragma unroll
        for (int j = 0; j < 4; j++) {
            int nt = j >> 1, q = j & 1;
            float m = c_[0][nt][q];
#pragma unroll
            for (int mt = 0; mt < 8; mt++) {
                m = fmaxf(m, c_[mt][nt][q]);
                m = fmaxf(m, c_[mt][nt][q + 2]);
            }
#pragma unroll
            for (int o = 4; o <= 16; o <<= 1)
                m = fmaxf(m, __shfl_xor_sync(0xffffffffu, m, o));
            mrow[j] = fmaxf(m, mf);
        }
#pragma unroll
        for (int j = 0; j < 4; j++) {
            int nt = j >> 1, q = j & 1;
            float s = 0.f;
#pragma unroll
            for (int mt = 0; mt < 8; mt++) {
                s += __expf(c_[mt][nt][q] - mrow[j]);
                s += __expf(c_[mt][nt][q + 2] - mrow[j]);
            }
#pragma unroll
            for (int o = 4; o <= 16; o <<= 1)
                s += __shfl_xor_sync(0xffffffffu, s, o);
            inv[j] = 1.f / (s + __expf(mf - mrow[j]) * sf);
        }

        float Tl = 0.f;
#pragma unroll
        for (int j = 0; j < 4; j++) Tl += __expf(mf - mrow[j]) * inv[j];
        Tl += __shfl_xor_sync(0xffffffffu, Tl, 1);
        Tl += __shfl_xor_sync(0xffffffffu, Tl, 2);

        float ov[8][2];
#pragma unroll
        for (int mt = 0; mt < 8; mt++) { ov[mt][0] = 0.f; ov[mt][1] = 0.f; }
#pragma unroll
        for (int j = 0; j < 4; j++) {
            int nt = j >> 1, q = j & 1;
            float w = inv[j], mr = mrow[j];
#pragma unroll
            for (int mt = 0; mt < 8; mt++) {
                float v0 = c_[mt][nt][q];
                float v1 = c_[mt][nt][q + 2];
                ov[mt][0] = fmaf(__expf(v0 - mr) * w, v0, ov[mt][0]);
                ov[mt][1] = fmaf(__expf(v1 - mr) * w, v1, ov[mt][1]);
            }
        }
#pragma unroll
        for (int mt = 0; mt < 8; mt++) {
#pragma unroll
            for (int cs = 0; cs < 2; cs++) {
                ov[mt][cs] += __shfl_xor_sync(0xffffffffu, ov[mt][cs], 1);
                ov[mt][cs] += __shfl_xor_sync(0xffffffffu, ov[mt][cs], 2);
            }
        }

        float* po = outF + (size_t)n * 256;
#pragma unroll
        for (int t = 0; t < 2; t++) {
            int mt = 2 * tig + t;
            po[16 * mt + gid]     = to_tf32(ov[mt][0]);
            po[16 * mt + gid + 8] = to_tf32(ov[mt][1]);
        }
        float4 g;
        g.x = to_tf32(f4.x * __expf(f4.x - mf) * Tl);
        g.y = to_tf32(f4.y * __expf(f4.y - mf) * Tl);
        g.z = to_tf32(f4.z * __expf(f4.z - mf) * Tl);
        g.w = to_tf32(f4.w * __expf(f4.w - mf) * Tl);
        *(float4*)(po + 128 + 4 * lane) = g;
    }
}

// ---------------------------------------------------------------------------
extern "C" void kernel_launch(void* const* d_in, const int* in_sizes, int n_in,
                              void* d_out, int out_size)
{
    const float* coords   = (const float*)d_in[0];
    const float* features = (const float*)d_in[1];
    const int*   nidx     = (const int*)d_in[2];
    const float* m1W1 = (const float*)d_in[3];  const float* m1b1 = (const float*)d_in[4];
    const float* m1W2 = (const float*)d_in[5];  const float* m1b2 = (const float*)d_in[6];
    const float* m2W1 = (const float*)d_in[7];  const float* m2b1 = (const float*)d_in[8];
    const float* m2W2 = (const float*)d_in[9];  const float* m2b2 = (const float*)d_in[10];
    const float* m3W1 = (const float*)d_in[11]; const float* m3b1 = (const float*)d_in[12];
    const float* m3W2 = (const float*)d_in[13]; const float* m3b2 = (const float*)d_in[14];
    const float* l1W1 = (const float*)d_in[15]; const float* l1b1 = (const float*)d_in[16];
    const float* l1W2 = (const float*)d_in[17]; const float* l1b2 = (const float*)d_in[18];
    const float* l2W1 = (const float*)d_in[19]; const float* l2b1 = (const float*)d_in[20];
    const float* l2W2 = (const float*)d_in[21]; const float* l2b2 = (const float*)d_in[22];
    const float* p1W1 = (const float*)d_in[23]; const float* p1b1 = (const float*)d_in[24];
    const float* p1W2 = (const float*)d_in[25]; const float* p1b2 = (const float*)d_in[26];
    const float* p2W1 = (const float*)d_in[27]; const float* p2b1 = (const float*)d_in[28];
    const float* p2W2 = (const float*)d_in[29]; const float* p2b2 = (const float*)d_in[30];
    float* out = (float*)d_out;

    int N = in_sizes[0] / 3;

    float *bufA, *bufB, *bufC, *bufF, *bufW;
    cudaGetSymbolAddress((void**)&bufA, g_bufA);
    cudaGetSymbolAddress((void**)&bufB, g_bufB);
    cudaGetSymbolAddress((void**)&bufC, g_bufC);
    cudaGetSymbolAddress((void**)&bufF, g_bufF);
    cudaGetSymbolAddress((void**)&bufW, g_bufW);

    cudaFuncSetAttribute(tgemm_kernel,
                         cudaFuncAttributeMaxDynamicSharedMemorySize,
                         GEMM_SMEM_BYTES);

    // tf32-rounded weight copies (offsets into g_bufW)
    const int oM1W1 = 0,      nM1W1 = 128 * 128;
    const int oM1W2 = 16384,  nM1W2 = 128 * 128;
    const int oM2W1 = 32768,  nM2W1 = 256 * 384;
    const int oM2W2 = 131072, nM2W2 = 384 * 512;
    const int oM3W1 = 327680, nM3W1 = 128 * 256;
    const int oM3W2 = 360448, nM3W2 = 256 * 512;
    const int oP1W1 = 491520, nP1W1 = 256 * 256;
    const int oP1W2 = 557056, nP1W2 = 256 * 128;
    const int oP2W1 = 589824, nP2W1 = 256 * 256;
    const int oP2W2 = 655360, nP2W2 = 256 * 256;

    WPack wp;
    wp.s[0] = m1W1; wp.n[0] = nM1W1; wp.off[0] = oM1W1;
    wp.s[1] = m1W2; wp.n[1] = nM1W2; wp.off[1] = oM1W2;
    wp.s[2] = m2W1; wp.n[2] = nM2W1; wp.off[2] = oM2W1;
    wp.s[3] = m2W2; wp.n[3] = nM2W2; wp.off[3] = oM2W2;
    wp.s[4] = m3W1; wp.n[4] = nM3W1; wp.off[4] = oM3W1;
    wp.s[5] = m3W2; wp.n[5] = nM3W2; wp.off[5] = oM3W2;
    wp.s[6] = p1W1; wp.n[6] = nP1W1; wp.off[6] = oP1W1;
    wp.s[7] = p1W2; wp.n[7] = nP1W2; wp.off[7] = oP1W2;
    wp.s[8] = p2W1; wp.n[8] = nP2W1; wp.off[8] = oP2W1;
    wp.s[9] = p2W2; wp.n[9] = nP2W2; wp.off[9] = oP2W2;

    round_weights_kernel<<<dim3(192, 10), 1024>>>(wp, bufW);
    round_feat_kernel<<<(N * 128 + 1023) / 1024, 1024>>>(features, bufF, N * 128);

    dim3 gblk(128), lblk(256);
    auto grid = [&](int M, int O) { return dim3((M + TBM - 1) / TBM, O / TBN); };
    int lse_grid = (N + 63) / 64;
    int SB = GEMM_SMEM_BYTES;

    // x = mlp1(features): 128 -> 128 -> 128
    tgemm_kernel<<<grid(N, 128), gblk, SB>>>(bufF, bufW + oM1W1, m1b1, nullptr, bufA, N, 128, 128, 5);
    tgemm_kernel<<<grid(N, 128), gblk, SB>>>(bufA, bufW + oM1W2, m1b2, nullptr, bufB, N, 128, 128, 0);
    // lse1 + channel-softmax pool -> (N,256)  [outputs tf32-rounded]
    lse_mma_kernel<<<lse_grid, lblk>>>(coords, nidx, bufB, l1W1, l1b1, l1W2, l1b2, bufA, N);
    // p1: 256 -> 256 -> 128
    tgemm_kernel<<<grid(N, 256), gblk, SB>>>(bufA, bufW + oP1W1, p1b1, nullptr, bufC, N, 256, 256, 5);
    tgemm_kernel<<<grid(N, 128), gblk, SB>>>(bufC, bufW + oP1W2, p1b2, nullptr, bufB, N, 256, 128, 0);
    // lse2 -> (N,256)
    lse_mma_kernel<<<lse_grid, lblk>>>(coords, nidx, bufB, l2W1, l2b1, l2W2, l2b2, bufA, N);
    // p2: 256 -> 256 -> 256
    tgemm_kernel<<<grid(N, 256), gblk, SB>>>(bufA, bufW + oP2W1, p2b1, nullptr, bufC, N, 256, 256, 5);
    tgemm_kernel<<<grid(N, 256), gblk, SB>>>(bufC, bufW + oP2W2, p2b2, nullptr, bufB, N, 256, 256, 4);
    // m3(features): 128 -> 256 -> 512
    tgemm_kernel<<<grid(N, 256), gblk, SB>>>(bufF, bufW + oM3W1, m3b1, nullptr, bufA, N, 128, 256, 5);
    tgemm_kernel<<<grid(N, 512), gblk, SB>>>(bufA, bufW + oM3W2, m3b2, nullptr, bufC, N, 256, 512, 0);
    // m2(x): 256 -> 384 -> 512, fused residual(+m3) + leaky_relu
    tgemm_kernel<<<grid(N, 384), gblk, SB>>>(bufB, bufW + oM2W1, m2b1, nullptr, bufA, N, 256, 384, 5);
    tgemm_kernel<<<grid(N, 512), gblk, SB>>>(bufA, bufW + oM2W2, m2b2, bufC, out, N, 384, 512, 2);
}

// round 7
// speedup vs baseline: 7.6485x; 1.1270x over previous
#include <cuda_runtime.h>
#include <math.h>
#include <stdint.h>

#define NMAX 100000
#define KNBR 16

// Scratch (static __device__ — allocation-guard safe)
__device__ float g_bufA[NMAX * 384];
__device__ float g_bufB[NMAX * 256];
__device__ float g_bufC[NMAX * 512];
__device__ float g_bufF[NMAX * 128];   // tf32-rounded features
__device__ float g_bufW[720896];       // tf32-rounded weights

__device__ __forceinline__ float to_tf32(float x) {
    float y;
    asm("cvt.rna.tf32.f32 %0, %1;" : "=f"(y) : "f"(x));
    return y;
}

__device__ __forceinline__ uint32_t smem_u32(const void* p) {
    uint32_t a;
    asm("{ .reg .u64 t; cvta.to.shared.u64 t, %1; cvt.u32.u64 %0, t; }"
        : "=r"(a) : "l"(p));
    return a;
}

__device__ __forceinline__ void cp_async16(uint32_t dst, const void* src, int szb) {
    asm volatile("cp.async.cg.shared.global [%0], [%1], 16, %2;"
                 :: "r"(dst), "l"(src), "r"(szb));
}

#define MMA_TF32(C, a0, a1, a2, a3, b0, b1)                                   \
    asm volatile(                                                             \
        "mma.sync.aligned.m16n8k8.row.col.f32.tf32.tf32.f32 "                 \
        "{%0,%1,%2,%3}, {%4,%5,%6,%7}, {%8,%9}, {%0,%1,%2,%3};"               \
        : "+f"((C)[0]), "+f"((C)[1]), "+f"((C)[2]), "+f"((C)[3])              \
        : "r"(a0), "r"(a1), "r"(a2), "r"(a3), "r"(b0), "r"(b1))

// ---------------------------------------------------------------------------
// Pre-rounding kernels.
// ---------------------------------------------------------------------------
struct WPack {
    const float* s[10];
    int n[10];
    int off[10];
};

__global__ void round_weights_kernel(WPack p, float* dst) {
    int m = blockIdx.y;
    int i = blockIdx.x * blockDim.x + threadIdx.x;
    if (i < p.n[m]) dst[p.off[m] + i] = to_tf32(p.s[m][i]);
}

__global__ void round_feat_kernel(const float* __restrict__ src,
                                  float* __restrict__ dst, int n) {
    int i = blockIdx.x * blockDim.x + threadIdx.x;
    if (i < n) dst[i] = to_tf32(src[i]);
}

// ---------------------------------------------------------------------------
// Tensor-core GEMM (tf32 mma.sync), cp.async 3-stage pipeline, TBK=32.
// act bits 0-1: 0 none, 1 relu, 2 leaky(x+res). Bit 2: round output to tf32.
// Block 128x128, 4 warps (2x2), warp tile 64x64. K % 32 == 0, O % 128 == 0.
// ---------------------------------------------------------------------------
#define TBM 128
#define TBN 128
#define ASTR 36
#define BSTR 136
#define AS_FL (128 * ASTR)        // 4608 floats per stage
#define BS_FL (32 * BSTR)         // 4352 floats per stage
#define NSTG 3
#define GEMM_SMEM_BYTES (NSTG * (AS_FL + BS_FL) * 4)   // 107520

__device__ __forceinline__ void gemm_issue_tile(
    const float* __restrict__ A, const float* __restrict__ W,
    int M, int K, int O, int bm, int bn, int tid,
    uint32_t as_u32, uint32_t bs_u32, int stage, int kt)
{
    int k0 = kt * 32;
    int arow0 = tid >> 3, acol = (tid & 7) * 4;
    int brow0 = tid >> 5, bcol = (tid & 31) * 4;
#pragma unroll
    for (int i = 0; i < 8; i++) {
        int row = arow0 + 16 * i;
        const float* src = A + (size_t)(bm + row) * K + k0 + acol;
        uint32_t dst = as_u32 + ((stage * AS_FL + row * ASTR + acol) << 2);
        cp_async16(dst, src, (bm + row) < M ? 16 : 0);
    }
#pragma unroll
    for (int i = 0; i < 8; i++) {
        int kr = brow0 + 4 * i;
        const float* src = W + (size_t)(k0 + kr) * O + bn + bcol;
        uint32_t dst = bs_u32 + ((stage * BS_FL + kr * BSTR + bcol) << 2);
        cp_async16(dst, src, 16);
    }
    asm volatile("cp.async.commit_group;");
}

__global__ __launch_bounds__(128, 2) void tgemm_kernel(
    const float* __restrict__ A, const float* __restrict__ W,
    const float* __restrict__ bias, const float* __restrict__ res,
    float* __restrict__ C, int M, int K, int O, int act)
{
    extern __shared__ float sm[];
    float* Asm = sm;                          // [NSTG][128][ASTR]
    float* Bsm = sm + NSTG * AS_FL;           // [NSTG][32][BSTR]
    uint32_t as_u32 = smem_u32(Asm);
    uint32_t bs_u32 = smem_u32(Bsm);

    int tid = threadIdx.x, lane = tid & 31, wid = tid >> 5;
    int bm = blockIdx.x * TBM, bn = blockIdx.y * TBN;
    int wm = wid & 1, wn = wid >> 1;
    int gid = lane >> 2, tig = lane & 3;
    bool rnd = (act & 4) != 0;
    int actv = act & 3;

    float c[4][8][4];
#pragma unroll
    for (int mt = 0; mt < 4; mt++)
#pragma unroll
        for (int nt = 0; nt < 8; nt++)
#pragma unroll
            for (int q = 0; q < 4; q++) c[mt][nt][q] = 0.f;

    int nk = K / 32;
    gemm_issue_tile(A, W, M, K, O, bm, bn, tid, as_u32, bs_u32, 0, 0);
    gemm_issue_tile(A, W, M, K, O, bm, bn, tid, as_u32, bs_u32, 1, 1);

    for (int kt = 0; kt < nk; kt++) {
        int s = kt % NSTG;
        if (kt + 2 < nk) {
            gemm_issue_tile(A, W, M, K, O, bm, bn, tid, as_u32, bs_u32,
                            (kt + 2) % NSTG, kt + 2);
            asm volatile("cp.async.wait_group 2;");
        } else if (kt + 1 < nk) {
            asm volatile("cp.async.wait_group 1;");
        } else {
            asm volatile("cp.async.wait_group 0;");
        }
        __syncthreads();

        const float* Ast = Asm + s * AS_FL;
        const float* Bst = Bsm + s * BS_FL;
#pragma unroll
        for (int ks = 0; ks < 4; ks++) {
            int k0 = ks * 8;
            uint32_t af[4][4];
            int mbase = wm * 64;
#pragma unroll
            for (int mt = 0; mt < 4; mt++) {
                int m = mbase + mt * 16 + gid;
                af[mt][0] = __float_as_uint(Ast[m * ASTR + k0 + tig]);
                af[mt][1] = __float_as_uint(Ast[(m + 8) * ASTR + k0 + tig]);
                af[mt][2] = __float_as_uint(Ast[m * ASTR + k0 + tig + 4]);
                af[mt][3] = __float_as_uint(Ast[(m + 8) * ASTR + k0 + tig + 4]);
            }
            uint32_t bf[8][2];
            int nbase = wn * 64;
#pragma unroll
            for (int nt = 0; nt < 8; nt++) {
                int n = nbase + nt * 8 + gid;
                bf[nt][0] = __float_as_uint(Bst[(k0 + tig) * BSTR + n]);
                bf[nt][1] = __float_as_uint(Bst[(k0 + tig + 4) * BSTR + n]);
            }
#pragma unroll
            for (int mt = 0; mt < 4; mt++)
#pragma unroll
                for (int nt = 0; nt < 8; nt++)
                    MMA_TF32(c[mt][nt], af[mt][0], af[mt][1], af[mt][2],
                             af[mt][3], bf[nt][0], bf[nt][1]);
        }
        __syncthreads();
    }

#pragma unroll
    for (int mt = 0; mt < 4; mt++) {
        int r0 = bm + wm * 64 + mt * 16 + gid;
        int r1 = r0 + 8;
        bool v0 = r0 < M, v1 = r1 < M;
#pragma unroll
        for (int nt = 0; nt < 8; nt++) {
            int col = bn + wn * 64 + nt * 8 + tig * 2;
            float2 bb = *(const float2*)(bias + col);
            float2 o0 = make_float2(c[mt][nt][0] + bb.x, c[mt][nt][1] + bb.y);
            float2 o1 = make_float2(c[mt][nt][2] + bb.x, c[mt][nt][3] + bb.y);
            if (actv == 1) {
                o0.x = fmaxf(o0.x, 0.f); o0.y = fmaxf(o0.y, 0.f);
                o1.x = fmaxf(o1.x, 0.f); o1.y = fmaxf(o1.y, 0.f);
            } else if (actv == 2) {
                if (v0) {
                    float2 r = *(const float2*)(res + (size_t)r0 * O + col);
                    o0.x += r.x; o0.y += r.y;
                }
                if (v1) {
                    float2 r = *(const float2*)(res + (size_t)r1 * O + col);
                    o1.x += r.x; o1.y += r.y;
                }
                o0.x = (o0.x > 0.f) ? o0.x : 0.01f * o0.x;
                o0.y = (o0.y > 0.f) ? o0.y : 0.01f * o0.y;
                o1.x = (o1.x > 0.f) ? o1.x : 0.01f * o1.x;
                o1.y = (o1.y > 0.f) ? o1.y : 0.01f * o1.y;
            }
            if (rnd) {
                o0.x = to_tf32(o0.x); o0.y = to_tf32(o0.y);
                o1.x = to_tf32(o1.x); o1.y = to_tf32(o1.y);
            }
            if (v0) *(float2*)(C + (size_t)r0 * O + col) = o0;
            if (v1) *(float2*)(C + (size_t)r1 * O + col) = o1;
        }
    }
}

// ---------------------------------------------------------------------------
// LSE + attentive pool, tensor-core version. Softmax WITHOUT max-subtraction
// (shift-invariant; values are O(1-10), fp32 exp safe), each exp computed once.
// ---------------------------------------------------------------------------
#define LSTR 136

__global__ __launch_bounds__(256) void lse_mma_kernel(
    const float* __restrict__ coords, const int* __restrict__ nidx,
    const float* __restrict__ feats,
    const float* __restrict__ W1, const float* __restrict__ B1,
    const float* __restrict__ W2, const float* __restrict__ B2,
    float* __restrict__ outF, int N)
{
    __shared__ float sW1[640];
    __shared__ float sB1[64];
    __shared__ float sB2[128];
    __shared__ float sW2[64 * LSTR];

    int tid = threadIdx.x, lane = tid & 31, wid = tid >> 5;
    int gid = lane >> 2, tig = lane & 3;

    for (int i = tid; i < 640; i += 256) sW1[i] = W1[i];
    if (tid < 64) sB1[tid] = B1[tid];
    if (tid < 128) sB2[tid] = B2[tid];
    for (int i = tid; i < 8192; i += 256) {
        int k = i >> 7, ch = i & 127;
        sW2[k * LSTR + ch] = to_tf32(W2[i]);
    }
    __syncthreads();

    int nbase = blockIdx.x * 64 + wid * 8;
    for (int p = 0; p < 8; p++) {
        int n = nbase + p;
        if (n >= N) break;

        int ib0 = nidx[n * KNBR + gid];
        int ib1 = nidx[n * KNBR + gid + 8];
        float ox = coords[n * 3], oy = coords[n * 3 + 1], oz = coords[n * 3 + 2];
        float ax = coords[ib0 * 3], ay = coords[ib0 * 3 + 1], az = coords[ib0 * 3 + 2];
        float bx = coords[ib1 * 3], by = coords[ib1 * 3 + 1], bz = coords[ib1 * 3 + 2];
        float arx = ox - ax, ary = oy - ay, arz = oz - az;
        float brx = ox - bx, bry = oy - by, brz = oz - bz;
        float ad = sqrtf(arx * arx + ary * ary + arz * arz);
        float bd = sqrtf(brx * brx + bry * bry + brz * brz);
        float ca[10] = {ox, oy, oz, ax, ay, az, arx, ary, arz, ad};
        float cb[10] = {ox, oy, oz, bx, by, bz, brx, bry, brz, bd};

        uint32_t hb0[16], hb1[16];
#pragma unroll
        for (int j = 0; j < 16; j++) {
            int ch = tig + 4 * j;
            float h0 = sB1[ch], h1 = h0;
#pragma unroll
            for (int i = 0; i < 10; i++) {
                float w = sW1[i * 64 + ch];
                h0 = fmaf(ca[i], w, h0);
                h1 = fmaf(cb[i], w, h1);
            }
            hb0[j] = __float_as_uint(to_tf32(fmaxf(h0, 0.f)));
            hb1[j] = __float_as_uint(to_tf32(fmaxf(h1, 0.f)));
        }

        float c_[8][2][4];
#pragma unroll
        for (int mt = 0; mt < 8; mt++)
#pragma unroll
            for (int nt = 0; nt < 2; nt++)
#pragma unroll
                for (int q = 0; q < 4; q++) c_[mt][nt][q] = 0.f;

#pragma unroll
        for (int s = 0; s < 8; s++) {
            uint32_t b00 = hb0[2 * s], b01 = hb0[2 * s + 1];
            uint32_t b10 = hb1[2 * s], b11 = hb1[2 * s + 1];
            const float* r0 = &sW2[(8 * s + tig) * LSTR];
            const float* r1 = &sW2[(8 * s + tig + 4) * LSTR];
#pragma unroll
            for (int mt = 0; mt < 8; mt++) {
                int cb0 = 16 * mt + gid;
                uint32_t a0 = __float_as_uint(r0[cb0]);
                uint32_t a1 = __float_as_uint(r0[cb0 + 8]);
                uint32_t a2 = __float_as_uint(r1[cb0]);
                uint32_t a3 = __float_as_uint(r1[cb0 + 8]);
                MMA_TF32(c_[mt][0], a0, a1, a2, a3, b00, b01);
                MMA_TF32(c_[mt][1], a0, a1, a2, a3, b10, b11);
            }
        }

#pragma unroll
        for (int mt = 0; mt < 8; mt++) {
            float bb0 = sB2[16 * mt + gid], bb1 = sB2[16 * mt + gid + 8];
#pragma unroll
            for (int nt = 0; nt < 2; nt++) {
                c_[mt][nt][0] += bb0; c_[mt][nt][1] += bb0;
                c_[mt][nt][2] += bb1; c_[mt][nt][3] += bb1;
            }
        }

        // ---- feats exps (no max subtraction) ----
        float4 f4 = *(const float4*)(feats + (size_t)n * 128 + 4 * lane);
        float ef[4] = {__expf(f4.x), __expf(f4.y), __expf(f4.z), __expf(f4.w)};
        float sf = ef[0] + ef[1] + ef[2] + ef[3];
#pragma unroll
        for (int o = 16; o > 0; o >>= 1)
            sf += __shfl_xor_sync(0xffffffffu, sf, o);

        // ---- per-row softmax + pool, exp computed once ----
        float ov[8][2];
#pragma unroll
        for (int mt = 0; mt < 8; mt++) { ov[mt][0] = 0.f; ov[mt][1] = 0.f; }
        float Tl = 0.f;

#pragma unroll
        for (int j = 0; j < 4; j++) {
            int nt = j >> 1, q = j & 1;
            float e0[8], e1[8], s = 0.f;
#pragma unroll
            for (int mt = 0; mt < 8; mt++) {
                e0[mt] = __expf(c_[mt][nt][q]);
                e1[mt] = __expf(c_[mt][nt][q + 2]);
                s += e0[mt] + e1[mt];
            }
#pragma unroll
            for (int o = 4; o <= 16; o <<= 1)
                s += __shfl_xor_sync(0xffffffffu, s, o);
            float inv = 1.f / (s + sf);
            Tl += inv;
#pragma unroll
            for (int mt = 0; mt < 8; mt++) {
                ov[mt][0] = fmaf(e0[mt] * inv, c_[mt][nt][q], ov[mt][0]);
                ov[mt][1] = fmaf(e1[mt] * inv, c_[mt][nt][q + 2], ov[mt][1]);
            }
        }
        Tl += __shfl_xor_sync(0xffffffffu, Tl, 1);
        Tl += __shfl_xor_sync(0xffffffffu, Tl, 2);

#pragma unroll
        for (int mt = 0; mt < 8; mt++) {
#pragma unroll
            for (int cs = 0; cs < 2; cs++) {
                ov[mt][cs] += __shfl_xor_sync(0xffffffffu, ov[mt][cs], 1);
                ov[mt][cs] += __shfl_xor_sync(0xffffffffu, ov[mt][cs], 2);
            }
        }

        float* po = outF + (size_t)n * 256;
#pragma unroll
        for (int t = 0; t < 2; t++) {
            int mt = 2 * tig + t;
            po[16 * mt + gid]     = to_tf32(ov[mt][0]);
            po[16 * mt + gid + 8] = to_tf32(ov[mt][1]);
        }
        float4 g;
        g.x = to_tf32(f4.x * ef[0] * Tl);
        g.y = to_tf32(f4.y * ef[1] * Tl);
        g.z = to_tf32(f4.z * ef[2] * Tl);
        g.w = to_tf32(f4.w * ef[3] * Tl);
        *(float4*)(po + 128 + 4 * lane) = g;
    }
}

// ---------------------------------------------------------------------------
extern "C" void kernel_launch(void* const* d_in, const int* in_sizes, int n_in,
                              void* d_out, int out_size)
{
    const float* coords   = (const float*)d_in[0];
    const float* features = (const float*)d_in[1];
    const int*   nidx     = (const int*)d_in[2];
    const float* m1W1 = (const float*)d_in[3];  const float* m1b1 = (const float*)d_in[4];
    const float* m1W2 = (const float*)d_in[5];  const float* m1b2 = (const float*)d_in[6];
    const float* m2W1 = (const float*)d_in[7];  const float* m2b1 = (const float*)d_in[8];
    const float* m2W2 = (const float*)d_in[9];  const float* m2b2 = (const float*)d_in[10];
    const float* m3W1 = (const float*)d_in[11]; const float* m3b1 = (const float*)d_in[12];
    const float* m3W2 = (const float*)d_in[13]; const float* m3b2 = (const float*)d_in[14];
    const float* l1W1 = (const float*)d_in[15]; const float* l1b1 = (const float*)d_in[16];
    const float* l1W2 = (const float*)d_in[17]; const float* l1b2 = (const float*)d_in[18];
    const float* l2W1 = (const float*)d_in[19]; const float* l2b1 = (const float*)d_in[20];
    const float* l2W2 = (const float*)d_in[21]; const float* l2b2 = (const float*)d_in[22];
    const float* p1W1 = (const float*)d_in[23]; const float* p1b1 = (const float*)d_in[24];
    const float* p1W2 = (const float*)d_in[25]; const float* p1b2 = (const float*)d_in[26];
    const float* p2W1 = (const float*)d_in[27]; const float* p2b1 = (const float*)d_in[28];
    const float* p2W2 = (const float*)d_in[29]; const float* p2b2 = (const float*)d_in[30];
    float* out = (float*)d_out;

    int N = in_sizes[0] / 3;

    float *bufA, *bufB, *bufC, *bufF, *bufW;
    cudaGetSymbolAddress((void**)&bufA, g_bufA);
    cudaGetSymbolAddress((void**)&bufB, g_bufB);
    cudaGetSymbolAddress((void**)&bufC, g_bufC);
    cudaGetSymbolAddress((void**)&bufF, g_bufF);
    cudaGetSymbolAddress((void**)&bufW, g_bufW);

    cudaFuncSetAttribute(tgemm_kernel,
                         cudaFuncAttributeMaxDynamicSharedMemorySize,
                         GEMM_SMEM_BYTES);

    const int oM1W1 = 0,      nM1W1 = 128 * 128;
    const int oM1W2 = 16384,  nM1W2 = 128 * 128;
    const int oM2W1 = 32768,  nM2W1 = 256 * 384;
    const int oM2W2 = 131072, nM2W2 = 384 * 512;
    const int oM3W1 = 327680, nM3W1 = 128 * 256;
    const int oM3W2 = 360448, nM3W2 = 256 * 512;
    const int oP1W1 = 491520, nP1W1 = 256 * 256;
    const int oP1W2 = 557056, nP1W2 = 256 * 128;
    const int oP2W1 = 589824, nP2W1 = 256 * 256;
    const int oP2W2 = 655360, nP2W2 = 256 * 256;

    WPack wp;
    wp.s[0] = m1W1; wp.n[0] = nM1W1; wp.off[0] = oM1W1;
    wp.s[1] = m1W2; wp.n[1] = nM1W2; wp.off[1] = oM1W2;
    wp.s[2] = m2W1; wp.n[2] = nM2W1; wp.off[2] = oM2W1;
    wp.s[3] = m2W2; wp.n[3] = nM2W2; wp.off[3] = oM2W2;
    wp.s[4] = m3W1; wp.n[4] = nM3W1; wp.off[4] = oM3W1;
    wp.s[5] = m3W2; wp.n[5] = nM3W2; wp.off[5] = oM3W2;
    wp.s[6] = p1W1; wp.n[6] = nP1W1; wp.off[6] = oP1W1;
    wp.s[7] = p1W2; wp.n[7] = nP1W2; wp.off[7] = oP1W2;
    wp.s[8] = p2W1; wp.n[8] = nP2W1; wp.off[8] = oP2W1;
    wp.s[9] = p2W2; wp.n[9] = nP2W2; wp.off[9] = oP2W2;

    round_weights_kernel<<<dim3(192, 10), 1024>>>(wp, bufW);
    round_feat_kernel<<<(N * 128 + 1023) / 1024, 1024>>>(features, bufF, N * 128);

    dim3 gblk(128), lblk(256);
    auto grid = [&](int M, int O) { return dim3((M + TBM - 1) / TBM, O / TBN); };
    int lse_grid = (N + 63) / 64;
    int SB = GEMM_SMEM_BYTES;

    // x = mlp1(features): 128 -> 128 -> 128
    tgemm_kernel<<<grid(N, 128), gblk, SB>>>(bufF, bufW + oM1W1, m1b1, nullptr, bufA, N, 128, 128, 5);
    tgemm_kernel<<<grid(N, 128), gblk, SB>>>(bufA, bufW + oM1W2, m1b2, nullptr, bufB, N, 128, 128, 0);
    // lse1 + channel-softmax pool -> (N,256)  [outputs tf32-rounded]
    lse_mma_kernel<<<lse_grid, lblk>>>(coords, nidx, bufB, l1W1, l1b1, l1W2, l1b2, bufA, N);
    // p1: 256 -> 256 -> 128
    tgemm_kernel<<<grid(N, 256), gblk, SB>>>(bufA, bufW + oP1W1, p1b1, nullptr, bufC, N, 256, 256, 5);
    tgemm_kernel<<<grid(N, 128), gblk, SB>>>(bufC, bufW + oP1W2, p1b2, nullptr, bufB, N, 256, 128, 0);
    // lse2 -> (N,256)
    lse_mma_kernel<<<lse_grid, lblk>>>(coords, nidx, bufB, l2W1, l2b1, l2W2, l2b2, bufA, N);
    // p2: 256 -> 256 -> 256
    tgemm_kernel<<<grid(N, 256), gblk, SB>>>(bufA, bufW + oP2W1, p2b1, nullptr, bufC, N, 256, 256, 5);
    tgemm_kernel<<<grid(N, 256), gblk, SB>>>(bufC, bufW + oP2W2, p2b2, nullptr, bufB, N, 256, 256, 4);
    // m3(features): 128 -> 256 -> 512
    tgemm_kernel<<<grid(N, 256), gblk, SB>>>(bufF, bufW + oM3W1, m3b1, nullptr, bufA, N, 128, 256, 5);
    tgemm_kernel<<<grid(N, 512), gblk, SB>>>(bufA, bufW + oM3W2, m3b2, nullptr, bufC, N, 256, 512, 0);
    // m2(x): 256 -> 384 -> 512, fused residual(+m3) + leaky_relu
    tgemm_kernel<<<grid(N, 384), gblk, SB>>>(bufB, bufW + oM2W1, m2b1, nullptr, bufA, N, 256, 384, 5);
    tgemm_kernel<<<grid(N, 512), gblk, SB>>>(bufA, bufW + oM2W2, m2b2, bufC, out, N, 384, 512, 2);
}

// round 9
// speedup vs baseline: 8.6043x; 1.1250x over previous
#include <cuda_runtime.h>
#include <cuda_fp16.h>
#include <math.h>
#include <stdint.h>

#define NMAX 100000
#define KNBR 16

// Scratch (static __device__ — allocation-guard safe)
__device__ __half g_hA[NMAX * 384];
__device__ __half g_hB[NMAX * 256];
__device__ float  g_bufC[NMAX * 512];   // fp32 res path + half tiles (cast)
__device__ __half g_hF[NMAX * 128];     // half features
__device__ __half g_hW[720896];         // half TRANSPOSED weights [O][K]

__device__ __forceinline__ float to_tf32(float x) {
    float y;
    asm("cvt.rna.tf32.f32 %0, %1;" : "=f"(y) : "f"(x));
    return y;
}

__device__ __forceinline__ uint32_t smem_u32(const void* p) {
    uint32_t a;
    asm("{ .reg .u64 t; cvta.to.shared.u64 t, %1; cvt.u32.u64 %0, t; }"
        : "=r"(a) : "l"(p));
    return a;
}

__device__ __forceinline__ void cp_async16(uint32_t dst, const void* src, int szb) {
    asm volatile("cp.async.cg.shared.global [%0], [%1], 16, %2;"
                 :: "r"(dst), "l"(src), "r"(szb));
}

#define MMA_F16(C, a0, a1, a2, a3, b0, b1)                                    \
    asm volatile(                                                             \
        "mma.sync.aligned.m16n8k16.row.col.f32.f16.f16.f32 "                  \
        "{%0,%1,%2,%3}, {%4,%5,%6,%7}, {%8,%9}, {%0,%1,%2,%3};"               \
        : "+f"((C)[0]), "+f"((C)[1]), "+f"((C)[2]), "+f"((C)[3])              \
        : "r"(a0), "r"(a1), "r"(a2), "r"(a3), "r"(b0), "r"(b1))

#define MMA_TF32(C, a0, a1, a2, a3, b0, b1)                                   \
    asm volatile(                                                             \
        "mma.sync.aligned.m16n8k8.row.col.f32.tf32.tf32.f32 "                 \
        "{%0,%1,%2,%3}, {%4,%5,%6,%7}, {%8,%9}, {%0,%1,%2,%3};"               \
        : "+f"((C)[0]), "+f"((C)[1]), "+f"((C)[2]), "+f"((C)[3])              \
        : "r"(a0), "r"(a1), "r"(a2), "r"(a3), "r"(b0), "r"(b1))

// ---------------------------------------------------------------------------
// Pre-round: weights -> half, transposed to [O][K]; features -> half.
// ---------------------------------------------------------------------------
struct WPackT {
    const float* s[10];
    int Kd[10];
    int Od[10];
    int off[10];
};

__global__ void round_weightsT_kernel(WPackT p, __half* dst) {
    int m = blockIdx.y;
    int i = blockIdx.x * blockDim.x + threadIdx.x;
    int Kd = p.Kd[m], Od = p.Od[m];
    if (i < Kd * Od) {
        int k = i / Od, o = i % Od;          // coalesced source read
        dst[p.off[m] + (size_t)o * Kd + k] = __float2half_rn(p.s[m][i]);
    }
}

__global__ void round_feat_kernel(const float* __restrict__ src,
                                  __half* __restrict__ dst, int n) {
    int i = blockIdx.x * blockDim.x + threadIdx.x;
    if (i < n) dst[i] = __float2half_rn(src[i]);
}

// ---------------------------------------------------------------------------
// fp16 tensor-core GEMM (mma.sync m16n8k16): C = act(A[M,K] @ Wt^T + bias (+res))
// A [M,K] half; Wt [O,K] half. act bits 0-1: 0 none, 1 relu, 2 leaky(x+res fp32).
// Bit 3 (8): output half, else fp32. Block 128x128, 4 warps (2x2), warp 64x64.
// 3-stage cp.async, TBK=32. K % 32 == 0, O % 128 == 0.
// ---------------------------------------------------------------------------
#define ASTH 40                         // halves per smem row (stride)
#define AS_HL (128 * ASTH)              // 5120 halves per operand
#define OP_B  (AS_HL * 2)               // 10240 bytes per operand
#define STG_B (2 * OP_B)                // 20480 bytes per stage (A+B)
#define NSTG 3
#define HGEMM_SMEM (NSTG * STG_B)       // 61440

__device__ __forceinline__ void hgemm_issue(
    const __half* __restrict__ A, const __half* __restrict__ Wt,
    int M, int K, int bm, int bn, int tid, uint32_t sbase, int stage, int kt)
{
    int k0 = kt * 32;
    uint32_t so = sbase + stage * STG_B;
#pragma unroll
    for (int i = 0; i < 4; i++) {
        int id = tid + 128 * i;
        int row = id >> 2, cc = id & 3;
        const __half* src = A + (size_t)(bm + row) * K + k0 + cc * 8;
        cp_async16(so + (row * ASTH + cc * 8) * 2, src, (bm + row) < M ? 16 : 0);
    }
#pragma unroll
    for (int i = 0; i < 4; i++) {
        int id = tid + 128 * i;
        int row = id >> 2, cc = id & 3;
        const __half* src = Wt + (size_t)(bn + row) * K + k0 + cc * 8;
        cp_async16(so + OP_B + (row * ASTH + cc * 8) * 2, src, 16);
    }
    asm volatile("cp.async.commit_group;");
}

__global__ __launch_bounds__(128, 2) void hgemm_kernel(
    const __half* __restrict__ A, const __half* __restrict__ Wt,
    const float* __restrict__ bias, const float* __restrict__ res,
    void* __restrict__ Cout, int M, int K, int O, int act)
{
    extern __shared__ float dsm[];
    uint32_t sb = smem_u32(dsm);

    int tid = threadIdx.x, lane = tid & 31, wid = tid >> 5;
    int bm = blockIdx.x * 128, bn = blockIdx.y * 128;
    int wm = wid & 1, wn = wid >> 1;
    int gid = lane >> 2, tig = lane & 3;
    bool hout = (act & 8) != 0;
    int actv = act & 3;

    float c[4][8][4];
#pragma unroll
    for (int mt = 0; mt < 4; mt++)
#pragma unroll
        for (int nt = 0; nt < 8; nt++)
#pragma unroll
            for (int q = 0; q < 4; q++) c[mt][nt][q] = 0.f;

    int nk = K / 32;
    hgemm_issue(A, Wt, M, K, bm, bn, tid, sb, 0, 0);
    hgemm_issue(A, Wt, M, K, bm, bn, tid, sb, 1, 1);

    for (int kt = 0; kt < nk; kt++) {
        int s = kt % NSTG;
        if (kt + 2 < nk) {
            hgemm_issue(A, Wt, M, K, bm, bn, tid, sb, (kt + 2) % NSTG, kt + 2);
            asm volatile("cp.async.wait_group 2;");
        } else if (kt + 1 < nk) {
            asm volatile("cp.async.wait_group 1;");
        } else {
            asm volatile("cp.async.wait_group 0;");
        }
        __syncthreads();

        const __half* Ast = (const __half*)((const char*)dsm + s * STG_B);
        const __half* Bst = Ast + AS_HL;
#pragma unroll
        for (int ks = 0; ks < 2; ks++) {
            int k0 = ks * 16;
            uint32_t af[4][4];
            int mbase = wm * 64;
#pragma unroll
            for (int mt = 0; mt < 4; mt++) {
                int m = mbase + mt * 16 + gid;
                af[mt][0] = *(const uint32_t*)&Ast[m * ASTH + k0 + 2 * tig];
                af[mt][1] = *(const uint32_t*)&Ast[(m + 8) * ASTH + k0 + 2 * tig];
                af[mt][2] = *(const uint32_t*)&Ast[m * ASTH + k0 + 2 * tig + 8];
                af[mt][3] = *(const uint32_t*)&Ast[(m + 8) * ASTH + k0 + 2 * tig + 8];
            }
            uint32_t bf[8][2];
            int nbase = wn * 64;
#pragma unroll
            for (int nt = 0; nt < 8; nt++) {
                int n = nbase + nt * 8 + gid;
                bf[nt][0] = *(const uint32_t*)&Bst[n * ASTH + k0 + 2 * tig];
                bf[nt][1] = *(const uint32_t*)&Bst[n * ASTH + k0 + 2 * tig + 8];
            }
#pragma unroll
            for (int mt = 0; mt < 4; mt++)
#pragma unroll
                for (int nt = 0; nt < 8; nt++)
                    MMA_F16(c[mt][nt], af[mt][0], af[mt][1], af[mt][2],
                            af[mt][3], bf[nt][0], bf[nt][1]);
        }
        __syncthreads();
    }

#pragma unroll
    for (int mt = 0; mt < 4; mt++) {
        int r0 = bm + wm * 64 + mt * 16 + gid;
        int r1 = r0 + 8;
        bool v0 = r0 < M, v1 = r1 < M;
#pragma unroll
        for (int nt = 0; nt < 8; nt++) {
            int col = bn + wn * 64 + nt * 8 + tig * 2;
            float2 bb = *(const float2*)(bias + col);
            float2 o0 = make_float2(c[mt][nt][0] + bb.x, c[mt][nt][1] + bb.y);
            float2 o1 = make_float2(c[mt][nt][2] + bb.x, c[mt][nt][3] + bb.y);
            if (actv == 1) {
                o0.x = fmaxf(o0.x, 0.f); o0.y = fmaxf(o0.y, 0.f);
                o1.x = fmaxf(o1.x, 0.f); o1.y = fmaxf(o1.y, 0.f);
            } else if (actv == 2) {
                if (v0) {
                    float2 r = *(const float2*)(res + (size_t)r0 * O + col);
                    o0.x += r.x; o0.y += r.y;
                }
                if (v1) {
                    float2 r = *(const float2*)(res + (size_t)r1 * O + col);
                    o1.x += r.x; o1.y += r.y;
                }
                o0.x = (o0.x > 0.f) ? o0.x : 0.01f * o0.x;
                o0.y = (o0.y > 0.f) ? o0.y : 0.01f * o0.y;
                o1.x = (o1.x > 0.f) ? o1.x : 0.01f * o1.x;
                o1.y = (o1.y > 0.f) ? o1.y : 0.01f * o1.y;
            }
            if (hout) {
                __half* Ch = (__half*)Cout;
                if (v0) *(__half2*)(Ch + (size_t)r0 * O + col) =
                            __floats2half2_rn(o0.x, o0.y);
                if (v1) *(__half2*)(Ch + (size_t)r1 * O + col) =
                            __floats2half2_rn(o1.x, o1.y);
            } else {
                float* Cf = (float*)Cout;
                if (v0) *(float2*)(Cf + (size_t)r0 * O + col) = o0;
                if (v1) *(float2*)(Cf + (size_t)r1 * O + col) = o1;
            }
        }
    }
}

// ---------------------------------------------------------------------------
// LSE + attentive pool (tf32 mma core, half feats in / half out).
// ---------------------------------------------------------------------------
#define LSTR 136

__global__ __launch_bounds__(256) void lse_mma_kernel(
    const float* __restrict__ coords, const int* __restrict__ nidx,
    const __half* __restrict__ feats,
    const float* __restrict__ W1, const float* __restrict__ B1,
    const float* __restrict__ W2, const float* __restrict__ B2,
    __half* __restrict__ outF, int N)
{
    __shared__ float sW1[640];
    __shared__ float sB1[64];
    __shared__ float sB2[128];
    __shared__ float sW2[64 * LSTR];

    int tid = threadIdx.x, lane = tid & 31, wid = tid >> 5;
    int gid = lane >> 2, tig = lane & 3;

    for (int i = tid; i < 640; i += 256) sW1[i] = W1[i];
    if (tid < 64) sB1[tid] = B1[tid];
    if (tid < 128) sB2[tid] = B2[tid];
    for (int i = tid; i < 8192; i += 256) {
        int k = i >> 7, ch = i & 127;
        sW2[k * LSTR + ch] = to_tf32(W2[i]);
    }
    __syncthreads();

    int nbase = blockIdx.x * 64 + wid * 8;
    for (int p = 0; p < 8; p++) {
        int n = nbase + p;
        if (n >= N) break;

        int ib0 = nidx[n * KNBR + gid];
        int ib1 = nidx[n * KNBR + gid + 8];
        float ox = coords[n * 3], oy = coords[n * 3 + 1], oz = coords[n * 3 + 2];
        float ax = coords[ib0 * 3], ay = coords[ib0 * 3 + 1], az = coords[ib0 * 3 + 2];
        float bx = coords[ib1 * 3], by = coords[ib1 * 3 + 1], bz = coords[ib1 * 3 + 2];
        float arx = ox - ax, ary = oy - ay, arz = oz - az;
        float brx = ox - bx, bry = oy - by, brz = oz - bz;
        float ad = sqrtf(arx * arx + ary * ary + arz * arz);
        float bd = sqrtf(brx * brx + bry * bry + brz * brz);
        float ca[10] = {ox, oy, oz, ax, ay, az, arx, ary, arz, ad};
        float cb[10] = {ox, oy, oz, bx, by, bz, brx, bry, brz, bd};

        uint32_t hb0[16], hb1[16];
#pragma unroll
        for (int j = 0; j < 16; j++) {
            int ch = tig + 4 * j;
            float h0 = sB1[ch], h1 = h0;
#pragma unroll
            for (int i = 0; i < 10; i++) {
                float w = sW1[i * 64 + ch];
                h0 = fmaf(ca[i], w, h0);
                h1 = fmaf(cb[i], w, h1);
            }
            hb0[j] = __float_as_uint(to_tf32(fmaxf(h0, 0.f)));
            hb1[j] = __float_as_uint(to_tf32(fmaxf(h1, 0.f)));
        }

        float c_[8][2][4];
#pragma unroll
        for (int mt = 0; mt < 8; mt++)
#pragma unroll
            for (int nt = 0; nt < 2; nt++)
#pragma unroll
                for (int q = 0; q < 4; q++) c_[mt][nt][q] = 0.f;

#pragma unroll
        for (int s = 0; s < 8; s++) {
            uint32_t b00 = hb0[2 * s], b01 = hb0[2 * s + 1];
            uint32_t b10 = hb1[2 * s], b11 = hb1[2 * s + 1];
            const float* r0 = &sW2[(8 * s + tig) * LSTR];
            const float* r1 = &sW2[(8 * s + tig + 4) * LSTR];
#pragma unroll
            for (int mt = 0; mt < 8; mt++) {
                int cb0 = 16 * mt + gid;
                uint32_t a0 = __float_as_uint(r0[cb0]);
                uint32_t a1 = __float_as_uint(r0[cb0 + 8]);
                uint32_t a2 = __float_as_uint(r1[cb0]);
                uint32_t a3 = __float_as_uint(r1[cb0 + 8]);
                MMA_TF32(c_[mt][0], a0, a1, a2, a3, b00, b01);
                MMA_TF32(c_[mt][1], a0, a1, a2, a3, b10, b11);
            }
        }

#pragma unroll
        for (int mt = 0; mt < 8; mt++) {
            float bb0 = sB2[16 * mt + gid], bb1 = sB2[16 * mt + gid + 8];
#pragma unroll
            for (int nt = 0; nt < 2; nt++) {
                c_[mt][nt][0] += bb0; c_[mt][nt][1] += bb0;
                c_[mt][nt][2] += bb1; c_[mt][nt][3] += bb1;
            }
        }

        const __half2* fp = (const __half2*)(feats + (size_t)n * 128);
        __half2 p0 = fp[2 * lane], p1 = fp[2 * lane + 1];
        float4 f4 = make_float4(__low2float(p0), __high2float(p0),
                                __low2float(p1), __high2float(p1));
        float ef[4] = {__expf(f4.x), __expf(f4.y), __expf(f4.z), __expf(f4.w)};
        float sf = ef[0] + ef[1] + ef[2] + ef[3];
#pragma unroll
        for (int o = 16; o > 0; o >>= 1)
            sf += __shfl_xor_sync(0xffffffffu, sf, o);

        float ov[8][2];
#pragma unroll
        for (int mt = 0; mt < 8; mt++) { ov[mt][0] = 0.f; ov[mt][1] = 0.f; }
        float Tl = 0.f;

#pragma unroll
        for (int j = 0; j < 4; j++) {
            int nt = j >> 1, q = j & 1;
            float e0[8], e1[8], s = 0.f;
#pragma unroll
            for (int mt = 0; mt < 8; mt++) {
                e0[mt] = __expf(c_[mt][nt][q]);
                e1[mt] = __expf(c_[mt][nt][q + 2]);
                s += e0[mt] + e1[mt];
            }
#pragma unroll
            for (int o = 4; o <= 16; o <<= 1)
                s += __shfl_xor_sync(0xffffffffu, s, o);
            float inv = 1.f / (s + sf);
            Tl += inv;
#pragma unroll
            for (int mt = 0; mt < 8; mt++) {
                ov[mt][0] = fmaf(e0[mt] * inv, c_[mt][nt][q], ov[mt][0]);
                ov[mt][1] = fmaf(e1[mt] * inv, c_[mt][nt][q + 2], ov[mt][1]);
            }
        }
        Tl += __shfl_xor_sync(0xffffffffu, Tl, 1);
        Tl += __shfl_xor_sync(0xffffffffu, Tl, 2);

#pragma unroll
        for (int mt = 0; mt < 8; mt++) {
#pragma unroll
            for (int cs = 0; cs < 2; cs++) {
                ov[mt][cs] += __shfl_xor_sync(0xffffffffu, ov[mt][cs], 1);
                ov[mt][cs] += __shfl_xor_sync(0xffffffffu, ov[mt][cs], 2);
            }
        }

        __half* po = outF + (size_t)n * 256;
#pragma unroll
        for (int t = 0; t < 2; t++) {
            int mt = 2 * tig + t;
            po[16 * mt + gid]     = __float2half_rn(ov[mt][0]);
            po[16 * mt + gid + 8] = __float2half_rn(ov[mt][1]);
        }
        __half2* gp = (__half2*)(po + 128 + 4 * lane);
        gp[0] = __floats2half2_rn(f4.x * ef[0] * Tl, f4.y * ef[1] * Tl);
        gp[1] = __floats2half2_rn(f4.z * ef[2] * Tl, f4.w * ef[3] * Tl);
    }
}

// ---------------------------------------------------------------------------
extern "C" void kernel_launch(void* const* d_in, const int* in_sizes, int n_in,
                              void* d_out, int out_size)
{
    const float* coords   = (const float*)d_in[0];
    const float* features = (const float*)d_in[1];
    const int*   nidx     = (const int*)d_in[2];
    const float* m1W1 = (const float*)d_in[3];  const float* m1b1 = (const float*)d_in[4];
    const float* m1W2 = (const float*)d_in[5];  const float* m1b2 = (const float*)d_in[6];
    const float* m2W1 = (const float*)d_in[7];  const float* m2b1 = (const float*)d_in[8];
    const float* m2W2 = (const float*)d_in[9];  const float* m2b2 = (const float*)d_in[10];
    const float* m3W1 = (const float*)d_in[11]; const float* m3b1 = (const float*)d_in[12];
    const float* m3W2 = (const float*)d_in[13]; const float* m3b2 = (const float*)d_in[14];
    const float* l1W1 = (const float*)d_in[15]; const float* l1b1 = (const float*)d_in[16];
    const float* l1W2 = (const float*)d_in[17]; const float* l1b2 = (const float*)d_in[18];
    const float* l2W1 = (const float*)d_in[19]; const float* l2b1 = (const float*)d_in[20];
    const float* l2W2 = (const float*)d_in[21]; const float* l2b2 = (const float*)d_in[22];
    const float* p1W1 = (const float*)d_in[23]; const float* p1b1 = (const float*)d_in[24];
    const float* p1W2 = (const float*)d_in[25]; const float* p1b2 = (const float*)d_in[26];
    const float* p2W1 = (const float*)d_in[27]; const float* p2b1 = (const float*)d_in[28];
    const float* p2W2 = (const float*)d_in[29]; const float* p2b2 = (const float*)d_in[30];
    float* out = (float*)d_out;

    int N = in_sizes[0] / 3;

    __half *hA, *hB, *hF, *hW;
    float* bufC;
    cudaGetSymbolAddress((void**)&hA, g_hA);
    cudaGetSymbolAddress((void**)&hB, g_hB);
    cudaGetSymbolAddress((void**)&bufC, g_bufC);
    cudaGetSymbolAddress((void**)&hF, g_hF);
    cudaGetSymbolAddress((void**)&hW, g_hW);
    __half* hC = (__half*)bufC;   // half view for intermediate tiles

    cudaFuncSetAttribute(hgemm_kernel,
                         cudaFuncAttributeMaxDynamicSharedMemorySize, HGEMM_SMEM);

    const int oM1W1 = 0;
    const int oM1W2 = 16384;
    const int oM2W1 = 32768;
    const int oM2W2 = 131072;
    const int oM3W1 = 327680;
    const int oM3W2 = 360448;
    const int oP1W1 = 491520;
    const int oP1W2 = 557056;
    const int oP2W1 = 589824;
    const int oP2W2 = 655360;

    WPackT wp;
    wp.s[0] = m1W1; wp.Kd[0] = 128; wp.Od[0] = 128; wp.off[0] = oM1W1;
    wp.s[1] = m1W2; wp.Kd[1] = 128; wp.Od[1] = 128; wp.off[1] = oM1W2;
    wp.s[2] = m2W1; wp.Kd[2] = 256; wp.Od[2] = 384; wp.off[2] = oM2W1;
    wp.s[3] = m2W2; wp.Kd[3] = 384; wp.Od[3] = 512; wp.off[3] = oM2W2;
    wp.s[4] = m3W1; wp.Kd[4] = 128; wp.Od[4] = 256; wp.off[4] = oM3W1;
    wp.s[5] = m3W2; wp.Kd[5] = 256; wp.Od[5] = 512; wp.off[5] = oM3W2;
    wp.s[6] = p1W1; wp.Kd[6] = 256; wp.Od[6] = 256; wp.off[6] = oP1W1;
    wp.s[7] = p1W2; wp.Kd[7] = 256; wp.Od[7] = 128; wp.off[7] = oP1W2;
    wp.s[8] = p2W1; wp.Kd[8] = 256; wp.Od[8] = 256; wp.off[8] = oP2W1;
    wp.s[9] = p2W2; wp.Kd[9] = 256; wp.Od[9] = 256; wp.off[9] = oP2W2;

    round_weightsT_kernel<<<dim3(192, 10), 1024>>>(wp, hW);
    round_feat_kernel<<<(N * 128 + 1023) / 1024, 1024>>>(features, hF, N * 128);

    dim3 gblk(128), lblk(256);
    auto grid = [&](int M, int O) { return dim3((M + 127) / 128, O / 128); };
    int lse_grid = (N + 63) / 64;
    int SB = HGEMM_SMEM;

    // x = mlp1(features): 128 -> 128 -> 128  (half chain)
    hgemm_kernel<<<grid(N, 128), gblk, SB>>>(hF, hW + oM1W1, m1b1, nullptr, hA, N, 128, 128, 9);
    hgemm_kernel<<<grid(N, 128), gblk, SB>>>(hA, hW + oM1W2, m1b2, nullptr, hB, N, 128, 128, 8);
    // lse1 + channel-softmax pool -> (N,256) half
    lse_mma_kernel<<<lse_grid, lblk>>>(coords, nidx, hB, l1W1, l1b1, l1W2, l1b2, hA, N);
    // p1: 256 -> 256 -> 128
    hgemm_kernel<<<grid(N, 256), gblk, SB>>>(hA, hW + oP1W1, p1b1, nullptr, hC, N, 256, 256, 9);
    hgemm_kernel<<<grid(N, 128), gblk, SB>>>(hC, hW + oP1W2, p1b2, nullptr, hB, N, 256, 128, 8);
    // lse2 -> (N,256) half
    lse_mma_kernel<<<lse_grid, lblk>>>(coords, nidx, hB, l2W1, l2b1, l2W2, l2b2, hA, N);
    // p2: 256 -> 256 -> 256
    hgemm_kernel<<<grid(N, 256), gblk, SB>>>(hA, hW + oP2W1, p2b1, nullptr, hC, N, 256, 256, 9);
    hgemm_kernel<<<grid(N, 256), gblk, SB>>>(hC, hW + oP2W2, p2b2, nullptr, hB, N, 256, 256, 8);
    // m3(features): 128 -> 256 -> 512  (layer2 out fp32, used as residual)
    hgemm_kernel<<<grid(N, 256), gblk, SB>>>(hF, hW + oM3W1, m3b1, nullptr, hA, N, 128, 256, 9);
    hgemm_kernel<<<grid(N, 512), gblk, SB>>>(hA, hW + oM3W2, m3b2, nullptr, bufC, N, 256, 512, 0);
    // m2(x): 256 -> 384 -> 512, fused residual(+m3 fp32) + leaky, fp32 out
    hgemm_kernel<<<grid(N, 384), gblk, SB>>>(hB, hW + oM2W1, m2b1, nullptr, hA, N, 256, 384, 9);
    hgemm_kernel<<<grid(N, 512), gblk, SB>>>(hA, hW + oM2W2, m2b2, bufC, out, N, 384, 512, 2);
}

// round 10
// speedup vs baseline: 8.7834x; 1.0208x over previous
#include <cuda_runtime.h>
#include <cuda_fp16.h>
#include <math.h>
#include <stdint.h>

#define NMAX 100000
#define KNBR 16

// Scratch (static __device__ — allocation-guard safe)
__device__ __half g_hA[NMAX * 384];
__device__ __half g_hB[NMAX * 256];
__device__ float  g_bufC[NMAX * 512];   // fp32 res path + half tiles (cast)
__device__ __half g_hF[NMAX * 128];     // half features
__device__ __half g_hW[720896];         // half TRANSPOSED weights [O][K]

__device__ __forceinline__ float to_tf32(float x) {
    float y;
    asm("cvt.rna.tf32.f32 %0, %1;" : "=f"(y) : "f"(x));
    return y;
}

__device__ __forceinline__ uint32_t smem_u32(const void* p) {
    uint32_t a;
    asm("{ .reg .u64 t; cvta.to.shared.u64 t, %1; cvt.u32.u64 %0, t; }"
        : "=r"(a) : "l"(p));
    return a;
}

__device__ __forceinline__ void cp_async16(uint32_t dst, const void* src, int szb) {
    asm volatile("cp.async.cg.shared.global [%0], [%1], 16, %2;"
                 :: "r"(dst), "l"(src), "r"(szb));
}

#define LDSM_X4(r0, r1, r2, r3, addr)                                         \
    asm volatile("ldmatrix.sync.aligned.m8n8.x4.shared.b16 {%0,%1,%2,%3}, [%4];" \
        : "=r"(r0), "=r"(r1), "=r"(r2), "=r"(r3) : "r"(addr))

#define MMA_F16(C, a0, a1, a2, a3, b0, b1)                                    \
    asm volatile(                                                             \
        "mma.sync.aligned.m16n8k16.row.col.f32.f16.f16.f32 "                  \
        "{%0,%1,%2,%3}, {%4,%5,%6,%7}, {%8,%9}, {%0,%1,%2,%3};"               \
        : "+f"((C)[0]), "+f"((C)[1]), "+f"((C)[2]), "+f"((C)[3])              \
        : "r"(a0), "r"(a1), "r"(a2), "r"(a3), "r"(b0), "r"(b1))

#define MMA_TF32(C, a0, a1, a2, a3, b0, b1)                                   \
    asm volatile(                                                             \
        "mma.sync.aligned.m16n8k8.row.col.f32.tf32.tf32.f32 "                 \
        "{%0,%1,%2,%3}, {%4,%5,%6,%7}, {%8,%9}, {%0,%1,%2,%3};"               \
        : "+f"((C)[0]), "+f"((C)[1]), "+f"((C)[2]), "+f"((C)[3])              \
        : "r"(a0), "r"(a1), "r"(a2), "r"(a3), "r"(b0), "r"(b1))

// ---------------------------------------------------------------------------
// Pre-round: weights -> half, transposed to [O][K]; features -> half.
// ---------------------------------------------------------------------------
struct WPackT {
    const float* s[10];
    int Kd[10];
    int Od[10];
    int off[10];
};

__global__ void round_weightsT_kernel(WPackT p, __half* dst) {
    int m = blockIdx.y;
    int i = blockIdx.x * blockDim.x + threadIdx.x;
    int Kd = p.Kd[m], Od = p.Od[m];
    if (i < Kd * Od) {
        int k = i / Od, o = i % Od;          // coalesced source read
        dst[p.off[m] + (size_t)o * Kd + k] = __float2half_rn(p.s[m][i]);
    }
}

__global__ void round_feat_kernel(const float* __restrict__ src,
                                  __half* __restrict__ dst, int n) {
    int i = blockIdx.x * blockDim.x + threadIdx.x;
    if (i < n) dst[i] = __float2half_rn(src[i]);
}

// ---------------------------------------------------------------------------
// fp16 tensor-core GEMM (mma.sync m16n8k16 + ldmatrix):
// C = act(A[M,K] @ Wt^T + bias (+res)); A [M,K] half; Wt [O,K] half.
// act bits 0-1: 0 none, 1 relu, 2 leaky(x+res fp32). Bit 3 (8): half output.
// Block 128x128, 4 warps (2x2), warp 64x64. 3-stage cp.async, TBK=32.
// K % 32 == 0, O % 128 == 0.
// ---------------------------------------------------------------------------
#define ASTH 40                         // halves per smem row (stride)
#define AS_HL (128 * ASTH)              // 5120 halves per operand
#define OP_B  (AS_HL * 2)               // 10240 bytes per operand
#define STG_B (2 * OP_B)                // 20480 bytes per stage (A+B)
#define NSTG 3
#define HGEMM_SMEM (NSTG * STG_B)       // 61440

__device__ __forceinline__ void hgemm_issue(
    const __half* __restrict__ A, const __half* __restrict__ Wt,
    int M, int K, int bm, int bn, int tid, uint32_t sbase, int stage, int kt)
{
    int k0 = kt * 32;
    uint32_t so = sbase + stage * STG_B;
#pragma unroll
    for (int i = 0; i < 4; i++) {
        int id = tid + 128 * i;
        int row = id >> 2, cc = id & 3;
        const __half* src = A + (size_t)(bm + row) * K + k0 + cc * 8;
        cp_async16(so + (row * ASTH + cc * 8) * 2, src, (bm + row) < M ? 16 : 0);
    }
#pragma unroll
    for (int i = 0; i < 4; i++) {
        int id = tid + 128 * i;
        int row = id >> 2, cc = id & 3;
        const __half* src = Wt + (size_t)(bn + row) * K + k0 + cc * 8;
        cp_async16(so + OP_B + (row * ASTH + cc * 8) * 2, src, 16);
    }
    asm volatile("cp.async.commit_group;");
}

__global__ __launch_bounds__(128, 2) void hgemm_kernel(
    const __half* __restrict__ A, const __half* __restrict__ Wt,
    const float* __restrict__ bias, const float* __restrict__ res,
    void* __restrict__ Cout, int M, int K, int O, int act)
{
    extern __shared__ float dsm[];
    uint32_t sb = smem_u32(dsm);

    int tid = threadIdx.x, lane = tid & 31, wid = tid >> 5;
    int bm = blockIdx.x * 128, bn = blockIdx.y * 128;
    int wm = wid & 1, wn = wid >> 1;
    int gid = lane >> 2, tig = lane & 3;
    bool hout = (act & 8) != 0;
    int actv = act & 3;

    // ldmatrix lane address offsets (halves)
    int aRow = wm * 64 + ((lane >> 3) & 1) * 8 + (lane & 7);
    int aCol = (lane >> 4) * 8;
    int bRow = wn * 64 + ((lane >> 4) & 1) * 8 + (lane & 7);
    int bCol = ((lane >> 3) & 1) * 8;
    uint32_t aOff = (uint32_t)(aRow * ASTH + aCol) * 2;
    uint32_t bOff = OP_B + (uint32_t)(bRow * ASTH + bCol) * 2;

    float c[4][8][4];
#pragma unroll
    for (int mt = 0; mt < 4; mt++)
#pragma unroll
        for (int nt = 0; nt < 8; nt++)
#pragma unroll
            for (int q = 0; q < 4; q++) c[mt][nt][q] = 0.f;

    int nk = K / 32;
    hgemm_issue(A, Wt, M, K, bm, bn, tid, sb, 0, 0);
    hgemm_issue(A, Wt, M, K, bm, bn, tid, sb, 1, 1);

    for (int kt = 0; kt < nk; kt++) {
        int s = kt % NSTG;
        if (kt + 2 < nk) {
            hgemm_issue(A, Wt, M, K, bm, bn, tid, sb, (kt + 2) % NSTG, kt + 2);
            asm volatile("cp.async.wait_group 2;");
        } else if (kt + 1 < nk) {
            asm volatile("cp.async.wait_group 1;");
        } else {
            asm volatile("cp.async.wait_group 0;");
        }
        __syncthreads();

        uint32_t sAddr = sb + s * STG_B;
#pragma unroll
        for (int ks = 0; ks < 2; ks++) {
            uint32_t kOff = (uint32_t)(ks * 16) * 2;
            uint32_t af[4][4];
#pragma unroll
            for (int mt = 0; mt < 4; mt++)
                LDSM_X4(af[mt][0], af[mt][1], af[mt][2], af[mt][3],
                        sAddr + aOff + (uint32_t)(mt * 16 * ASTH) * 2 + kOff);
            uint32_t bf[8][2];
#pragma unroll
            for (int nt2 = 0; nt2 < 4; nt2++)
                LDSM_X4(bf[2 * nt2][0], bf[2 * nt2][1],
                        bf[2 * nt2 + 1][0], bf[2 * nt2 + 1][1],
                        sAddr + bOff + (uint32_t)(nt2 * 16 * ASTH) * 2 + kOff);
#pragma unroll
            for (int mt = 0; mt < 4; mt++)
#pragma unroll
                for (int nt = 0; nt < 8; nt++)
                    MMA_F16(c[mt][nt], af[mt][0], af[mt][1], af[mt][2],
                            af[mt][3], bf[nt][0], bf[nt][1]);
        }
        __syncthreads();
    }

#pragma unroll
    for (int mt = 0; mt < 4; mt++) {
        int r0 = bm + wm * 64 + mt * 16 + gid;
        int r1 = r0 + 8;
        bool v0 = r0 < M, v1 = r1 < M;
#pragma unroll
        for (int nt = 0; nt < 8; nt++) {
            int col = bn + wn * 64 + nt * 8 + tig * 2;
            float2 bb = *(const float2*)(bias + col);
            float2 o0 = make_float2(c[mt][nt][0] + bb.x, c[mt][nt][1] + bb.y);
            float2 o1 = make_float2(c[mt][nt][2] + bb.x, c[mt][nt][3] + bb.y);
            if (actv == 1) {
                o0.x = fmaxf(o0.x, 0.f); o0.y = fmaxf(o0.y, 0.f);
                o1.x = fmaxf(o1.x, 0.f); o1.y = fmaxf(o1.y, 0.f);
            } else if (actv == 2) {
                if (v0) {
                    float2 r = *(const float2*)(res + (size_t)r0 * O + col);
                    o0.x += r.x; o0.y += r.y;
                }
                if (v1) {
                    float2 r = *(const float2*)(res + (size_t)r1 * O + col);
                    o1.x += r.x; o1.y += r.y;
                }
                o0.x = (o0.x > 0.f) ? o0.x : 0.01f * o0.x;
                o0.y = (o0.y > 0.f) ? o0.y : 0.01f * o0.y;
                o1.x = (o1.x > 0.f) ? o1.x : 0.01f * o1.x;
                o1.y = (o1.y > 0.f) ? o1.y : 0.01f * o1.y;
            }
            if (hout) {
                __half* Ch = (__half*)Cout;
                if (v0) *(__half2*)(Ch + (size_t)r0 * O + col) =
                            __floats2half2_rn(o0.x, o0.y);
                if (v1) *(__half2*)(Ch + (size_t)r1 * O + col) =
                            __floats2half2_rn(o1.x, o1.y);
            } else {
                float* Cf = (float*)Cout;
                if (v0) *(float2*)(Cf + (size_t)r0 * O + col) = o0;
                if (v1) *(float2*)(Cf + (size_t)r1 * O + col) = o1;
            }
        }
    }
}

// ---------------------------------------------------------------------------
// LSE + attentive pool (tf32 mma core, half feats in / half out). Unchanged.
// ---------------------------------------------------------------------------
#define LSTR 136

__global__ __launch_bounds__(256) void lse_mma_kernel(
    const float* __restrict__ coords, const int* __restrict__ nidx,
    const __half* __restrict__ feats,
    const float* __restrict__ W1, const float* __restrict__ B1,
    const float* __restrict__ W2, const float* __restrict__ B2,
    __half* __restrict__ outF, int N)
{
    __shared__ float sW1[640];
    __shared__ float sB1[64];
    __shared__ float sB2[128];
    __shared__ float sW2[64 * LSTR];

    int tid = threadIdx.x, lane = tid & 31, wid = tid >> 5;
    int gid = lane >> 2, tig = lane & 3;

    for (int i = tid; i < 640; i += 256) sW1[i] = W1[i];
    if (tid < 64) sB1[tid] = B1[tid];
    if (tid < 128) sB2[tid] = B2[tid];
    for (int i = tid; i < 8192; i += 256) {
        int k = i >> 7, ch = i & 127;
        sW2[k * LSTR + ch] = to_tf32(W2[i]);
    }
    __syncthreads();

    int nbase = blockIdx.x * 64 + wid * 8;
    for (int p = 0; p < 8; p++) {
        int n = nbase + p;
        if (n >= N) break;

        int ib0 = nidx[n * KNBR + gid];
        int ib1 = nidx[n * KNBR + gid + 8];
        float ox = coords[n * 3], oy = coords[n * 3 + 1], oz = coords[n * 3 + 2];
        float ax = coords[ib0 * 3], ay = coords[ib0 * 3 + 1], az = coords[ib0 * 3 + 2];
        float bx = coords[ib1 * 3], by = coords[ib1 * 3 + 1], bz = coords[ib1 * 3 + 2];
        float arx = ox - ax, ary = oy - ay, arz = oz - az;
        float brx = ox - bx, bry = oy - by, brz = oz - bz;
        float ad = sqrtf(arx * arx + ary * ary + arz * arz);
        float bd = sqrtf(brx * brx + bry * bry + brz * brz);
        float ca[10] = {ox, oy, oz, ax, ay, az, arx, ary, arz, ad};
        float cb[10] = {ox, oy, oz, bx, by, bz, brx, bry, brz, bd};

        uint32_t hb0[16], hb1[16];
#pragma unroll
        for (int j = 0; j < 16; j++) {
            int ch = tig + 4 * j;
            float h0 = sB1[ch], h1 = h0;
#pragma unroll
            for (int i = 0; i < 10; i++) {
                float w = sW1[i * 64 + ch];
                h0 = fmaf(ca[i], w, h0);
                h1 = fmaf(cb[i], w, h1);
            }
            hb0[j] = __float_as_uint(to_tf32(fmaxf(h0, 0.f)));
            hb1[j] = __float_as_uint(to_tf32(fmaxf(h1, 0.f)));
        }

        float c_[8][2][4];
#pragma unroll
        for (int mt = 0; mt < 8; mt++)
#pragma unroll
            for (int nt = 0; nt < 2; nt++)
#pragma unroll
                for (int q = 0; q < 4; q++) c_[mt][nt][q] = 0.f;

#pragma unroll
        for (int s = 0; s < 8; s++) {
            uint32_t b00 = hb0[2 * s], b01 = hb0[2 * s + 1];
            uint32_t b10 = hb1[2 * s], b11 = hb1[2 * s + 1];
            const float* r0 = &sW2[(8 * s + tig) * LSTR];
            const float* r1 = &sW2[(8 * s + tig + 4) * LSTR];
#pragma unroll
            for (int mt = 0; mt < 8; mt++) {
                int cb0 = 16 * mt + gid;
                uint32_t a0 = __float_as_uint(r0[cb0]);
                uint32_t a1 = __float_as_uint(r0[cb0 + 8]);
                uint32_t a2 = __float_as_uint(r1[cb0]);
                uint32_t a3 = __float_as_uint(r1[cb0 + 8]);
                MMA_TF32(c_[mt][0], a0, a1, a2, a3, b00, b01);
                MMA_TF32(c_[mt][1], a0, a1, a2, a3, b10, b11);
            }
        }

#pragma unroll
        for (int mt = 0; mt < 8; mt++) {
            float bb0 = sB2[16 * mt + gid], bb1 = sB2[16 * mt + gid + 8];
#pragma unroll
            for (int nt = 0; nt < 2; nt++) {
                c_[mt][nt][0] += bb0; c_[mt][nt][1] += bb0;
                c_[mt][nt][2] += bb1; c_[mt][nt][3] += bb1;
            }
        }

        const __half2* fp = (const __half2*)(feats + (size_t)n * 128);
        __half2 p0 = fp[2 * lane], p1 = fp[2 * lane + 1];
        float4 f4 = make_float4(__low2float(p0), __high2float(p0),
                                __low2float(p1), __high2float(p1));
        float ef[4] = {__expf(f4.x), __expf(f4.y), __expf(f4.z), __expf(f4.w)};
        float sf = ef[0] + ef[1] + ef[2] + ef[3];
#pragma unroll
        for (int o = 16; o > 0; o >>= 1)
            sf += __shfl_xor_sync(0xffffffffu, sf, o);

        float ov[8][2];
#pragma unroll
        for (int mt = 0; mt < 8; mt++) { ov[mt][0] = 0.f; ov[mt][1] = 0.f; }
        float Tl = 0.f;

#pragma unroll
        for (int j = 0; j < 4; j++) {
            int nt = j >> 1, q = j & 1;
            float e0[8], e1[8], s = 0.f;
#pragma unroll
            for (int mt = 0; mt < 8; mt++) {
                e0[mt] = __expf(c_[mt][nt][q]);
                e1[mt] = __expf(c_[mt][nt][q + 2]);
                s += e0[mt] + e1[mt];
            }
#pragma unroll
            for (int o = 4; o <= 16; o <<= 1)
                s += __shfl_xor_sync(0xffffffffu, s, o);
            float inv = 1.f / (s + sf);
            Tl += inv;
#pragma unroll
            for (int mt = 0; mt < 8; mt++) {
                ov[mt][0] = fmaf(e0[mt] * inv, c_[mt][nt][q], ov[mt][0]);
                ov[mt][1] = fmaf(e1[mt] * inv, c_[mt][nt][q + 2], ov[mt][1]);
            }
        }
        Tl += __shfl_xor_sync(0xffffffffu, Tl, 1);
        Tl += __shfl_xor_sync(0xffffffffu, Tl, 2);

#pragma unroll
        for (int mt = 0; mt < 8; mt++) {
#pragma unroll
            for (int cs = 0; cs < 2; cs++) {
                ov[mt][cs] += __shfl_xor_sync(0xffffffffu, ov[mt][cs], 1);
                ov[mt][cs] += __shfl_xor_sync(0xffffffffu, ov[mt][cs], 2);
            }
        }

        __half* po = outF + (size_t)n * 256;
#pragma unroll
        for (int t = 0; t < 2; t++) {
            int mt = 2 * tig + t;
            po[16 * mt + gid]     = __float2half_rn(ov[mt][0]);
            po[16 * mt + gid + 8] = __float2half_rn(ov[mt][1]);
        }
        __half2* gp = (__half2*)(po + 128 + 4 * lane);
        gp[0] = __floats2half2_rn(f4.x * ef[0] * Tl, f4.y * ef[1] * Tl);
        gp[1] = __floats2half2_rn(f4.z * ef[2] * Tl, f4.w * ef[3] * Tl);
    }
}

// ---------------------------------------------------------------------------
extern "C" void kernel_launch(void* const* d_in, const int* in_sizes, int n_in,
                              void* d_out, int out_size)
{
    const float* coords   = (const float*)d_in[0];
    const float* features = (const float*)d_in[1];
    const int*   nidx     = (const int*)d_in[2];
    const float* m1W1 = (const float*)d_in[3];  const float* m1b1 = (const float*)d_in[4];
    const float* m1W2 = (const float*)d_in[5];  const float* m1b2 = (const float*)d_in[6];
    const float* m2W1 = (const float*)d_in[7];  const float* m2b1 = (const float*)d_in[8];
    const float* m2W2 = (const float*)d_in[9];  const float* m2b2 = (const float*)d_in[10];
    const float* m3W1 = (const float*)d_in[11]; const float* m3b1 = (const float*)d_in[12];
    const float* m3W2 = (const float*)d_in[13]; const float* m3b2 = (const float*)d_in[14];
    const float* l1W1 = (const float*)d_in[15]; const float* l1b1 = (const float*)d_in[16];
    const float* l1W2 = (const float*)d_in[17]; const float* l1b2 = (const float*)d_in[18];
    const float* l2W1 = (const float*)d_in[19]; const float* l2b1 = (const float*)d_in[20];
    const float* l2W2 = (const float*)d_in[21]; const float* l2b2 = (const float*)d_in[22];
    const float* p1W1 = (const float*)d_in[23]; const float* p1b1 = (const float*)d_in[24];
    const float* p1W2 = (const float*)d_in[25]; const float* p1b2 = (const float*)d_in[26];
    const float* p2W1 = (const float*)d_in[27]; const float* p2b1 = (const float*)d_in[28];
    const float* p2W2 = (const float*)d_in[29]; const float* p2b2 = (const float*)d_in[30];
    float* out = (float*)d_out;

    int N = in_sizes[0] / 3;

    __half *hA, *hB, *hF, *hW;
    float* bufC;
    cudaGetSymbolAddress((void**)&hA, g_hA);
    cudaGetSymbolAddress((void**)&hB, g_hB);
    cudaGetSymbolAddress((void**)&bufC, g_bufC);
    cudaGetSymbolAddress((void**)&hF, g_hF);
    cudaGetSymbolAddress((void**)&hW, g_hW);
    __half* hC = (__half*)bufC;   // half view for intermediate tiles

    cudaFuncSetAttribute(hgemm_kernel,
                         cudaFuncAttributeMaxDynamicSharedMemorySize, HGEMM_SMEM);

    const int oM1W1 = 0;
    const int oM1W2 = 16384;
    const int oM2W1 = 32768;
    const int oM2W2 = 131072;
    const int oM3W1 = 327680;
    const int oM3W2 = 360448;
    const int oP1W1 = 491520;
    const int oP1W2 = 557056;
    const int oP2W1 = 589824;
    const int oP2W2 = 655360;

    WPackT wp;
    wp.s[0] = m1W1; wp.Kd[0] = 128; wp.Od[0] = 128; wp.off[0] = oM1W1;
    wp.s[1] = m1W2; wp.Kd[1] = 128; wp.Od[1] = 128; wp.off[1] = oM1W2;
    wp.s[2] = m2W1; wp.Kd[2] = 256; wp.Od[2] = 384; wp.off[2] = oM2W1;
    wp.s[3] = m2W2; wp.Kd[3] = 384; wp.Od[3] = 512; wp.off[3] = oM2W2;
    wp.s[4] = m3W1; wp.Kd[4] = 128; wp.Od[4] = 256; wp.off[4] = oM3W1;
    wp.s[5] = m3W2; wp.Kd[5] = 256; wp.Od[5] = 512; wp.off[5] = oM3W2;
    wp.s[6] = p1W1; wp.Kd[6] = 256; wp.Od[6] = 256; wp.off[6] = oP1W1;
    wp.s[7] = p1W2; wp.Kd[7] = 256; wp.Od[7] = 128; wp.off[7] = oP1W2;
    wp.s[8] = p2W1; wp.Kd[8] = 256; wp.Od[8] = 256; wp.off[8] = oP2W1;
    wp.s[9] = p2W2; wp.Kd[9] = 256; wp.Od[9] = 256; wp.off[9] = oP2W2;

    round_weightsT_kernel<<<dim3(192, 10), 1024>>>(wp, hW);
    round_feat_kernel<<<(N * 128 + 1023) / 1024, 1024>>>(features, hF, N * 128);

    dim3 gblk(128), lblk(256);
    auto grid = [&](int M, int O) { return dim3((M + 127) / 128, O / 128); };
    int lse_grid = (N + 63) / 64;
    int SB = HGEMM_SMEM;

    // x = mlp1(features): 128 -> 128 -> 128  (half chain)
    hgemm_kernel<<<grid(N, 128), gblk, SB>>>(hF, hW + oM1W1, m1b1, nullptr, hA, N, 128, 128, 9);
    hgemm_kernel<<<grid(N, 128), gblk, SB>>>(hA, hW + oM1W2, m1b2, nullptr, hB, N, 128, 128, 8);
    // lse1 + channel-softmax pool -> (N,256) half
    lse_mma_kernel<<<lse_grid, lblk>>>(coords, nidx, hB, l1W1, l1b1, l1W2, l1b2, hA, N);
    // p1: 256 -> 256 -> 128
    hgemm_kernel<<<grid(N, 256), gblk, SB>>>(hA, hW + oP1W1, p1b1, nullptr, hC, N, 256, 256, 9);
    hgemm_kernel<<<grid(N, 128), gblk, SB>>>(hC, hW + oP1W2, p1b2, nullptr, hB, N, 256, 128, 8);
    // lse2 -> (N,256) half
    lse_mma_kernel<<<lse_grid, lblk>>>(coords, nidx, hB, l2W1, l2b1, l2W2, l2b2, hA, N);
    // p2: 256 -> 256 -> 256
    hgemm_kernel<<<grid(N, 256), gblk, SB>>>(hA, hW + oP2W1, p2b1, nullptr, hC, N, 256, 256, 9);
    hgemm_kernel<<<grid(N, 256), gblk, SB>>>(hC, hW + oP2W2, p2b2, nullptr, hB, N, 256, 256, 8);
    // m3(features): 128 -> 256 -> 512  (layer2 out fp32, used as residual)
    hgemm_kernel<<<grid(N, 256), gblk, SB>>>(hF, hW + oM3W1, m3b1, nullptr, hA, N, 128, 256, 9);
    hgemm_kernel<<<grid(N, 512), gblk, SB>>>(hA, hW + oM3W2, m3b2, nullptr, bufC, N, 256, 512, 0);
    // m2(x): 256 -> 384 -> 512, fused residual(+m3 fp32) + leaky, fp32 out
    hgemm_kernel<<<grid(N, 384), gblk, SB>>>(hB, hW + oM2W1, m2b1, nullptr, hA, N, 256, 384, 9);
    hgemm_kernel<<<grid(N, 512), gblk, SB>>>(hA, hW + oM2W2, m2b2, bufC, out, N, 384, 512, 2);
}

// round 11
// speedup vs baseline: 8.8698x; 1.0098x over previous
#include <cuda_runtime.h>
#include <cuda_fp16.h>
#include <math.h>
#include <stdint.h>

#define NMAX 100000
#define KNBR 16

// Scratch (static __device__ — allocation-guard safe)
__device__ __half g_hA[NMAX * 384];
__device__ __half g_hB[NMAX * 256];
__device__ float  g_bufC[NMAX * 512];   // fp32 res path + half tiles (cast)
__device__ __half g_hF[NMAX * 128];     // half features
__device__ __half g_hW[720896];         // half TRANSPOSED weights [O][K]

__device__ __forceinline__ float to_tf32(float x) {
    float y;
    asm("cvt.rna.tf32.f32 %0, %1;" : "=f"(y) : "f"(x));
    return y;
}

__device__ __forceinline__ uint32_t smem_u32(const void* p) {
    uint32_t a;
    asm("{ .reg .u64 t; cvta.to.shared.u64 t, %1; cvt.u32.u64 %0, t; }"
        : "=r"(a) : "l"(p));
    return a;
}

__device__ __forceinline__ void cp_async16(uint32_t dst, const void* src, int szb) {
    asm volatile("cp.async.cg.shared.global [%0], [%1], 16, %2;"
                 :: "r"(dst), "l"(src), "r"(szb));
}

#define LDSM_X4(r0, r1, r2, r3, addr)                                         \
    asm volatile("ldmatrix.sync.aligned.m8n8.x4.shared.b16 {%0,%1,%2,%3}, [%4];" \
        : "=r"(r0), "=r"(r1), "=r"(r2), "=r"(r3) : "r"(addr))

#define MMA_F16(C, a0, a1, a2, a3, b0, b1)                                    \
    asm volatile(                                                             \
        "mma.sync.aligned.m16n8k16.row.col.f32.f16.f16.f32 "                  \
        "{%0,%1,%2,%3}, {%4,%5,%6,%7}, {%8,%9}, {%0,%1,%2,%3};"               \
        : "+f"((C)[0]), "+f"((C)[1]), "+f"((C)[2]), "+f"((C)[3])              \
        : "r"(a0), "r"(a1), "r"(a2), "r"(a3), "r"(b0), "r"(b1))

#define MMA_TF32(C, a0, a1, a2, a3, b0, b1)                                   \
    asm volatile(                                                             \
        "mma.sync.aligned.m16n8k8.row.col.f32.tf32.tf32.f32 "                 \
        "{%0,%1,%2,%3}, {%4,%5,%6,%7}, {%8,%9}, {%0,%1,%2,%3};"               \
        : "+f"((C)[0]), "+f"((C)[1]), "+f"((C)[2]), "+f"((C)[3])              \
        : "r"(a0), "r"(a1), "r"(a2), "r"(a3), "r"(b0), "r"(b1))

// ---------------------------------------------------------------------------
// Pre-round: weights -> half, transposed to [O][K]; features -> half.
// ---------------------------------------------------------------------------
struct WPackT {
    const float* s[10];
    int Kd[10];
    int Od[10];
    int off[10];
};

__global__ void round_weightsT_kernel(WPackT p, __half* dst) {
    int m = blockIdx.y;
    int i = blockIdx.x * blockDim.x + threadIdx.x;
    int Kd = p.Kd[m], Od = p.Od[m];
    if (i < Kd * Od) {
        int k = i / Od, o = i % Od;          // coalesced source read
        dst[p.off[m] + (size_t)o * Kd + k] = __float2half_rn(p.s[m][i]);
    }
}

__global__ void round_feat_kernel(const float* __restrict__ src,
                                  __half* __restrict__ dst, int n) {
    int i = blockIdx.x * blockDim.x + threadIdx.x;
    if (i < n) dst[i] = __float2half_rn(src[i]);
}

// ---------------------------------------------------------------------------
// fp16 tensor-core GEMM (mma.sync m16n8k16 + ldmatrix):
// C = act(A[M,K] @ Wt^T + bias (+res)); A [M,K] half; Wt [O,K] half.
// act bits 0-1: 0 none, 1 relu, 2 leaky(x+res fp32). Bit 3 (8): half output.
// Block 128x128, 8 warps (2x4), warp tile 64x32. 4-stage cp.async, TBK=32,
// ONE barrier per k-tile. K % 32 == 0, O % 128 == 0.
// ---------------------------------------------------------------------------
#define ASTH 40                         // halves per smem row (stride)
#define AS_HL (128 * ASTH)              // 5120 halves per operand
#define OP_B  (AS_HL * 2)               // 10240 bytes per operand
#define STG_B (2 * OP_B)                // 20480 bytes per stage (A+B)
#define NSTG 4
#define HGEMM_SMEM (NSTG * STG_B)       // 81920

__device__ __forceinline__ void hgemm_issue(
    const __half* __restrict__ A, const __half* __restrict__ Wt,
    int M, int K, int bm, int bn, int tid, uint32_t sbase, int stage, int kt)
{
    int k0 = kt * 32;
    uint32_t so = sbase + stage * STG_B;
#pragma unroll
    for (int i = 0; i < 2; i++) {
        int id = tid + 256 * i;
        int row = id >> 2, cc = id & 3;
        const __half* src = A + (size_t)(bm + row) * K + k0 + cc * 8;
        cp_async16(so + (row * ASTH + cc * 8) * 2, src, (bm + row) < M ? 16 : 0);
    }
#pragma unroll
    for (int i = 0; i < 2; i++) {
        int id = tid + 256 * i;
        int row = id >> 2, cc = id & 3;
        const __half* src = Wt + (size_t)(bn + row) * K + k0 + cc * 8;
        cp_async16(so + OP_B + (row * ASTH + cc * 8) * 2, src, 16);
    }
    asm volatile("cp.async.commit_group;");
}

__global__ __launch_bounds__(256, 2) void hgemm_kernel(
    const __half* __restrict__ A, const __half* __restrict__ Wt,
    const float* __restrict__ bias, const float* __restrict__ res,
    void* __restrict__ Cout, int M, int K, int O, int act)
{
    extern __shared__ float dsm[];
    uint32_t sb = smem_u32(dsm);

    int tid = threadIdx.x, lane = tid & 31, wid = tid >> 5;
    int bm = blockIdx.x * 128, bn = blockIdx.y * 128;
    int wm = wid & 1, wn = wid >> 1;        // warp grid 2 (M) x 4 (N)
    int gid = lane >> 2, tig = lane & 3;
    bool hout = (act & 8) != 0;
    int actv = act & 3;

    // ldmatrix lane address offsets (halves)
    int aRow = wm * 64 + ((lane >> 3) & 1) * 8 + (lane & 7);
    int aCol = (lane >> 4) * 8;
    int bRow = wn * 32 + ((lane >> 4) & 1) * 8 + (lane & 7);
    int bCol = ((lane >> 3) & 1) * 8;
    uint32_t aOff = (uint32_t)(aRow * ASTH + aCol) * 2;
    uint32_t bOff = OP_B + (uint32_t)(bRow * ASTH + bCol) * 2;

    float c[4][4][4];
#pragma unroll
    for (int mt = 0; mt < 4; mt++)
#pragma unroll
        for (int nt = 0; nt < 4; nt++)
#pragma unroll
            for (int q = 0; q < 4; q++) c[mt][nt][q] = 0.f;

    int nk = K / 32;
    hgemm_issue(A, Wt, M, K, bm, bn, tid, sb, 0, 0);
    hgemm_issue(A, Wt, M, K, bm, bn, tid, sb, 1, 1);

    for (int kt = 0; kt < nk; kt++) {
        int s = kt & 3;
        if (kt + 2 < nk) {
            hgemm_issue(A, Wt, M, K, bm, bn, tid, sb, (kt + 2) & 3, kt + 2);
            asm volatile("cp.async.wait_group 2;");
        } else if (kt + 1 < nk) {
            asm volatile("cp.async.wait_group 1;");
        } else {
            asm volatile("cp.async.wait_group 0;");
        }
        __syncthreads();

        uint32_t sAddr = sb + s * STG_B;
#pragma unroll
        for (int ks = 0; ks < 2; ks++) {
            uint32_t kOff = (uint32_t)(ks * 16) * 2;
            uint32_t af[4][4];
#pragma unroll
            for (int mt = 0; mt < 4; mt++)
                LDSM_X4(af[mt][0], af[mt][1], af[mt][2], af[mt][3],
                        sAddr + aOff + (uint32_t)(mt * 16 * ASTH) * 2 + kOff);
            uint32_t bf[4][2];
#pragma unroll
            for (int nt2 = 0; nt2 < 2; nt2++)
                LDSM_X4(bf[2 * nt2][0], bf[2 * nt2][1],
                        bf[2 * nt2 + 1][0], bf[2 * nt2 + 1][1],
                        sAddr + bOff + (uint32_t)(nt2 * 16 * ASTH) * 2 + kOff);
#pragma unroll
            for (int mt = 0; mt < 4; mt++)
#pragma unroll
                for (int nt = 0; nt < 4; nt++)
                    MMA_F16(c[mt][nt], af[mt][0], af[mt][1], af[mt][2],
                            af[mt][3], bf[nt][0], bf[nt][1]);
        }
    }

#pragma unroll
    for (int mt = 0; mt < 4; mt++) {
        int r0 = bm + wm * 64 + mt * 16 + gid;
        int r1 = r0 + 8;
        bool v0 = r0 < M, v1 = r1 < M;
#pragma unroll
        for (int nt = 0; nt < 4; nt++) {
            int col = bn + wn * 32 + nt * 8 + tig * 2;
            float2 bb = *(const float2*)(bias + col);
            float2 o0 = make_float2(c[mt][nt][0] + bb.x, c[mt][nt][1] + bb.y);
            float2 o1 = make_float2(c[mt][nt][2] + bb.x, c[mt][nt][3] + bb.y);
            if (actv == 1) {
                o0.x = fmaxf(o0.x, 0.f); o0.y = fmaxf(o0.y, 0.f);
                o1.x = fmaxf(o1.x, 0.f); o1.y = fmaxf(o1.y, 0.f);
            } else if (actv == 2) {
                if (v0) {
                    float2 r = *(const float2*)(res + (size_t)r0 * O + col);
                    o0.x += r.x; o0.y += r.y;
                }
                if (v1) {
                    float2 r = *(const float2*)(res + (size_t)r1 * O + col);
                    o1.x += r.x; o1.y += r.y;
                }
                o0.x = (o0.x > 0.f) ? o0.x : 0.01f * o0.x;
                o0.y = (o0.y > 0.f) ? o0.y : 0.01f * o0.y;
                o1.x = (o1.x > 0.f) ? o1.x : 0.01f * o1.x;
                o1.y = (o1.y > 0.f) ? o1.y : 0.01f * o1.y;
            }
            if (hout) {
                __half* Ch = (__half*)Cout;
                if (v0) *(__half2*)(Ch + (size_t)r0 * O + col) =
                            __floats2half2_rn(o0.x, o0.y);
                if (v1) *(__half2*)(Ch + (size_t)r1 * O + col) =
                            __floats2half2_rn(o1.x, o1.y);
            } else {
                float* Cf = (float*)Cout;
                if (v0) *(float2*)(Cf + (size_t)r0 * O + col) = o0;
                if (v1) *(float2*)(Cf + (size_t)r1 * O + col) = o1;
            }
        }
    }
}

// ---------------------------------------------------------------------------
// LSE + attentive pool (tf32 mma core, half feats in / half out). Unchanged.
// ---------------------------------------------------------------------------
#define LSTR 136

__global__ __launch_bounds__(256) void lse_mma_kernel(
    const float* __restrict__ coords, const int* __restrict__ nidx,
    const __half* __restrict__ feats,
    const float* __restrict__ W1, const float* __restrict__ B1,
    const float* __restrict__ W2, const float* __restrict__ B2,
    __half* __restrict__ outF, int N)
{
    __shared__ float sW1[640];
    __shared__ float sB1[64];
    __shared__ float sB2[128];
    __shared__ float sW2[64 * LSTR];

    int tid = threadIdx.x, lane = tid & 31, wid = tid >> 5;
    int gid = lane >> 2, tig = lane & 3;

    for (int i = tid; i < 640; i += 256) sW1[i] = W1[i];
    if (tid < 64) sB1[tid] = B1[tid];
    if (tid < 128) sB2[tid] = B2[tid];
    for (int i = tid; i < 8192; i += 256) {
        int k = i >> 7, ch = i & 127;
        sW2[k * LSTR + ch] = to_tf32(W2[i]);
    }
    __syncthreads();

    int nbase = blockIdx.x * 64 + wid * 8;
    for (int p = 0; p < 8; p++) {
        int n = nbase + p;
        if (n >= N) break;

        int ib0 = nidx[n * KNBR + gid];
        int ib1 = nidx[n * KNBR + gid + 8];
        float ox = coords[n * 3], oy = coords[n * 3 + 1], oz = coords[n * 3 + 2];
        float ax = coords[ib0 * 3], ay = coords[ib0 * 3 + 1], az = coords[ib0 * 3 + 2];
        float bx = coords[ib1 * 3], by = coords[ib1 * 3 + 1], bz = coords[ib1 * 3 + 2];
        float arx = ox - ax, ary = oy - ay, arz = oz - az;
        float brx = ox - bx, bry = oy - by, brz = oz - bz;
        float ad = sqrtf(arx * arx + ary * ary + arz * arz);
        float bd = sqrtf(brx * brx + bry * bry + brz * brz);
        float ca[10] = {ox, oy, oz, ax, ay, az, arx, ary, arz, ad};
        float cb[10] = {ox, oy, oz, bx, by, bz, brx, bry, brz, bd};

        uint32_t hb0[16], hb1[16];
#pragma unroll
        for (int j = 0; j < 16; j++) {
            int ch = tig + 4 * j;
            float h0 = sB1[ch], h1 = h0;
#pragma unroll
            for (int i = 0; i < 10; i++) {
                float w = sW1[i * 64 + ch];
                h0 = fmaf(ca[i], w, h0);
                h1 = fmaf(cb[i], w, h1);
            }
            hb0[j] = __float_as_uint(to_tf32(fmaxf(h0, 0.f)));
            hb1[j] = __float_as_uint(to_tf32(fmaxf(h1, 0.f)));
        }

        float c_[8][2][4];
#pragma unroll
        for (int mt = 0; mt < 8; mt++)
#pragma unroll
            for (int nt = 0; nt < 2; nt++)
#pragma unroll
                for (int q = 0; q < 4; q++) c_[mt][nt][q] = 0.f;

#pragma unroll
        for (int s = 0; s < 8; s++) {
            uint32_t b00 = hb0[2 * s], b01 = hb0[2 * s + 1];
            uint32_t b10 = hb1[2 * s], b11 = hb1[2 * s + 1];
            const float* r0 = &sW2[(8 * s + tig) * LSTR];
            const float* r1 = &sW2[(8 * s + tig + 4) * LSTR];
#pragma unroll
            for (int mt = 0; mt < 8; mt++) {
                int cb0 = 16 * mt + gid;
                uint32_t a0 = __float_as_uint(r0[cb0]);
                uint32_t a1 = __float_as_uint(r0[cb0 + 8]);
                uint32_t a2 = __float_as_uint(r1[cb0]);
                uint32_t a3 = __float_as_uint(r1[cb0 + 8]);
                MMA_TF32(c_[mt][0], a0, a1, a2, a3, b00, b01);
                MMA_TF32(c_[mt][1], a0, a1, a2, a3, b10, b11);
            }
        }

#pragma unroll
        for (int mt = 0; mt < 8; mt++) {
            float bb0 = sB2[16 * mt + gid], bb1 = sB2[16 * mt + gid + 8];
#pragma unroll
            for (int nt = 0; nt < 2; nt++) {
                c_[mt][nt][0] += bb0; c_[mt][nt][1] += bb0;
                c_[mt][nt][2] += bb1; c_[mt][nt][3] += bb1;
            }
        }

        const __half2* fp = (const __half2*)(feats + (size_t)n * 128);
        __half2 p0 = fp[2 * lane], p1 = fp[2 * lane + 1];
        float4 f4 = make_float4(__low2float(p0), __high2float(p0),
                                __low2float(p1), __high2float(p1));
        float ef[4] = {__expf(f4.x), __expf(f4.y), __expf(f4.z), __expf(f4.w)};
        float sf = ef[0] + ef[1] + ef[2] + ef[3];
#pragma unroll
        for (int o = 16; o > 0; o >>= 1)
            sf += __shfl_xor_sync(0xffffffffu, sf, o);

        float ov[8][2];
#pragma unroll
        for (int mt = 0; mt < 8; mt++) { ov[mt][0] = 0.f; ov[mt][1] = 0.f; }
        float Tl = 0.f;

#pragma unroll
        for (int j = 0; j < 4; j++) {
            int nt = j >> 1, q = j & 1;
            float e0[8], e1[8], s = 0.f;
#pragma unroll
            for (int mt = 0; mt < 8; mt++) {
                e0[mt] = __expf(c_[mt][nt][q]);
                e1[mt] = __expf(c_[mt][nt][q + 2]);
                s += e0[mt] + e1[mt];
            }
#pragma unroll
            for (int o = 4; o <= 16; o <<= 1)
                s += __shfl_xor_sync(0xffffffffu, s, o);
            float inv = 1.f / (s + sf);
            Tl += inv;
#pragma unroll
            for (int mt = 0; mt < 8; mt++) {
                ov[mt][0] = fmaf(e0[mt] * inv, c_[mt][nt][q], ov[mt][0]);
                ov[mt][1] = fmaf(e1[mt] * inv, c_[mt][nt][q + 2], ov[mt][1]);
            }
        }
        Tl += __shfl_xor_sync(0xffffffffu, Tl, 1);
        Tl += __shfl_xor_sync(0xffffffffu, Tl, 2);

#pragma unroll
        for (int mt = 0; mt < 8; mt++) {
#pragma unroll
            for (int cs = 0; cs < 2; cs++) {
                ov[mt][cs] += __shfl_xor_sync(0xffffffffu, ov[mt][cs], 1);
                ov[mt][cs] += __shfl_xor_sync(0xffffffffu, ov[mt][cs], 2);
            }
        }

        __half* po = outF + (size_t)n * 256;
#pragma unroll
        for (int t = 0; t < 2; t++) {
            int mt = 2 * tig + t;
            po[16 * mt + gid]     = __float2half_rn(ov[mt][0]);
            po[16 * mt + gid + 8] = __float2half_rn(ov[mt][1]);
        }
        __half2* gp = (__half2*)(po + 128 + 4 * lane);
        gp[0] = __floats2half2_rn(f4.x * ef[0] * Tl, f4.y * ef[1] * Tl);
        gp[1] = __floats2half2_rn(f4.z * ef[2] * Tl, f4.w * ef[3] * Tl);
    }
}

// ---------------------------------------------------------------------------
extern "C" void kernel_launch(void* const* d_in, const int* in_sizes, int n_in,
                              void* d_out, int out_size)
{
    const float* coords   = (const float*)d_in[0];
    const float* features = (const float*)d_in[1];
    const int*   nidx     = (const int*)d_in[2];
    const float* m1W1 = (const float*)d_in[3];  const float* m1b1 = (const float*)d_in[4];
    const float* m1W2 = (const float*)d_in[5];  const float* m1b2 = (const float*)d_in[6];
    const float* m2W1 = (const float*)d_in[7];  const float* m2b1 = (const float*)d_in[8];
    const float* m2W2 = (const float*)d_in[9];  const float* m2b2 = (const float*)d_in[10];
    const float* m3W1 = (const float*)d_in[11]; const float* m3b1 = (const float*)d_in[12];
    const float* m3W2 = (const float*)d_in[13]; const float* m3b2 = (const float*)d_in[14];
    const float* l1W1 = (const float*)d_in[15]; const float* l1b1 = (const float*)d_in[16];
    const float* l1W2 = (const float*)d_in[17]; const float* l1b2 = (const float*)d_in[18];
    const float* l2W1 = (const float*)d_in[19]; const float* l2b1 = (const float*)d_in[20];
    const float* l2W2 = (const float*)d_in[21]; const float* l2b2 = (const float*)d_in[22];
    const float* p1W1 = (const float*)d_in[23]; const float* p1b1 = (const float*)d_in[24];
    const float* p1W2 = (const float*)d_in[25]; const float* p1b2 = (const float*)d_in[26];
    const float* p2W1 = (const float*)d_in[27]; const float* p2b1 = (const float*)d_in[28];
    const float* p2W2 = (const float*)d_in[29]; const float* p2b2 = (const float*)d_in[30];
    float* out = (float*)d_out;

    int N = in_sizes[0] / 3;

    __half *hA, *hB, *hF, *hW;
    float* bufC;
    cudaGetSymbolAddress((void**)&hA, g_hA);
    cudaGetSymbolAddress((void**)&hB, g_hB);
    cudaGetSymbolAddress((void**)&bufC, g_bufC);
    cudaGetSymbolAddress((void**)&hF, g_hF);
    cudaGetSymbolAddress((void**)&hW, g_hW);
    __half* hC = (__half*)bufC;   // half view for intermediate tiles

    cudaFuncSetAttribute(hgemm_kernel,
                         cudaFuncAttributeMaxDynamicSharedMemorySize, HGEMM_SMEM);

    const int oM1W1 = 0;
    const int oM1W2 = 16384;
    const int oM2W1 = 32768;
    const int oM2W2 = 131072;
    const int oM3W1 = 327680;
    const int oM3W2 = 360448;
    const int oP1W1 = 491520;
    const int oP1W2 = 557056;
    const int oP2W1 = 589824;
    const int oP2W2 = 655360;

    WPackT wp;
    wp.s[0] = m1W1; wp.Kd[0] = 128; wp.Od[0] = 128; wp.off[0] = oM1W1;
    wp.s[1] = m1W2; wp.Kd[1] = 128; wp.Od[1] = 128; wp.off[1] = oM1W2;
    wp.s[2] = m2W1; wp.Kd[2] = 256; wp.Od[2] = 384; wp.off[2] = oM2W1;
    wp.s[3] = m2W2; wp.Kd[3] = 384; wp.Od[3] = 512; wp.off[3] = oM2W2;
    wp.s[4] = m3W1; wp.Kd[4] = 128; wp.Od[4] = 256; wp.off[4] = oM3W1;
    wp.s[5] = m3W2; wp.Kd[5] = 256; wp.Od[5] = 512; wp.off[5] = oM3W2;
    wp.s[6] = p1W1; wp.Kd[6] = 256; wp.Od[6] = 256; wp.off[6] = oP1W1;
    wp.s[7] = p1W2; wp.Kd[7] = 256; wp.Od[7] = 128; wp.off[7] = oP1W2;
    wp.s[8] = p2W1; wp.Kd[8] = 256; wp.Od[8] = 256; wp.off[8] = oP2W1;
    wp.s[9] = p2W2; wp.Kd[9] = 256; wp.Od[9] = 256; wp.off[9] = oP2W2;

    round_weightsT_kernel<<<dim3(192, 10), 1024>>>(wp, hW);
    round_feat_kernel<<<(N * 128 + 1023) / 1024, 1024>>>(features, hF, N * 128);

    dim3 gblk(256), lblk(256);
    auto grid = [&](int M, int O) { return dim3((M + 127) / 128, O / 128); };
    int lse_grid = (N + 63) / 64;
    int SB = HGEMM_SMEM;

    // x = mlp1(features): 128 -> 128 -> 128  (half chain)
    hgemm_kernel<<<grid(N, 128), gblk, SB>>>(hF, hW + oM1W1, m1b1, nullptr, hA, N, 128, 128, 9);
    hgemm_kernel<<<grid(N, 128), gblk, SB>>>(hA, hW + oM1W2, m1b2, nullptr, hB, N, 128, 128, 8);
    // lse1 + channel-softmax pool -> (N,256) half
    lse_mma_kernel<<<lse_grid, lblk>>>(coords, nidx, hB, l1W1, l1b1, l1W2, l1b2, hA, N);
    // p1: 256 -> 256 -> 128
    hgemm_kernel<<<grid(N, 256), gblk, SB>>>(hA, hW + oP1W1, p1b1, nullptr, hC, N, 256, 256, 9);
    hgemm_kernel<<<grid(N, 128), gblk, SB>>>(hC, hW + oP1W2, p1b2, nullptr, hB, N, 256, 128, 8);
    // lse2 -> (N,256) half
    lse_mma_kernel<<<lse_grid, lblk>>>(coords, nidx, hB, l2W1, l2b1, l2W2, l2b2, hA, N);
    // p2: 256 -> 256 -> 256
    hgemm_kernel<<<grid(N, 256), gblk, SB>>>(hA, hW + oP2W1, p2b1, nullptr, hC, N, 256, 256, 9);
    hgemm_kernel<<<grid(N, 256), gblk, SB>>>(hC, hW + oP2W2, p2b2, nullptr, hB, N, 256, 256, 8);
    // m3(features): 128 -> 256 -> 512  (layer2 out fp32, used as residual)
    hgemm_kernel<<<grid(N, 256), gblk, SB>>>(hF, hW + oM3W1, m3b1, nullptr, hA, N, 128, 256, 9);
    hgemm_kernel<<<grid(N, 512), gblk, SB>>>(hA, hW + oM3W2, m3b2, nullptr, bufC, N, 256, 512, 0);
    // m2(x): 256 -> 384 -> 512, fused residual(+m3 fp32) + leaky, fp32 out
    hgemm_kernel<<<grid(N, 384), gblk, SB>>>(hB, hW + oM2W1, m2b1, nullptr, hA, N, 256, 384, 9);
    hgemm_kernel<<<grid(N, 512), gblk, SB>>>(hA, hW + oM2W2, m2b2, bufC, out, N, 384, 512, 2);
}

// round 12
// speedup vs baseline: 9.0129x; 1.0161x over previous
#include <cuda_runtime.h>
#include <cuda_fp16.h>
#include <math.h>
#include <stdint.h>

#define NMAX 100000
#define KNBR 16

// Scratch (static __device__ — allocation-guard safe)
__device__ __half g_hA[NMAX * 384];
__device__ __half g_hB[NMAX * 256];
__device__ float  g_bufC[NMAX * 512];   // fp32 / half view for main-chain tiles
__device__ __half g_hF[NMAX * 128];     // half features
__device__ __half g_hW[720896];         // half TRANSPOSED weights [O][K]
__device__ __half g_hD[NMAX * 256];     // m3 hidden (side stream)
__device__ float  g_bufD[NMAX * 512];   // m3 output fp32 (side stream)

__device__ __forceinline__ float to_tf32(float x) {
    float y;
    asm("cvt.rna.tf32.f32 %0, %1;" : "=f"(y) : "f"(x));
    return y;
}

__device__ __forceinline__ uint32_t smem_u32(const void* p) {
    uint32_t a;
    asm("{ .reg .u64 t; cvta.to.shared.u64 t, %1; cvt.u32.u64 %0, t; }"
        : "=r"(a) : "l"(p));
    return a;
}

__device__ __forceinline__ void cp_async16(uint32_t dst, const void* src, int szb) {
    asm volatile("cp.async.cg.shared.global [%0], [%1], 16, %2;"
                 :: "r"(dst), "l"(src), "r"(szb));
}

#define LDSM_X4(r0, r1, r2, r3, addr)                                         \
    asm volatile("ldmatrix.sync.aligned.m8n8.x4.shared.b16 {%0,%1,%2,%3}, [%4];" \
        : "=r"(r0), "=r"(r1), "=r"(r2), "=r"(r3) : "r"(addr))

#define MMA_F16(C, a0, a1, a2, a3, b0, b1)                                    \
    asm volatile(                                                             \
        "mma.sync.aligned.m16n8k16.row.col.f32.f16.f16.f32 "                  \
        "{%0,%1,%2,%3}, {%4,%5,%6,%7}, {%8,%9}, {%0,%1,%2,%3};"               \
        : "+f"((C)[0]), "+f"((C)[1]), "+f"((C)[2]), "+f"((C)[3])              \
        : "r"(a0), "r"(a1), "r"(a2), "r"(a3), "r"(b0), "r"(b1))

#define MMA_TF32(C, a0, a1, a2, a3, b0, b1)                                   \
    asm volatile(                                                             \
        "mma.sync.aligned.m16n8k8.row.col.f32.tf32.tf32.f32 "                 \
        "{%0,%1,%2,%3}, {%4,%5,%6,%7}, {%8,%9}, {%0,%1,%2,%3};"               \
        : "+f"((C)[0]), "+f"((C)[1]), "+f"((C)[2]), "+f"((C)[3])              \
        : "r"(a0), "r"(a1), "r"(a2), "r"(a3), "r"(b0), "r"(b1))

// ---------------------------------------------------------------------------
// Pre-round: weights -> half, transposed to [O][K]; features -> half.
// ---------------------------------------------------------------------------
struct WPackT {
    const float* s[10];
    int Kd[10];
    int Od[10];
    int off[10];
};

__global__ void round_weightsT_kernel(WPackT p, __half* dst) {
    int m = blockIdx.y;
    int i = blockIdx.x * blockDim.x + threadIdx.x;
    int Kd = p.Kd[m], Od = p.Od[m];
    if (i < Kd * Od) {
        int k = i / Od, o = i % Od;          // coalesced source read
        dst[p.off[m] + (size_t)o * Kd + k] = __float2half_rn(p.s[m][i]);
    }
}

__global__ void round_feat_kernel(const float* __restrict__ src,
                                  __half* __restrict__ dst, int n) {
    int i = blockIdx.x * blockDim.x + threadIdx.x;
    if (i < n) dst[i] = __float2half_rn(src[i]);
}

// ---------------------------------------------------------------------------
// fp16 tensor-core GEMM (mma.sync m16n8k16 + ldmatrix). Unchanged from R11.
// act bits 0-1: 0 none, 1 relu, 2 leaky(x+res fp32). Bit 3 (8): half output.
// Block 128x128, 8 warps (2x4), warp tile 64x32. 4-stage cp.async, TBK=32.
// ---------------------------------------------------------------------------
#define ASTH 40
#define AS_HL (128 * ASTH)
#define OP_B  (AS_HL * 2)
#define STG_B (2 * OP_B)
#define NSTG 4
#define HGEMM_SMEM (NSTG * STG_B)       // 81920

__device__ __forceinline__ void hgemm_issue(
    const __half* __restrict__ A, const __half* __restrict__ Wt,
    int M, int K, int bm, int bn, int tid, uint32_t sbase, int stage, int kt)
{
    int k0 = kt * 32;
    uint32_t so = sbase + stage * STG_B;
#pragma unroll
    for (int i = 0; i < 2; i++) {
        int id = tid + 256 * i;
        int row = id >> 2, cc = id & 3;
        const __half* src = A + (size_t)(bm + row) * K + k0 + cc * 8;
        cp_async16(so + (row * ASTH + cc * 8) * 2, src, (bm + row) < M ? 16 : 0);
    }
#pragma unroll
    for (int i = 0; i < 2; i++) {
        int id = tid + 256 * i;
        int row = id >> 2, cc = id & 3;
        const __half* src = Wt + (size_t)(bn + row) * K + k0 + cc * 8;
        cp_async16(so + OP_B + (row * ASTH + cc * 8) * 2, src, 16);
    }
    asm volatile("cp.async.commit_group;");
}

__global__ __launch_bounds__(256, 2) void hgemm_kernel(
    const __half* __restrict__ A, const __half* __restrict__ Wt,
    const float* __restrict__ bias, const float* __restrict__ res,
    void* __restrict__ Cout, int M, int K, int O, int act)
{
    extern __shared__ float dsm[];
    uint32_t sb = smem_u32(dsm);

    int tid = threadIdx.x, lane = tid & 31, wid = tid >> 5;
    int bm = blockIdx.x * 128, bn = blockIdx.y * 128;
    int wm = wid & 1, wn = wid >> 1;        // warp grid 2 (M) x 4 (N)
    int gid = lane >> 2, tig = lane & 3;
    bool hout = (act & 8) != 0;
    int actv = act & 3;

    int aRow = wm * 64 + ((lane >> 3) & 1) * 8 + (lane & 7);
    int aCol = (lane >> 4) * 8;
    int bRow = wn * 32 + ((lane >> 4) & 1) * 8 + (lane & 7);
    int bCol = ((lane >> 3) & 1) * 8;
    uint32_t aOff = (uint32_t)(aRow * ASTH + aCol) * 2;
    uint32_t bOff = OP_B + (uint32_t)(bRow * ASTH + bCol) * 2;

    float c[4][4][4];
#pragma unroll
    for (int mt = 0; mt < 4; mt++)
#pragma unroll
        for (int nt = 0; nt < 4; nt++)
#pragma unroll
            for (int q = 0; q < 4; q++) c[mt][nt][q] = 0.f;

    int nk = K / 32;
    hgemm_issue(A, Wt, M, K, bm, bn, tid, sb, 0, 0);
    hgemm_issue(A, Wt, M, K, bm, bn, tid, sb, 1, 1);

    for (int kt = 0; kt < nk; kt++) {
        int s = kt & 3;
        if (kt + 2 < nk) {
            hgemm_issue(A, Wt, M, K, bm, bn, tid, sb, (kt + 2) & 3, kt + 2);
            asm volatile("cp.async.wait_group 2;");
        } else if (kt + 1 < nk) {
            asm volatile("cp.async.wait_group 1;");
        } else {
            asm volatile("cp.async.wait_group 0;");
        }
        __syncthreads();

        uint32_t sAddr = sb + s * STG_B;
#pragma unroll
        for (int ks = 0; ks < 2; ks++) {
            uint32_t kOff = (uint32_t)(ks * 16) * 2;
            uint32_t af[4][4];
#pragma unroll
            for (int mt = 0; mt < 4; mt++)
                LDSM_X4(af[mt][0], af[mt][1], af[mt][2], af[mt][3],
                        sAddr + aOff + (uint32_t)(mt * 16 * ASTH) * 2 + kOff);
            uint32_t bf[4][2];
#pragma unroll
            for (int nt2 = 0; nt2 < 2; nt2++)
                LDSM_X4(bf[2 * nt2][0], bf[2 * nt2][1],
                        bf[2 * nt2 + 1][0], bf[2 * nt2 + 1][1],
                        sAddr + bOff + (uint32_t)(nt2 * 16 * ASTH) * 2 + kOff);
#pragma unroll
            for (int mt = 0; mt < 4; mt++)
#pragma unroll
                for (int nt = 0; nt < 4; nt++)
                    MMA_F16(c[mt][nt], af[mt][0], af[mt][1], af[mt][2],
                            af[mt][3], bf[nt][0], bf[nt][1]);
        }
    }

#pragma unroll
    for (int mt = 0; mt < 4; mt++) {
        int r0 = bm + wm * 64 + mt * 16 + gid;
        int r1 = r0 + 8;
        bool v0 = r0 < M, v1 = r1 < M;
#pragma unroll
        for (int nt = 0; nt < 4; nt++) {
            int col = bn + wn * 32 + nt * 8 + tig * 2;
            float2 bb = *(const float2*)(bias + col);
            float2 o0 = make_float2(c[mt][nt][0] + bb.x, c[mt][nt][1] + bb.y);
            float2 o1 = make_float2(c[mt][nt][2] + bb.x, c[mt][nt][3] + bb.y);
            if (actv == 1) {
                o0.x = fmaxf(o0.x, 0.f); o0.y = fmaxf(o0.y, 0.f);
                o1.x = fmaxf(o1.x, 0.f); o1.y = fmaxf(o1.y, 0.f);
            } else if (actv == 2) {
                if (v0) {
                    float2 r = *(const float2*)(res + (size_t)r0 * O + col);
                    o0.x += r.x; o0.y += r.y;
                }
                if (v1) {
                    float2 r = *(const float2*)(res + (size_t)r1 * O + col);
                    o1.x += r.x; o1.y += r.y;
                }
                o0.x = (o0.x > 0.f) ? o0.x : 0.01f * o0.x;
                o0.y = (o0.y > 0.f) ? o0.y : 0.01f * o0.y;
                o1.x = (o1.x > 0.f) ? o1.x : 0.01f * o1.x;
                o1.y = (o1.y > 0.f) ? o1.y : 0.01f * o1.y;
            }
            if (hout) {
                __half* Ch = (__half*)Cout;
                if (v0) *(__half2*)(Ch + (size_t)r0 * O + col) =
                            __floats2half2_rn(o0.x, o0.y);
                if (v1) *(__half2*)(Ch + (size_t)r1 * O + col) =
                            __floats2half2_rn(o1.x, o1.y);
            } else {
                float* Cf = (float*)Cout;
                if (v0) *(float2*)(Cf + (size_t)r0 * O + col) = o0;
                if (v1) *(float2*)(Cf + (size_t)r1 * O + col) = o1;
            }
        }
    }
}

// ---------------------------------------------------------------------------
// LSE + attentive pool (tf32 mma core, half feats in / half out). Unchanged.
// ---------------------------------------------------------------------------
#define LSTR 136

__global__ __launch_bounds__(256) void lse_mma_kernel(
    const float* __restrict__ coords, const int* __restrict__ nidx,
    const __half* __restrict__ feats,
    const float* __restrict__ W1, const float* __restrict__ B1,
    const float* __restrict__ W2, const float* __restrict__ B2,
    __half* __restrict__ outF, int N)
{
    __shared__ float sW1[640];
    __shared__ float sB1[64];
    __shared__ float sB2[128];
    __shared__ float sW2[64 * LSTR];

    int tid = threadIdx.x, lane = tid & 31, wid = tid >> 5;
    int gid = lane >> 2, tig = lane & 3;

    for (int i = tid; i < 640; i += 256) sW1[i] = W1[i];
    if (tid < 64) sB1[tid] = B1[tid];
    if (tid < 128) sB2[tid] = B2[tid];
    for (int i = tid; i < 8192; i += 256) {
        int k = i >> 7, ch = i & 127;
        sW2[k * LSTR + ch] = to_tf32(W2[i]);
    }
    __syncthreads();

    int nbase = blockIdx.x * 64 + wid * 8;
    for (int p = 0; p < 8; p++) {
        int n = nbase + p;
        if (n >= N) break;

        int ib0 = nidx[n * KNBR + gid];
        int ib1 = nidx[n * KNBR + gid + 8];
        float ox = coords[n * 3], oy = coords[n * 3 + 1], oz = coords[n * 3 + 2];
        float ax = coords[ib0 * 3], ay = coords[ib0 * 3 + 1], az = coords[ib0 * 3 + 2];
        float bx = coords[ib1 * 3], by = coords[ib1 * 3 + 1], bz = coords[ib1 * 3 + 2];
        float arx = ox - ax, ary = oy - ay, arz = oz - az;
        float brx = ox - bx, bry = oy - by, brz = oz - bz;
        float ad = sqrtf(arx * arx + ary * ary + arz * arz);
        float bd = sqrtf(brx * brx + bry * bry + brz * brz);
        float ca[10] = {ox, oy, oz, ax, ay, az, arx, ary, arz, ad};
        float cb[10] = {ox, oy, oz, bx, by, bz, brx, bry, brz, bd};

        uint32_t hb0[16], hb1[16];
#pragma unroll
        for (int j = 0; j < 16; j++) {
            int ch = tig + 4 * j;
            float h0 = sB1[ch], h1 = h0;
#pragma unroll
            for (int i = 0; i < 10; i++) {
                float w = sW1[i * 64 + ch];
                h0 = fmaf(ca[i], w, h0);
                h1 = fmaf(cb[i], w, h1);
            }
            hb0[j] = __float_as_uint(to_tf32(fmaxf(h0, 0.f)));
            hb1[j] = __float_as_uint(to_tf32(fmaxf(h1, 0.f)));
        }

        float c_[8][2][4];
#pragma unroll
        for (int mt = 0; mt < 8; mt++)
#pragma unroll
            for (int nt = 0; nt < 2; nt++)
#pragma unroll
                for (int q = 0; q < 4; q++) c_[mt][nt][q] = 0.f;

#pragma unroll
        for (int s = 0; s < 8; s++) {
            uint32_t b00 = hb0[2 * s], b01 = hb0[2 * s + 1];
            uint32_t b10 = hb1[2 * s], b11 = hb1[2 * s + 1];
            const float* r0 = &sW2[(8 * s + tig) * LSTR];
            const float* r1 = &sW2[(8 * s + tig + 4) * LSTR];
#pragma unroll
            for (int mt = 0; mt < 8; mt++) {
                int cb0 = 16 * mt + gid;
                uint32_t a0 = __float_as_uint(r0[cb0]);
                uint32_t a1 = __float_as_uint(r0[cb0 + 8]);
                uint32_t a2 = __float_as_uint(r1[cb0]);
                uint32_t a3 = __float_as_uint(r1[cb0 + 8]);
                MMA_TF32(c_[mt][0], a0, a1, a2, a3, b00, b01);
                MMA_TF32(c_[mt][1], a0, a1, a2, a3, b10, b11);
            }
        }

#pragma unroll
        for (int mt = 0; mt < 8; mt++) {
            float bb0 = sB2[16 * mt + gid], bb1 = sB2[16 * mt + gid + 8];
#pragma unroll
            for (int nt = 0; nt < 2; nt++) {
                c_[mt][nt][0] += bb0; c_[mt][nt][1] += bb0;
                c_[mt][nt][2] += bb1; c_[mt][nt][3] += bb1;
            }
        }

        const __half2* fp = (const __half2*)(feats + (size_t)n * 128);
        __half2 p0 = fp[2 * lane], p1 = fp[2 * lane + 1];
        float4 f4 = make_float4(__low2float(p0), __high2float(p0),
                                __low2float(p1), __high2float(p1));
        float ef[4] = {__expf(f4.x), __expf(f4.y), __expf(f4.z), __expf(f4.w)};
        float sf = ef[0] + ef[1] + ef[2] + ef[3];
#pragma unroll
        for (int o = 16; o > 0; o >>= 1)
            sf += __shfl_xor_sync(0xffffffffu, sf, o);

        float ov[8][2];
#pragma unroll
        for (int mt = 0; mt < 8; mt++) { ov[mt][0] = 0.f; ov[mt][1] = 0.f; }
        float Tl = 0.f;

#pragma unroll
        for (int j = 0; j < 4; j++) {
            int nt = j >> 1, q = j & 1;
            float e0[8], e1[8], s = 0.f;
#pragma unroll
            for (int mt = 0; mt < 8; mt++) {
                e0[mt] = __expf(c_[mt][nt][q]);
                e1[mt] = __expf(c_[mt][nt][q + 2]);
                s += e0[mt] + e1[mt];
            }
#pragma unroll
            for (int o = 4; o <= 16; o <<= 1)
                s += __shfl_xor_sync(0xffffffffu, s, o);
            float inv = 1.f / (s + sf);
            Tl += inv;
#pragma unroll
            for (int mt = 0; mt < 8; mt++) {
                ov[mt][0] = fmaf(e0[mt] * inv, c_[mt][nt][q], ov[mt][0]);
                ov[mt][1] = fmaf(e1[mt] * inv, c_[mt][nt][q + 2], ov[mt][1]);
            }
        }
        Tl += __shfl_xor_sync(0xffffffffu, Tl, 1);
        Tl += __shfl_xor_sync(0xffffffffu, Tl, 2);

#pragma unroll
        for (int mt = 0; mt < 8; mt++) {
#pragma unroll
            for (int cs = 0; cs < 2; cs++) {
                ov[mt][cs] += __shfl_xor_sync(0xffffffffu, ov[mt][cs], 1);
                ov[mt][cs] += __shfl_xor_sync(0xffffffffu, ov[mt][cs], 2);
            }
        }

        __half* po = outF + (size_t)n * 256;
#pragma unroll
        for (int t = 0; t < 2; t++) {
            int mt = 2 * tig + t;
            po[16 * mt + gid]     = __float2half_rn(ov[mt][0]);
            po[16 * mt + gid + 8] = __float2half_rn(ov[mt][1]);
        }
        __half2* gp = (__half2*)(po + 128 + 4 * lane);
        gp[0] = __floats2half2_rn(f4.x * ef[0] * Tl, f4.y * ef[1] * Tl);
        gp[1] = __floats2half2_rn(f4.z * ef[2] * Tl, f4.w * ef[3] * Tl);
    }
}

// ---------------------------------------------------------------------------
extern "C" void kernel_launch(void* const* d_in, const int* in_sizes, int n_in,
                              void* d_out, int out_size)
{
    const float* coords   = (const float*)d_in[0];
    const float* features = (const float*)d_in[1];
    const int*   nidx     = (const int*)d_in[2];
    const float* m1W1 = (const float*)d_in[3];  const float* m1b1 = (const float*)d_in[4];
    const float* m1W2 = (const float*)d_in[5];  const float* m1b2 = (const float*)d_in[6];
    const float* m2W1 = (const float*)d_in[7];  const float* m2b1 = (const float*)d_in[8];
    const float* m2W2 = (const float*)d_in[9];  const float* m2b2 = (const float*)d_in[10];
    const float* m3W1 = (const float*)d_in[11]; const float* m3b1 = (const float*)d_in[12];
    const float* m3W2 = (const float*)d_in[13]; const float* m3b2 = (const float*)d_in[14];
    const float* l1W1 = (const float*)d_in[15]; const float* l1b1 = (const float*)d_in[16];
    const float* l1W2 = (const float*)d_in[17]; const float* l1b2 = (const float*)d_in[18];
    const float* l2W1 = (const float*)d_in[19]; const float* l2b1 = (const float*)d_in[20];
    const float* l2W2 = (const float*)d_in[21]; const float* l2b2 = (const float*)d_in[22];
    const float* p1W1 = (const float*)d_in[23]; const float* p1b1 = (const float*)d_in[24];
    const float* p1W2 = (const float*)d_in[25]; const float* p1b2 = (const float*)d_in[26];
    const float* p2W1 = (const float*)d_in[27]; const float* p2b1 = (const float*)d_in[28];
    const float* p2W2 = (const float*)d_in[29]; const float* p2b2 = (const float*)d_in[30];
    float* out = (float*)d_out;

    int N = in_sizes[0] / 3;

    __half *hA, *hB, *hF, *hW, *hD;
    float *bufC, *bufD;
    cudaGetSymbolAddress((void**)&hA, g_hA);
    cudaGetSymbolAddress((void**)&hB, g_hB);
    cudaGetSymbolAddress((void**)&bufC, g_bufC);
    cudaGetSymbolAddress((void**)&hF, g_hF);
    cudaGetSymbolAddress((void**)&hW, g_hW);
    cudaGetSymbolAddress((void**)&hD, g_hD);
    cudaGetSymbolAddress((void**)&bufD, g_bufD);
    __half* hC = (__half*)bufC;   // half view for main-chain intermediates

    // One-time setup (first call is the uncaptured correctness run)
    static cudaStream_t s2 = nullptr;
    static cudaEvent_t ev0 = nullptr, evW = nullptr, evF = nullptr, evM3 = nullptr;
    if (!s2) {
        cudaFuncSetAttribute(hgemm_kernel,
                             cudaFuncAttributeMaxDynamicSharedMemorySize,
                             HGEMM_SMEM);
        cudaStreamCreateWithFlags(&s2, cudaStreamNonBlocking);
        cudaEventCreateWithFlags(&ev0, cudaEventDisableTiming);
        cudaEventCreateWithFlags(&evW, cudaEventDisableTiming);
        cudaEventCreateWithFlags(&evF, cudaEventDisableTiming);
        cudaEventCreateWithFlags(&evM3, cudaEventDisableTiming);
    }

    const int oM1W1 = 0;
    const int oM1W2 = 16384;
    const int oM2W1 = 32768;
    const int oM2W2 = 131072;
    const int oM3W1 = 327680;
    const int oM3W2 = 360448;
    const int oP1W1 = 491520;
    const int oP1W2 = 557056;
    const int oP2W1 = 589824;
    const int oP2W2 = 655360;

    WPackT wp;
    wp.s[0] = m1W1; wp.Kd[0] = 128; wp.Od[0] = 128; wp.off[0] = oM1W1;
    wp.s[1] = m1W2; wp.Kd[1] = 128; wp.Od[1] = 128; wp.off[1] = oM1W2;
    wp.s[2] = m2W1; wp.Kd[2] = 256; wp.Od[2] = 384; wp.off[2] = oM2W1;
    wp.s[3] = m2W2; wp.Kd[3] = 384; wp.Od[3] = 512; wp.off[3] = oM2W2;
    wp.s[4] = m3W1; wp.Kd[4] = 128; wp.Od[4] = 256; wp.off[4] = oM3W1;
    wp.s[5] = m3W2; wp.Kd[5] = 256; wp.Od[5] = 512; wp.off[5] = oM3W2;
    wp.s[6] = p1W1; wp.Kd[6] = 256; wp.Od[6] = 256; wp.off[6] = oP1W1;
    wp.s[7] = p1W2; wp.Kd[7] = 256; wp.Od[7] = 128; wp.off[7] = oP1W2;
    wp.s[8] = p2W1; wp.Kd[8] = 256; wp.Od[8] = 256; wp.off[8] = oP2W1;
    wp.s[9] = p2W2; wp.Kd[9] = 256; wp.Od[9] = 256; wp.off[9] = oP2W2;

    dim3 gblk(256), lblk(256);
    auto grid = [&](int M, int O) { return dim3((M + 127) / 128, O / 128); };
    int lse_grid = (N + 63) / 64;
    int SB = HGEMM_SMEM;

    // ---- fork: weights round on s2, features round on legacy ----
    cudaEventRecord(ev0, 0);
    cudaStreamWaitEvent(s2, ev0, 0);
    round_weightsT_kernel<<<dim3(192, 10), 1024, 0, s2>>>(wp, hW);
    cudaEventRecord(evW, s2);

    round_feat_kernel<<<(N * 128 + 1023) / 1024, 1024>>>(features, hF, N * 128);
    cudaEventRecord(evF, 0);

    // ---- side stream: m3 chain (features -> 256 -> 512 fp32) ----
    cudaStreamWaitEvent(s2, evF, 0);
    hgemm_kernel<<<grid(N, 256), gblk, SB, s2>>>(hF, hW + oM3W1, m3b1, nullptr, hD, N, 128, 256, 9);
    hgemm_kernel<<<grid(N, 512), gblk, SB, s2>>>(hD, hW + oM3W2, m3b2, nullptr, bufD, N, 256, 512, 0);
    cudaEventRecord(evM3, s2);

    // ---- main chain (legacy stream), waits for weights ----
    cudaStreamWaitEvent(0, evW, 0);
    // m1: 128 -> 128 -> 128
    hgemm_kernel<<<grid(N, 128), gblk, SB>>>(hF, hW + oM1W1, m1b1, nullptr, hA, N, 128, 128, 9);
    hgemm_kernel<<<grid(N, 128), gblk, SB>>>(hA, hW + oM1W2, m1b2, nullptr, hB, N, 128, 128, 8);
    // lse1 -> (N,256) half
    lse_mma_kernel<<<lse_grid, lblk>>>(coords, nidx, hB, l1W1, l1b1, l1W2, l1b2, hA, N);
    // p1: 256 -> 256 -> 128
    hgemm_kernel<<<grid(N, 256), gblk, SB>>>(hA, hW + oP1W1, p1b1, nullptr, hC, N, 256, 256, 9);
    hgemm_kernel<<<grid(N, 128), gblk, SB>>>(hC, hW + oP1W2, p1b2, nullptr, hB, N, 256, 128, 8);
    // lse2 -> (N,256) half
    lse_mma_kernel<<<lse_grid, lblk>>>(coords, nidx, hB, l2W1, l2b1, l2W2, l2b2, hA, N);
    // p2: 256 -> 256 -> 256
    hgemm_kernel<<<grid(N, 256), gblk, SB>>>(hA, hW + oP2W1, p2b1, nullptr, hC, N, 256, 256, 9);
    hgemm_kernel<<<grid(N, 256), gblk, SB>>>(hC, hW + oP2W2, p2b2, nullptr, hB, N, 256, 256, 8);
    // m2: 256 -> 384, then join m3 residual for final 384 -> 512
    hgemm_kernel<<<grid(N, 384), gblk, SB>>>(hB, hW + oM2W1, m2b1, nullptr, hA, N, 256, 384, 9);
    cudaStreamWaitEvent(0, evM3, 0);
    hgemm_kernel<<<grid(N, 512), gblk, SB>>>(hA, hW + oM2W2, m2b2, bufD, out, N, 384, 512, 2);
}

// round 13
// speedup vs baseline: 9.2643x; 1.0279x over previous
#include <cuda_runtime.h>
#include <cuda_fp16.h>
#include <math.h>
#include <stdint.h>

#define NMAX 100000
#define KNBR 16

// Scratch (static __device__ — allocation-guard safe)
__device__ __half g_hA[NMAX * 384];
__device__ __half g_hB[NMAX * 256];
__device__ float  g_bufC[NMAX * 512];   // fp32 / half view for main-chain tiles
__device__ __half g_hF[NMAX * 128];     // half features
__device__ __half g_hW[720896];         // half transposed weights (incl. [512][640] concat)
__device__ __half g_hD[NMAX * 256];     // m3 hidden (side stream)

__device__ __forceinline__ float to_tf32(float x) {
    float y;
    asm("cvt.rna.tf32.f32 %0, %1;" : "=f"(y) : "f"(x));
    return y;
}

__device__ __forceinline__ uint32_t smem_u32(const void* p) {
    uint32_t a;
    asm("{ .reg .u64 t; cvta.to.shared.u64 t, %1; cvt.u32.u64 %0, t; }"
        : "=r"(a) : "l"(p));
    return a;
}

__device__ __forceinline__ void cp_async16(uint32_t dst, const void* src, int szb) {
    asm volatile("cp.async.cg.shared.global [%0], [%1], 16, %2;"
                 :: "r"(dst), "l"(src), "r"(szb));
}

#define LDSM_X4(r0, r1, r2, r3, addr)                                         \
    asm volatile("ldmatrix.sync.aligned.m8n8.x4.shared.b16 {%0,%1,%2,%3}, [%4];" \
        : "=r"(r0), "=r"(r1), "=r"(r2), "=r"(r3) : "r"(addr))

#define MMA_F16(C, a0, a1, a2, a3, b0, b1)                                    \
    asm volatile(                                                             \
        "mma.sync.aligned.m16n8k16.row.col.f32.f16.f16.f32 "                  \
        "{%0,%1,%2,%3}, {%4,%5,%6,%7}, {%8,%9}, {%0,%1,%2,%3};"               \
        : "+f"((C)[0]), "+f"((C)[1]), "+f"((C)[2]), "+f"((C)[3])              \
        : "r"(a0), "r"(a1), "r"(a2), "r"(a3), "r"(b0), "r"(b1))

#define MMA_TF32(C, a0, a1, a2, a3, b0, b1)                                   \
    asm volatile(                                                             \
        "mma.sync.aligned.m16n8k8.row.col.f32.tf32.tf32.f32 "                 \
        "{%0,%1,%2,%3}, {%4,%5,%6,%7}, {%8,%9}, {%0,%1,%2,%3};"               \
        : "+f"((C)[0]), "+f"((C)[1]), "+f"((C)[2]), "+f"((C)[3])              \
        : "r"(a0), "r"(a1), "r"(a2), "r"(a3), "r"(b0), "r"(b1))

// ---------------------------------------------------------------------------
// Pre-round: weights -> half, transposed to [O][ld] with column offset
// (lets m2W2 / m3W2 land concatenated in one [512][640] region).
// ---------------------------------------------------------------------------
struct WPackT {
    const float* s[10];
    int Kd[10];
    int Od[10];
    int ld[10];
    int coff[10];
    int off[10];
};

__global__ void round_weightsT_kernel(WPackT p, __half* dst) {
    int m = blockIdx.y;
    int i = blockIdx.x * blockDim.x + threadIdx.x;
    int Kd = p.Kd[m], Od = p.Od[m];
    if (i < Kd * Od) {
        int k = i / Od, o = i % Od;          // coalesced source read
        dst[p.off[m] + (size_t)o * p.ld[m] + p.coff[m] + k] =
            __float2half_rn(p.s[m][i]);
    }
}

__global__ void round_feat_kernel(const float* __restrict__ src,
                                  __half* __restrict__ dst, int n) {
    int i = blockIdx.x * blockDim.x + threadIdx.x;
    if (i < n) dst[i] = __float2half_rn(src[i]);
}

// ---------------------------------------------------------------------------
// fp16 tensor-core GEMM (mma.sync m16n8k16 + ldmatrix), dual-A capable:
// C = act([A|A2][M, K+K2] @ Wt^T + bias (+bias2) (+res));  Wt row stride K+K2.
// act bits 0-1: 0 none, 1 relu, 2 leaky(+res if res!=null). Bit 3 (8): half out.
// Block 128x128, 8 warps (2x4), warp 64x32. 4-stage cp.async, TBK=32.
// ---------------------------------------------------------------------------
#define ASTH 40
#define AS_HL (128 * ASTH)
#define OP_B  (AS_HL * 2)
#define STG_B (2 * OP_B)
#define NSTG 4
#define HGEMM_SMEM (NSTG * STG_B)       // 81920

__device__ __forceinline__ void hgemm_issue2(
    const __half* __restrict__ Abase, int strideA, int kloc,
    const __half* __restrict__ Wt, int KW, int kw,
    int M, int bm, int bn, int tid, uint32_t sbase, int stage)
{
    uint32_t so = sbase + stage * STG_B;
#pragma unroll
    for (int i = 0; i < 2; i++) {
        int id = tid + 256 * i;
        int row = id >> 2, cc = id & 3;
        const __half* src = Abase + (size_t)(bm + row) * strideA + kloc + cc * 8;
        cp_async16(so + (row * ASTH + cc * 8) * 2, src, (bm + row) < M ? 16 : 0);
    }
#pragma unroll
    for (int i = 0; i < 2; i++) {
        int id = tid + 256 * i;
        int row = id >> 2, cc = id & 3;
        const __half* src = Wt + (size_t)(bn + row) * KW + kw + cc * 8;
        cp_async16(so + OP_B + (row * ASTH + cc * 8) * 2, src, 16);
    }
    asm volatile("cp.async.commit_group;");
}

__global__ __launch_bounds__(256, 2) void hgemm_kernel(
    const __half* __restrict__ A, const __half* __restrict__ A2,
    const __half* __restrict__ Wt,
    const float* __restrict__ bias, const float* __restrict__ bias2,
    const float* __restrict__ res,
    void* __restrict__ Cout, int M, int K, int K2, int O, int act)
{
    extern __shared__ float dsm[];
    uint32_t sb = smem_u32(dsm);

    int tid = threadIdx.x, lane = tid & 31, wid = tid >> 5;
    int bm = blockIdx.x * 128, bn = blockIdx.y * 128;
    int wm = wid & 1, wn = wid >> 1;        // warp grid 2 (M) x 4 (N)
    int gid = lane >> 2, tig = lane & 3;
    bool hout = (act & 8) != 0;
    int actv = act & 3;
    int KW = K + K2;
    int nk1 = K / 32, nk = KW / 32;

    int aRow = wm * 64 + ((lane >> 3) & 1) * 8 + (lane & 7);
    int aCol = (lane >> 4) * 8;
    int bRow = wn * 32 + ((lane >> 4) & 1) * 8 + (lane & 7);
    int bCol = ((lane >> 3) & 1) * 8;
    uint32_t aOff = (uint32_t)(aRow * ASTH + aCol) * 2;
    uint32_t bOff = OP_B + (uint32_t)(bRow * ASTH + bCol) * 2;

    float c[4][4][4];
#pragma unroll
    for (int mt = 0; mt < 4; mt++)
#pragma unroll
        for (int nt = 0; nt < 4; nt++)
#pragma unroll
            for (int q = 0; q < 4; q++) c[mt][nt][q] = 0.f;

    auto issue = [&](int kt, int stage) {
        const __half* Ab; int strA, kloc;
        if (kt < nk1) { Ab = A;  strA = K;  kloc = kt * 32; }
        else          { Ab = A2; strA = K2; kloc = (kt - nk1) * 32; }
        hgemm_issue2(Ab, strA, kloc, Wt, KW, kt * 32, M, bm, bn, tid, sb, stage);
    };

    issue(0, 0);
    issue(1, 1);

    for (int kt = 0; kt < nk; kt++) {
        int s = kt & 3;
        if (kt + 2 < nk) {
            issue(kt + 2, (kt + 2) & 3);
            asm volatile("cp.async.wait_group 2;");
        } else if (kt + 1 < nk) {
            asm volatile("cp.async.wait_group 1;");
        } else {
            asm volatile("cp.async.wait_group 0;");
        }
        __syncthreads();

        uint32_t sAddr = sb + s * STG_B;
#pragma unroll
        for (int ks = 0; ks < 2; ks++) {
            uint32_t kOff = (uint32_t)(ks * 16) * 2;
            uint32_t af[4][4];
#pragma unroll
            for (int mt = 0; mt < 4; mt++)
                LDSM_X4(af[mt][0], af[mt][1], af[mt][2], af[mt][3],
                        sAddr + aOff + (uint32_t)(mt * 16 * ASTH) * 2 + kOff);
            uint32_t bf[4][2];
#pragma unroll
            for (int nt2 = 0; nt2 < 2; nt2++)
                LDSM_X4(bf[2 * nt2][0], bf[2 * nt2][1],
                        bf[2 * nt2 + 1][0], bf[2 * nt2 + 1][1],
                        sAddr + bOff + (uint32_t)(nt2 * 16 * ASTH) * 2 + kOff);
#pragma unroll
            for (int mt = 0; mt < 4; mt++)
#pragma unroll
                for (int nt = 0; nt < 4; nt++)
                    MMA_F16(c[mt][nt], af[mt][0], af[mt][1], af[mt][2],
                            af[mt][3], bf[nt][0], bf[nt][1]);
        }
    }

#pragma unroll
    for (int mt = 0; mt < 4; mt++) {
        int r0 = bm + wm * 64 + mt * 16 + gid;
        int r1 = r0 + 8;
        bool v0 = r0 < M, v1 = r1 < M;
#pragma unroll
        for (int nt = 0; nt < 4; nt++) {
            int col = bn + wn * 32 + nt * 8 + tig * 2;
            float2 bb = *(const float2*)(bias + col);
            if (bias2) {
                float2 b2 = *(const float2*)(bias2 + col);
                bb.x += b2.x; bb.y += b2.y;
            }
            float2 o0 = make_float2(c[mt][nt][0] + bb.x, c[mt][nt][1] + bb.y);
            float2 o1 = make_float2(c[mt][nt][2] + bb.x, c[mt][nt][3] + bb.y);
            if (actv == 1) {
                o0.x = fmaxf(o0.x, 0.f); o0.y = fmaxf(o0.y, 0.f);
                o1.x = fmaxf(o1.x, 0.f); o1.y = fmaxf(o1.y, 0.f);
            } else if (actv == 2) {
                if (res) {
                    if (v0) {
                        float2 r = *(const float2*)(res + (size_t)r0 * O + col);
                        o0.x += r.x; o0.y += r.y;
                    }
                    if (v1) {
                        float2 r = *(const float2*)(res + (size_t)r1 * O + col);
                        o1.x += r.x; o1.y += r.y;
                    }
                }
                o0.x = (o0.x > 0.f) ? o0.x : 0.01f * o0.x;
                o0.y = (o0.y > 0.f) ? o0.y : 0.01f * o0.y;
                o1.x = (o1.x > 0.f) ? o1.x : 0.01f * o1.x;
                o1.y = (o1.y > 0.f) ? o1.y : 0.01f * o1.y;
            }
            if (hout) {
                __half* Ch = (__half*)Cout;
                if (v0) *(__half2*)(Ch + (size_t)r0 * O + col) =
                            __floats2half2_rn(o0.x, o0.y);
                if (v1) *(__half2*)(Ch + (size_t)r1 * O + col) =
                            __floats2half2_rn(o1.x, o1.y);
            } else {
                float* Cf = (float*)Cout;
                if (v0) *(float2*)(Cf + (size_t)r0 * O + col) = o0;
                if (v1) *(float2*)(Cf + (size_t)r1 * O + col) = o1;
            }
        }
    }
}

// ---------------------------------------------------------------------------
// LSE + attentive pool (tf32 mma core, half feats in / half out). Unchanged.
// ---------------------------------------------------------------------------
#define LSTR 136

__global__ __launch_bounds__(256) void lse_mma_kernel(
    const float* __restrict__ coords, const int* __restrict__ nidx,
    const __half* __restrict__ feats,
    const float* __restrict__ W1, const float* __restrict__ B1,
    const float* __restrict__ W2, const float* __restrict__ B2,
    __half* __restrict__ outF, int N)
{
    __shared__ float sW1[640];
    __shared__ float sB1[64];
    __shared__ float sB2[128];
    __shared__ float sW2[64 * LSTR];

    int tid = threadIdx.x, lane = tid & 31, wid = tid >> 5;
    int gid = lane >> 2, tig = lane & 3;

    for (int i = tid; i < 640; i += 256) sW1[i] = W1[i];
    if (tid < 64) sB1[tid] = B1[tid];
    if (tid < 128) sB2[tid] = B2[tid];
    for (int i = tid; i < 8192; i += 256) {
        int k = i >> 7, ch = i & 127;
        sW2[k * LSTR + ch] = to_tf32(W2[i]);
    }
    __syncthreads();

    int nbase = blockIdx.x * 64 + wid * 8;
    for (int p = 0; p < 8; p++) {
        int n = nbase + p;
        if (n >= N) break;

        int ib0 = nidx[n * KNBR + gid];
        int ib1 = nidx[n * KNBR + gid + 8];
        float ox = coords[n * 3], oy = coords[n * 3 + 1], oz = coords[n * 3 + 2];
        float ax = coords[ib0 * 3], ay = coords[ib0 * 3 + 1], az = coords[ib0 * 3 + 2];
        float bx = coords[ib1 * 3], by = coords[ib1 * 3 + 1], bz = coords[ib1 * 3 + 2];
        float arx = ox - ax, ary = oy - ay, arz = oz - az;
        float brx = ox - bx, bry = oy - by, brz = oz - bz;
        float ad = sqrtf(arx * arx + ary * ary + arz * arz);
        float bd = sqrtf(brx * brx + bry * bry + brz * brz);
        float ca[10] = {ox, oy, oz, ax, ay, az, arx, ary, arz, ad};
        float cb[10] = {ox, oy, oz, bx, by, bz, brx, bry, brz, bd};

        uint32_t hb0[16], hb1[16];
#pragma unroll
        for (int j = 0; j < 16; j++) {
            int ch = tig + 4 * j;
            float h0 = sB1[ch], h1 = h0;
#pragma unroll
            for (int i = 0; i < 10; i++) {
                float w = sW1[i * 64 + ch];
                h0 = fmaf(ca[i], w, h0);
                h1 = fmaf(cb[i], w, h1);
            }
            hb0[j] = __float_as_uint(to_tf32(fmaxf(h0, 0.f)));
            hb1[j] = __float_as_uint(to_tf32(fmaxf(h1, 0.f)));
        }

        float c_[8][2][4];
#pragma unroll
        for (int mt = 0; mt < 8; mt++)
#pragma unroll
            for (int nt = 0; nt < 2; nt++)
#pragma unroll
                for (int q = 0; q < 4; q++) c_[mt][nt][q] = 0.f;

#pragma unroll
        for (int s = 0; s < 8; s++) {
            uint32_t b00 = hb0[2 * s], b01 = hb0[2 * s + 1];
            uint32_t b10 = hb1[2 * s], b11 = hb1[2 * s + 1];
            const float* r0 = &sW2[(8 * s + tig) * LSTR];
            const float* r1 = &sW2[(8 * s + tig + 4) * LSTR];
#pragma unroll
            for (int mt = 0; mt < 8; mt++) {
                int cb0 = 16 * mt + gid;
                uint32_t a0 = __float_as_uint(r0[cb0]);
                uint32_t a1 = __float_as_uint(r0[cb0 + 8]);
                uint32_t a2 = __float_as_uint(r1[cb0]);
                uint32_t a3 = __float_as_uint(r1[cb0 + 8]);
                MMA_TF32(c_[mt][0], a0, a1, a2, a3, b00, b01);
                MMA_TF32(c_[mt][1], a0, a1, a2, a3, b10, b11);
            }
        }

#pragma unroll
        for (int mt = 0; mt < 8; mt++) {
            float bb0 = sB2[16 * mt + gid], bb1 = sB2[16 * mt + gid + 8];
#pragma unroll
            for (int nt = 0; nt < 2; nt++) {
                c_[mt][nt][0] += bb0; c_[mt][nt][1] += bb0;
                c_[mt][nt][2] += bb1; c_[mt][nt][3] += bb1;
            }
        }

        const __half2* fp = (const __half2*)(feats + (size_t)n * 128);
        __half2 p0 = fp[2 * lane], p1 = fp[2 * lane + 1];
        float4 f4 = make_float4(__low2float(p0), __high2float(p0),
                                __low2float(p1), __high2float(p1));
        float ef[4] = {__expf(f4.x), __expf(f4.y), __expf(f4.z), __expf(f4.w)};
        float sf = ef[0] + ef[1] + ef[2] + ef[3];
#pragma unroll
        for (int o = 16; o > 0; o >>= 1)
            sf += __shfl_xor_sync(0xffffffffu, sf, o);

        float ov[8][2];
#pragma unroll
        for (int mt = 0; mt < 8; mt++) { ov[mt][0] = 0.f; ov[mt][1] = 0.f; }
        float Tl = 0.f;

#pragma unroll
        for (int j = 0; j < 4; j++) {
            int nt = j >> 1, q = j & 1;
            float e0[8], e1[8], s = 0.f;
#pragma unroll
            for (int mt = 0; mt < 8; mt++) {
                e0[mt] = __expf(c_[mt][nt][q]);
                e1[mt] = __expf(c_[mt][nt][q + 2]);
                s += e0[mt] + e1[mt];
            }
#pragma unroll
            for (int o = 4; o <= 16; o <<= 1)
                s += __shfl_xor_sync(0xffffffffu, s, o);
            float inv = 1.f / (s + sf);
            Tl += inv;
#pragma unroll
            for (int mt = 0; mt < 8; mt++) {
                ov[mt][0] = fmaf(e0[mt] * inv, c_[mt][nt][q], ov[mt][0]);
                ov[mt][1] = fmaf(e1[mt] * inv, c_[mt][nt][q + 2], ov[mt][1]);
            }
        }
        Tl += __shfl_xor_sync(0xffffffffu, Tl, 1);
        Tl += __shfl_xor_sync(0xffffffffu, Tl, 2);

#pragma unroll
        for (int mt = 0; mt < 8; mt++) {
#pragma unroll
            for (int cs = 0; cs < 2; cs++) {
                ov[mt][cs] += __shfl_xor_sync(0xffffffffu, ov[mt][cs], 1);
                ov[mt][cs] += __shfl_xor_sync(0xffffffffu, ov[mt][cs], 2);
            }
        }

        __half* po = outF + (size_t)n * 256;
#pragma unroll
        for (int t = 0; t < 2; t++) {
            int mt = 2 * tig + t;
            po[16 * mt + gid]     = __float2half_rn(ov[mt][0]);
            po[16 * mt + gid + 8] = __float2half_rn(ov[mt][1]);
        }
        __half2* gp = (__half2*)(po + 128 + 4 * lane);
        gp[0] = __floats2half2_rn(f4.x * ef[0] * Tl, f4.y * ef[1] * Tl);
        gp[1] = __floats2half2_rn(f4.z * ef[2] * Tl, f4.w * ef[3] * Tl);
    }
}

// ---------------------------------------------------------------------------
extern "C" void kernel_launch(void* const* d_in, const int* in_sizes, int n_in,
                              void* d_out, int out_size)
{
    const float* coords   = (const float*)d_in[0];
    const float* features = (const float*)d_in[1];
    const int*   nidx     = (const int*)d_in[2];
    const float* m1W1 = (const float*)d_in[3];  const float* m1b1 = (const float*)d_in[4];
    const float* m1W2 = (const float*)d_in[5];  const float* m1b2 = (const float*)d_in[6];
    const float* m2W1 = (const float*)d_in[7];  const float* m2b1 = (const float*)d_in[8];
    const float* m2W2 = (const float*)d_in[9];  const float* m2b2 = (const float*)d_in[10];
    const float* m3W1 = (const float*)d_in[11]; const float* m3b1 = (const float*)d_in[12];
    const float* m3W2 = (const float*)d_in[13]; const float* m3b2 = (const float*)d_in[14];
    const float* l1W1 = (const float*)d_in[15]; const float* l1b1 = (const float*)d_in[16];
    const float* l1W2 = (const float*)d_in[17]; const float* l1b2 = (const float*)d_in[18];
    const float* l2W1 = (const float*)d_in[19]; const float* l2b1 = (const float*)d_in[20];
    const float* l2W2 = (const float*)d_in[21]; const float* l2b2 = (const float*)d_in[22];
    const float* p1W1 = (const float*)d_in[23]; const float* p1b1 = (const float*)d_in[24];
    const float* p1W2 = (const float*)d_in[25]; const float* p1b2 = (const float*)d_in[26];
    const float* p2W1 = (const float*)d_in[27]; const float* p2b1 = (const float*)d_in[28];
    const float* p2W2 = (const float*)d_in[29]; const float* p2b2 = (const float*)d_in[30];
    float* out = (float*)d_out;

    int N = in_sizes[0] / 3;

    __half *hA, *hB, *hF, *hW, *hD;
    float* bufC;
    cudaGetSymbolAddress((void**)&hA, g_hA);
    cudaGetSymbolAddress((void**)&hB, g_hB);
    cudaGetSymbolAddress((void**)&bufC, g_bufC);
    cudaGetSymbolAddress((void**)&hF, g_hF);
    cudaGetSymbolAddress((void**)&hW, g_hW);
    cudaGetSymbolAddress((void**)&hD, g_hD);
    __half* hC = (__half*)bufC;   // half view for main-chain intermediates

    static cudaStream_t s2 = nullptr;
    static cudaEvent_t ev0 = nullptr, evW = nullptr, evF = nullptr, evM3 = nullptr;
    if (!s2) {
        cudaFuncSetAttribute(hgemm_kernel,
                             cudaFuncAttributeMaxDynamicSharedMemorySize,
                             HGEMM_SMEM);
        cudaStreamCreateWithFlags(&s2, cudaStreamNonBlocking);
        cudaEventCreateWithFlags(&ev0, cudaEventDisableTiming);
        cudaEventCreateWithFlags(&evW, cudaEventDisableTiming);
        cudaEventCreateWithFlags(&evF, cudaEventDisableTiming);
        cudaEventCreateWithFlags(&evM3, cudaEventDisableTiming);
    }

    // Weight layout in g_hW (halves):
    const int oM1W1 = 0;        // 128x128
    const int oM1W2 = 16384;    // 128x128
    const int oM2W1 = 32768;    // 384x256
    const int oM3W1 = 131072;   // 256x128
    const int oP1W1 = 163840;   // 256x256
    const int oP1W2 = 229376;   // 128x256
    const int oP2W1 = 262144;   // 256x256
    const int oP2W2 = 327680;   // 256x256
    const int oWCAT = 393216;   // 512x640  ([m2W2 | m3W2] per output row)

    WPackT wp;
    auto setw = [&](int i, const float* s, int Kd, int Od, int ld, int coff, int off) {
        wp.s[i] = s; wp.Kd[i] = Kd; wp.Od[i] = Od;
        wp.ld[i] = ld; wp.coff[i] = coff; wp.off[i] = off;
    };
    setw(0, m1W1, 128, 128, 128, 0, oM1W1);
    setw(1, m1W2, 128, 128, 128, 0, oM1W2);
    setw(2, m2W1, 256, 384, 256, 0, oM2W1);
    setw(3, m2W2, 384, 512, 640, 0, oWCAT);
    setw(4, m3W1, 128, 256, 128, 0, oM3W1);
    setw(5, m3W2, 256, 512, 640, 384, oWCAT);
    setw(6, p1W1, 256, 256, 256, 0, oP1W1);
    setw(7, p1W2, 256, 128, 256, 0, oP1W2);
    setw(8, p2W1, 256, 256, 256, 0, oP2W1);
    setw(9, p2W2, 256, 256, 256, 0, oP2W2);

    dim3 gblk(256), lblk(256);
    auto grid = [&](int M, int O) { return dim3((M + 127) / 128, O / 128); };
    int lse_grid = (N + 63) / 64;
    int SB = HGEMM_SMEM;

    // ---- fork: weights round on s2, features round on legacy ----
    cudaEventRecord(ev0, 0);
    cudaStreamWaitEvent(s2, ev0, 0);
    round_weightsT_kernel<<<dim3(192, 10), 1024, 0, s2>>>(wp, hW);
    cudaEventRecord(evW, s2);

    round_feat_kernel<<<(N * 128 + 1023) / 1024, 1024>>>(features, hF, N * 128);
    cudaEventRecord(evF, 0);

    // ---- side stream: m3 hidden only (features -> 256 half) ----
    cudaStreamWaitEvent(s2, evF, 0);
    hgemm_kernel<<<grid(N, 256), gblk, SB, s2>>>(
        hF, nullptr, hW + oM3W1, m3b1, nullptr, nullptr, hD, N, 128, 0, 256, 9);
    cudaEventRecord(evM3, s2);

    // ---- main chain (legacy stream), waits for weights ----
    cudaStreamWaitEvent(0, evW, 0);
    // m1: 128 -> 128 -> 128
    hgemm_kernel<<<grid(N, 128), gblk, SB>>>(
        hF, nullptr, hW + oM1W1, m1b1, nullptr, nullptr, hA, N, 128, 0, 128, 9);
    hgemm_kernel<<<grid(N, 128), gblk, SB>>>(
        hA, nullptr, hW + oM1W2, m1b2, nullptr, nullptr, hB, N, 128, 0, 128, 8);
    // lse1 -> (N,256) half
    lse_mma_kernel<<<lse_grid, lblk>>>(coords, nidx, hB, l1W1, l1b1, l1W2, l1b2, hA, N);
    // p1: 256 -> 256 -> 128
    hgemm_kernel<<<grid(N, 256), gblk, SB>>>(
        hA, nullptr, hW + oP1W1, p1b1, nullptr, nullptr, hC, N, 256, 0, 256, 9);
    hgemm_kernel<<<grid(N, 128), gblk, SB>>>(
        hC, nullptr, hW + oP1W2, p1b2, nullptr, nullptr, hB, N, 256, 0, 128, 8);
    // lse2 -> (N,256) half
    lse_mma_kernel<<<lse_grid, lblk>>>(coords, nidx, hB, l2W1, l2b1, l2W2, l2b2, hA, N);
    // p2: 256 -> 256 -> 256
    hgemm_kernel<<<grid(N, 256), gblk, SB>>>(
        hA, nullptr, hW + oP2W1, p2b1, nullptr, nullptr, hC, N, 256, 0, 256, 9);
    hgemm_kernel<<<grid(N, 256), gblk, SB>>>(
        hC, nullptr, hW + oP2W2, p2b2, nullptr, nullptr, hB, N, 256, 0, 256, 8);
    // m2 hidden: 256 -> 384 (relu, half)
    hgemm_kernel<<<grid(N, 384), gblk, SB>>>(
        hB, nullptr, hW + oM2W1, m2b1, nullptr, nullptr, hA, N, 256, 0, 384, 9);
    // FUSED final: leaky( [m2_hidden | m3_hidden] @ [m2W2; m3W2] + b2 + b3 )
    cudaStreamWaitEvent(0, evM3, 0);
    hgemm_kernel<<<grid(N, 512), gblk, SB>>>(
        hA, hD, hW + oWCAT, m2b2, m3b2, nullptr, out, N, 384, 256, 512, 2);
}

// round 14
// speedup vs baseline: 9.2705x; 1.0007x over previous
#include <cuda_runtime.h>
#include <cuda_fp16.h>
#include <math.h>
#include <stdint.h>

#define NMAX 100000
#define KNBR 16

// Scratch (static __device__ — allocation-guard safe)
__device__ __half g_hA[NMAX * 384];
__device__ __half g_hB[NMAX * 256];
__device__ float  g_bufC[NMAX * 512];
__device__ __half g_hF[NMAX * 128];     // half features
__device__ __half g_hW[720896];         // half transposed weights (incl. [512][640] concat)
__device__ __half g_hD[NMAX * 256];     // m3 hidden (side stream)

__device__ __forceinline__ float to_tf32(float x) {
    float y;
    asm("cvt.rna.tf32.f32 %0, %1;" : "=f"(y) : "f"(x));
    return y;
}

__device__ __forceinline__ uint32_t smem_u32(const void* p) {
    uint32_t a;
    asm("{ .reg .u64 t; cvta.to.shared.u64 t, %1; cvt.u32.u64 %0, t; }"
        : "=r"(a) : "l"(p));
    return a;
}

__device__ __forceinline__ void cp_async16(uint32_t dst, const void* src, int szb) {
    asm volatile("cp.async.cg.shared.global [%0], [%1], 16, %2;"
                 :: "r"(dst), "l"(src), "r"(szb));
}

#define LDSM_X4(r0, r1, r2, r3, addr)                                         \
    asm volatile("ldmatrix.sync.aligned.m8n8.x4.shared.b16 {%0,%1,%2,%3}, [%4];" \
        : "=r"(r0), "=r"(r1), "=r"(r2), "=r"(r3) : "r"(addr))

#define MMA_F16(C, a0, a1, a2, a3, b0, b1)                                    \
    asm volatile(                                                             \
        "mma.sync.aligned.m16n8k16.row.col.f32.f16.f16.f32 "                  \
        "{%0,%1,%2,%3}, {%4,%5,%6,%7}, {%8,%9}, {%0,%1,%2,%3};"               \
        : "+f"((C)[0]), "+f"((C)[1]), "+f"((C)[2]), "+f"((C)[3])              \
        : "r"(a0), "r"(a1), "r"(a2), "r"(a3), "r"(b0), "r"(b1))

#define MMA_TF32(C, a0, a1, a2, a3, b0, b1)                                   \
    asm volatile(                                                             \
        "mma.sync.aligned.m16n8k8.row.col.f32.tf32.tf32.f32 "                 \
        "{%0,%1,%2,%3}, {%4,%5,%6,%7}, {%8,%9}, {%0,%1,%2,%3};"               \
        : "+f"((C)[0]), "+f"((C)[1]), "+f"((C)[2]), "+f"((C)[3])              \
        : "r"(a0), "r"(a1), "r"(a2), "r"(a3), "r"(b0), "r"(b1))

// ---------------------------------------------------------------------------
// Pre-round: weights -> half, transposed to [O][ld] with column offset.
// ---------------------------------------------------------------------------
struct WPackT {
    const float* s[10];
    int Kd[10];
    int Od[10];
    int ld[10];
    int coff[10];
    int off[10];
};

__global__ void round_weightsT_kernel(WPackT p, __half* dst) {
    int m = blockIdx.y;
    int i = blockIdx.x * blockDim.x + threadIdx.x;
    int Kd = p.Kd[m], Od = p.Od[m];
    if (i < Kd * Od) {
        int k = i / Od, o = i % Od;
        dst[p.off[m] + (size_t)o * p.ld[m] + p.coff[m] + k] =
            __float2half_rn(p.s[m][i]);
    }
}

__global__ void round_feat_kernel(const float* __restrict__ src,
                                  __half* __restrict__ dst, int n) {
    int i = blockIdx.x * blockDim.x + threadIdx.x;
    if (i < n) dst[i] = __float2half_rn(src[i]);
}

// ---------------------------------------------------------------------------
// Shared tiling constants
// ---------------------------------------------------------------------------
#define ASTH 40
#define AS_HL (128 * ASTH)
#define OP_B  (AS_HL * 2)
#define STG_B (2 * OP_B)
#define NSTG 4
#define HGEMM_SMEM (NSTG * STG_B)       // 81920
#define SINT 264                        // intermediate smem stride (halves)
#define MLP2_SMEM (NSTG * STG_B + 128 * SINT * 2)   // 149504

// ---------------------------------------------------------------------------
// fp16 tensor-core GEMM (dual-A capable). Same as R13.
// ---------------------------------------------------------------------------
__device__ __forceinline__ void hgemm_issue2(
    const __half* __restrict__ Abase, int strideA, int kloc,
    const __half* __restrict__ Wt, int KW, int kw,
    int M, int bm, int bn, int tid, uint32_t sbase, int stage)
{
    uint32_t so = sbase + stage * STG_B;
#pragma unroll
    for (int i = 0; i < 2; i++) {
        int id = tid + 256 * i;
        int row = id >> 2, cc = id & 3;
        const __half* src = Abase + (size_t)(bm + row) * strideA + kloc + cc * 8;
        cp_async16(so + (row * ASTH + cc * 8) * 2, src, (bm + row) < M ? 16 : 0);
    }
#pragma unroll
    for (int i = 0; i < 2; i++) {
        int id = tid + 256 * i;
        int row = id >> 2, cc = id & 3;
        const __half* src = Wt + (size_t)(bn + row) * KW + kw + cc * 8;
        cp_async16(so + OP_B + (row * ASTH + cc * 8) * 2, src, 16);
    }
    asm volatile("cp.async.commit_group;");
}

__global__ __launch_bounds__(256, 2) void hgemm_kernel(
    const __half* __restrict__ A, const __half* __restrict__ A2,
    const __half* __restrict__ Wt,
    const float* __restrict__ bias, const float* __restrict__ bias2,
    const float* __restrict__ res,
    void* __restrict__ Cout, int M, int K, int K2, int O, int act)
{
    extern __shared__ float dsm[];
    uint32_t sb = smem_u32(dsm);

    int tid = threadIdx.x, lane = tid & 31, wid = tid >> 5;
    int bm = blockIdx.x * 128, bn = blockIdx.y * 128;
    int wm = wid & 1, wn = wid >> 1;
    int gid = lane >> 2, tig = lane & 3;
    bool hout = (act & 8) != 0;
    int actv = act & 3;
    int KW = K + K2;
    int nk1 = K / 32, nk = KW / 32;

    int aRow = wm * 64 + ((lane >> 3) & 1) * 8 + (lane & 7);
    int aCol = (lane >> 4) * 8;
    int bRow = wn * 32 + ((lane >> 4) & 1) * 8 + (lane & 7);
    int bCol = ((lane >> 3) & 1) * 8;
    uint32_t aOff = (uint32_t)(aRow * ASTH + aCol) * 2;
    uint32_t bOff = OP_B + (uint32_t)(bRow * ASTH + bCol) * 2;

    float c[4][4][4];
#pragma unroll
    for (int mt = 0; mt < 4; mt++)
#pragma unroll
        for (int nt = 0; nt < 4; nt++)
#pragma unroll
            for (int q = 0; q < 4; q++) c[mt][nt][q] = 0.f;

    auto issue = [&](int kt, int stage) {
        const __half* Ab; int strA, kloc;
        if (kt < nk1) { Ab = A;  strA = K;  kloc = kt * 32; }
        else          { Ab = A2; strA = K2; kloc = (kt - nk1) * 32; }
        hgemm_issue2(Ab, strA, kloc, Wt, KW, kt * 32, M, bm, bn, tid, sb, stage);
    };

    issue(0, 0);
    issue(1, 1);

    for (int kt = 0; kt < nk; kt++) {
        int s = kt & 3;
        if (kt + 2 < nk) {
            issue(kt + 2, (kt + 2) & 3);
            asm volatile("cp.async.wait_group 2;");
        } else if (kt + 1 < nk) {
            asm volatile("cp.async.wait_group 1;");
        } else {
            asm volatile("cp.async.wait_group 0;");
        }
        __syncthreads();

        uint32_t sAddr = sb + s * STG_B;
#pragma unroll
        for (int ks = 0; ks < 2; ks++) {
            uint32_t kOff = (uint32_t)(ks * 16) * 2;
            uint32_t af[4][4];
#pragma unroll
            for (int mt = 0; mt < 4; mt++)
                LDSM_X4(af[mt][0], af[mt][1], af[mt][2], af[mt][3],
                        sAddr + aOff + (uint32_t)(mt * 16 * ASTH) * 2 + kOff);
            uint32_t bf[4][2];
#pragma unroll
            for (int nt2 = 0; nt2 < 2; nt2++)
                LDSM_X4(bf[2 * nt2][0], bf[2 * nt2][1],
                        bf[2 * nt2 + 1][0], bf[2 * nt2 + 1][1],
                        sAddr + bOff + (uint32_t)(nt2 * 16 * ASTH) * 2 + kOff);
#pragma unroll
            for (int mt = 0; mt < 4; mt++)
#pragma unroll
                for (int nt = 0; nt < 4; nt++)
                    MMA_F16(c[mt][nt], af[mt][0], af[mt][1], af[mt][2],
                            af[mt][3], bf[nt][0], bf[nt][1]);
        }
    }

#pragma unroll
    for (int mt = 0; mt < 4; mt++) {
        int r0 = bm + wm * 64 + mt * 16 + gid;
        int r1 = r0 + 8;
        bool v0 = r0 < M, v1 = r1 < M;
#pragma unroll
        for (int nt = 0; nt < 4; nt++) {
            int col = bn + wn * 32 + nt * 8 + tig * 2;
            float2 bb = *(const float2*)(bias + col);
            if (bias2) {
                float2 b2 = *(const float2*)(bias2 + col);
                bb.x += b2.x; bb.y += b2.y;
            }
            float2 o0 = make_float2(c[mt][nt][0] + bb.x, c[mt][nt][1] + bb.y);
            float2 o1 = make_float2(c[mt][nt][2] + bb.x, c[mt][nt][3] + bb.y);
            if (actv == 1) {
                o0.x = fmaxf(o0.x, 0.f); o0.y = fmaxf(o0.y, 0.f);
                o1.x = fmaxf(o1.x, 0.f); o1.y = fmaxf(o1.y, 0.f);
            } else if (actv == 2) {
                if (res) {
                    if (v0) {
                        float2 r = *(const float2*)(res + (size_t)r0 * O + col);
                        o0.x += r.x; o0.y += r.y;
                    }
                    if (v1) {
                        float2 r = *(const float2*)(res + (size_t)r1 * O + col);
                        o1.x += r.x; o1.y += r.y;
                    }
                }
                o0.x = (o0.x > 0.f) ? o0.x : 0.01f * o0.x;
                o0.y = (o0.y > 0.f) ? o0.y : 0.01f * o0.y;
                o1.x = (o1.x > 0.f) ? o1.x : 0.01f * o1.x;
                o1.y = (o1.y > 0.f) ? o1.y : 0.01f * o1.y;
            }
            if (hout) {
                __half* Ch = (__half*)Cout;
                if (v0) *(__half2*)(Ch + (size_t)r0 * O + col) =
                            __floats2half2_rn(o0.x, o0.y);
                if (v1) *(__half2*)(Ch + (size_t)r1 * O + col) =
                            __floats2half2_rn(o1.x, o1.y);
            } else {
                float* Cf = (float*)Cout;
                if (v0) *(float2*)(Cf + (size_t)r0 * O + col) = o0;
                if (v1) *(float2*)(Cf + (size_t)r1 * O + col) = o1;
            }
        }
    }
}

// ---------------------------------------------------------------------------
// Fused 2-layer MLP: out = (relu(A@W1t^T + b1)) @ W2t^T + b2, half output.
// Layer-1 intermediate lives in smem (128 x SINT half). One CTA = 128 rows.
// O1 in {128,256}, O2 in {128,256}, K1 % 32 == 0. nk per chunk must be 4 or 8
// (last mainloop stage = 3, prologue writes 0/1 -> no stage-reuse hazard).
// ---------------------------------------------------------------------------
__device__ __forceinline__ void mlp2_issueB(
    const __half* __restrict__ W, int strW, int wrow0, int kloc,
    int tid, uint32_t sbase, int stage)
{
    uint32_t so = sbase + stage * STG_B;
#pragma unroll
    for (int i = 0; i < 2; i++) {
        int id = tid + 256 * i;
        int row = id >> 2, cc = id & 3;
        const __half* src = W + (size_t)(wrow0 + row) * strW + kloc + cc * 8;
        cp_async16(so + OP_B + (row * ASTH + cc * 8) * 2, src, 16);
    }
    asm volatile("cp.async.commit_group;");
}

__global__ __launch_bounds__(256, 1) void mlp2_kernel(
    const __half* __restrict__ A,
    const __half* __restrict__ W1t, const float* __restrict__ b1,
    const __half* __restrict__ W2t, const float* __restrict__ b2,
    __half* __restrict__ Cout, int M, int K1, int O1, int O2)
{
    extern __shared__ float dsm[];
    uint32_t sb = smem_u32(dsm);
    __half* Sint = (__half*)((char*)dsm + NSTG * STG_B);
    uint32_t sintu = sb + NSTG * STG_B;

    int tid = threadIdx.x, lane = tid & 31, wid = tid >> 5;
    int bm = blockIdx.x * 128;
    int wm = wid & 1, wn = wid >> 1;
    int gid = lane >> 2, tig = lane & 3;

    int aRow = wm * 64 + ((lane >> 3) & 1) * 8 + (lane & 7);
    int aCol = (lane >> 4) * 8;
    int bRow = wn * 32 + ((lane >> 4) & 1) * 8 + (lane & 7);
    int bCol = ((lane >> 3) & 1) * 8;
    uint32_t aOff = (uint32_t)(aRow * ASTH + aCol) * 2;
    uint32_t bOff = OP_B + (uint32_t)(bRow * ASTH + bCol) * 2;
    uint32_t aOff2 = (uint32_t)(aRow * SINT + aCol) * 2;   // layer2 A from Sint

    // ================= layer 1 =================
    int nk1 = K1 / 32;
    for (int c1 = 0; c1 < O1 / 128; c1++) {
        float c[4][4][4];
#pragma unroll
        for (int mt = 0; mt < 4; mt++)
#pragma unroll
            for (int nt = 0; nt < 4; nt++)
#pragma unroll
                for (int q = 0; q < 4; q++) c[mt][nt][q] = 0.f;

        auto issue1 = [&](int kt, int stage) {
            uint32_t so = sb + stage * STG_B;
            int kloc = kt * 32;
#pragma unroll
            for (int i = 0; i < 2; i++) {
                int id = tid + 256 * i;
                int row = id >> 2, cc = id & 3;
                const __half* src = A + (size_t)(bm + row) * K1 + kloc + cc * 8;
                cp_async16(so + (row * ASTH + cc * 8) * 2, src,
                           (bm + row) < M ? 16 : 0);
            }
#pragma unroll
            for (int i = 0; i < 2; i++) {
                int id = tid + 256 * i;
                int row = id >> 2, cc = id & 3;
                const __half* src =
                    W1t + (size_t)(c1 * 128 + row) * K1 + kloc + cc * 8;
                cp_async16(so + OP_B + (row * ASTH + cc * 8) * 2, src, 16);
            }
            asm volatile("cp.async.commit_group;");
        };

        issue1(0, 0);
        issue1(1, 1);
        for (int kt = 0; kt < nk1; kt++) {
            int s = kt & 3;
            if (kt + 2 < nk1) {
                issue1(kt + 2, (kt + 2) & 3);
                asm volatile("cp.async.wait_group 2;");
            } else if (kt + 1 < nk1) {
                asm volatile("cp.async.wait_group 1;");
            } else {
                asm volatile("cp.async.wait_group 0;");
            }
            __syncthreads();

            uint32_t sAddr = sb + s * STG_B;
#pragma unroll
            for (int ks = 0; ks < 2; ks++) {
                uint32_t kOff = (uint32_t)(ks * 16) * 2;
                uint32_t af[4][4];
#pragma unroll
                for (int mt = 0; mt < 4; mt++)
                    LDSM_X4(af[mt][0], af[mt][1], af[mt][2], af[mt][3],
                            sAddr + aOff + (uint32_t)(mt * 16 * ASTH) * 2 + kOff);
                uint32_t bf[4][2];
#pragma unroll
                for (int nt2 = 0; nt2 < 2; nt2++)
                    LDSM_X4(bf[2 * nt2][0], bf[2 * nt2][1],
                            bf[2 * nt2 + 1][0], bf[2 * nt2 + 1][1],
                            sAddr + bOff + (uint32_t)(nt2 * 16 * ASTH) * 2 + kOff);
#pragma unroll
                for (int mt = 0; mt < 4; mt++)
#pragma unroll
                    for (int nt = 0; nt < 4; nt++)
                        MMA_F16(c[mt][nt], af[mt][0], af[mt][1], af[mt][2],
                                af[mt][3], bf[nt][0], bf[nt][1]);
            }
        }

        // epilogue -> Sint (relu + bias, half)
#pragma unroll
        for (int mt = 0; mt < 4; mt++) {
            int lr0 = wm * 64 + mt * 16 + gid;
            int lr1 = lr0 + 8;
#pragma unroll
            for (int nt = 0; nt < 4; nt++) {
                int col = c1 * 128 + wn * 32 + nt * 8 + tig * 2;
                float2 bb = *(const float2*)(b1 + col);
                float o00 = fmaxf(c[mt][nt][0] + bb.x, 0.f);
                float o01 = fmaxf(c[mt][nt][1] + bb.y, 0.f);
                float o10 = fmaxf(c[mt][nt][2] + bb.x, 0.f);
                float o11 = fmaxf(c[mt][nt][3] + bb.y, 0.f);
                *(__half2*)(Sint + lr0 * SINT + col) = __floats2half2_rn(o00, o01);
                *(__half2*)(Sint + lr1 * SINT + col) = __floats2half2_rn(o10, o11);
            }
        }
        __syncthreads();
    }

    // ================= layer 2 =================
    int nk2 = O1 / 32;
    for (int c2 = 0; c2 < O2 / 128; c2++) {
        float c[4][4][4];
#pragma unroll
        for (int mt = 0; mt < 4; mt++)
#pragma unroll
            for (int nt = 0; nt < 4; nt++)
#pragma unroll
                for (int q = 0; q < 4; q++) c[mt][nt][q] = 0.f;

        mlp2_issueB(W2t, O1, c2 * 128, 0, tid, sb, 0);
        mlp2_issueB(W2t, O1, c2 * 128, 32, tid, sb, 1);
        for (int kt = 0; kt < nk2; kt++) {
            int s = kt & 3;
            if (kt + 2 < nk2) {
                mlp2_issueB(W2t, O1, c2 * 128, (kt + 2) * 32, tid, sb, (kt + 2) & 3);
                asm volatile("cp.async.wait_group 2;");
            } else if (kt + 1 < nk2) {
                asm volatile("cp.async.wait_group 1;");
            } else {
                asm volatile("cp.async.wait_group 0;");
            }
            __syncthreads();

            uint32_t sAddr = sb + s * STG_B;
#pragma unroll
            for (int ks = 0; ks < 2; ks++) {
                uint32_t kBase = (uint32_t)(kt * 32 + ks * 16) * 2;
                uint32_t af[4][4];
#pragma unroll
                for (int mt = 0; mt < 4; mt++)
                    LDSM_X4(af[mt][0], af[mt][1], af[mt][2], af[mt][3],
                            sintu + aOff2 + (uint32_t)(mt * 16 * SINT) * 2 + kBase);
                uint32_t kOff = (uint32_t)(ks * 16) * 2;
                uint32_t bf[4][2];
#pragma unroll
                for (int nt2 = 0; nt2 < 2; nt2++)
                    LDSM_X4(bf[2 * nt2][0], bf[2 * nt2][1],
                            bf[2 * nt2 + 1][0], bf[2 * nt2 + 1][1],
                            sAddr + bOff + (uint32_t)(nt2 * 16 * ASTH) * 2 + kOff);
#pragma unroll
                for (int mt = 0; mt < 4; mt++)
#pragma unroll
                    for (int nt = 0; nt < 4; nt++)
                        MMA_F16(c[mt][nt], af[mt][0], af[mt][1], af[mt][2],
                                af[mt][3], bf[nt][0], bf[nt][1]);
            }
        }

        // epilogue -> gmem half (no activation)
#pragma unroll
        for (int mt = 0; mt < 4; mt++) {
            int r0 = bm + wm * 64 + mt * 16 + gid;
            int r1 = r0 + 8;
            bool v0 = r0 < M, v1 = r1 < M;
#pragma unroll
            for (int nt = 0; nt < 4; nt++) {
                int col = c2 * 128 + wn * 32 + nt * 8 + tig * 2;
                float2 bb = *(const float2*)(b2 + col);
                if (v0)
                    *(__half2*)(Cout + (size_t)r0 * O2 + col) =
                        __floats2half2_rn(c[mt][nt][0] + bb.x,
                                          c[mt][nt][1] + bb.y);
                if (v1)
                    *(__half2*)(Cout + (size_t)r1 * O2 + col) =
                        __floats2half2_rn(c[mt][nt][2] + bb.x,
                                          c[mt][nt][3] + bb.y);
            }
        }
        __syncthreads();
    }
}

// ---------------------------------------------------------------------------
// LSE + attentive pool (tf32 mma core, half feats in / half out). Unchanged.
// ---------------------------------------------------------------------------
#define LSTR 136

__global__ __launch_bounds__(256) void lse_mma_kernel(
    const float* __restrict__ coords, const int* __restrict__ nidx,
    const __half* __restrict__ feats,
    const float* __restrict__ W1, const float* __restrict__ B1,
    const float* __restrict__ W2, const float* __restrict__ B2,
    __half* __restrict__ outF, int N)
{
    __shared__ float sW1[640];
    __shared__ float sB1[64];
    __shared__ float sB2[128];
    __shared__ float sW2[64 * LSTR];

    int tid = threadIdx.x, lane = tid & 31, wid = tid >> 5;
    int gid = lane >> 2, tig = lane & 3;

    for (int i = tid; i < 640; i += 256) sW1[i] = W1[i];
    if (tid < 64) sB1[tid] = B1[tid];
    if (tid < 128) sB2[tid] = B2[tid];
    for (int i = tid; i < 8192; i += 256) {
        int k = i >> 7, ch = i & 127;
        sW2[k * LSTR + ch] = to_tf32(W2[i]);
    }
    __syncthreads();

    int nbase = blockIdx.x * 64 + wid * 8;
    for (int p = 0; p < 8; p++) {
        int n = nbase + p;
        if (n >= N) break;

        int ib0 = nidx[n * KNBR + gid];
        int ib1 = nidx[n * KNBR + gid + 8];
        float ox = coords[n * 3], oy = coords[n * 3 + 1], oz = coords[n * 3 + 2];
        float ax = coords[ib0 * 3], ay = coords[ib0 * 3 + 1], az = coords[ib0 * 3 + 2];
        float bx = coords[ib1 * 3], by = coords[ib1 * 3 + 1], bz = coords[ib1 * 3 + 2];
        float arx = ox - ax, ary = oy - ay, arz = oz - az;
        float brx = ox - bx, bry = oy - by, brz = oz - bz;
        float ad = sqrtf(arx * arx + ary * ary + arz * arz);
        float bd = sqrtf(brx * brx + bry * bry + brz * brz);
        float ca[10] = {ox, oy, oz, ax, ay, az, arx, ary, arz, ad};
        float cb[10] = {ox, oy, oz, bx, by, bz, brx, bry, brz, bd};

        uint32_t hb0[16], hb1[16];
#pragma unroll
        for (int j = 0; j < 16; j++) {
            int ch = tig + 4 * j;
            float h0 = sB1[ch], h1 = h0;
#pragma unroll
            for (int i = 0; i < 10; i++) {
                float w = sW1[i * 64 + ch];
                h0 = fmaf(ca[i], w, h0);
                h1 = fmaf(cb[i], w, h1);
            }
            hb0[j] = __float_as_uint(to_tf32(fmaxf(h0, 0.f)));
            hb1[j] = __float_as_uint(to_tf32(fmaxf(h1, 0.f)));
        }

        float c_[8][2][4];
#pragma unroll
        for (int mt = 0; mt < 8; mt++)
#pragma unroll
            for (int nt = 0; nt < 2; nt++)
#pragma unroll
                for (int q = 0; q < 4; q++) c_[mt][nt][q] = 0.f;

#pragma unroll
        for (int s = 0; s < 8; s++) {
            uint32_t b00 = hb0[2 * s], b01 = hb0[2 * s + 1];
            uint32_t b10 = hb1[2 * s], b11 = hb1[2 * s + 1];
            const float* r0 = &sW2[(8 * s + tig) * LSTR];
            const float* r1 = &sW2[(8 * s + tig + 4) * LSTR];
#pragma unroll
            for (int mt = 0; mt < 8; mt++) {
                int cb0 = 16 * mt + gid;
                uint32_t a0 = __float_as_uint(r0[cb0]);
                uint32_t a1 = __float_as_uint(r0[cb0 + 8]);
                uint32_t a2 = __float_as_uint(r1[cb0]);
                uint32_t a3 = __float_as_uint(r1[cb0 + 8]);
                MMA_TF32(c_[mt][0], a0, a1, a2, a3, b00, b01);
                MMA_TF32(c_[mt][1], a0, a1, a2, a3, b10, b11);
            }
        }

#pragma unroll
        for (int mt = 0; mt < 8; mt++) {
            float bb0 = sB2[16 * mt + gid], bb1 = sB2[16 * mt + gid + 8];
#pragma unroll
            for (int nt = 0; nt < 2; nt++) {
                c_[mt][nt][0] += bb0; c_[mt][nt][1] += bb0;
                c_[mt][nt][2] += bb1; c_[mt][nt][3] += bb1;
            }
        }

        const __half2* fp = (const __half2*)(feats + (size_t)n * 128);
        __half2 p0 = fp[2 * lane], p1 = fp[2 * lane + 1];
        float4 f4 = make_float4(__low2float(p0), __high2float(p0),
                                __low2float(p1), __high2float(p1));
        float ef[4] = {__expf(f4.x), __expf(f4.y), __expf(f4.z), __expf(f4.w)};
        float sf = ef[0] + ef[1] + ef[2] + ef[3];
#pragma unroll
        for (int o = 16; o > 0; o >>= 1)
            sf += __shfl_xor_sync(0xffffffffu, sf, o);

        float ov[8][2];
#pragma unroll
        for (int mt = 0; mt < 8; mt++) { ov[mt][0] = 0.f; ov[mt][1] = 0.f; }
        float Tl = 0.f;

#pragma unroll
        for (int j = 0; j < 4; j++) {
            int nt = j >> 1, q = j & 1;
            float e0[8], e1[8], s = 0.f;
#pragma unroll
            for (int mt = 0; mt < 8; mt++) {
                e0[mt] = __expf(c_[mt][nt][q]);
                e1[mt] = __expf(c_[mt][nt][q + 2]);
                s += e0[mt] + e1[mt];
            }
#pragma unroll
            for (int o = 4; o <= 16; o <<= 1)
                s += __shfl_xor_sync(0xffffffffu, s, o);
            float inv = 1.f / (s + sf);
            Tl += inv;
#pragma unroll
            for (int mt = 0; mt < 8; mt++) {
                ov[mt][0] = fmaf(e0[mt] * inv, c_[mt][nt][q], ov[mt][0]);
                ov[mt][1] = fmaf(e1[mt] * inv, c_[mt][nt][q + 2], ov[mt][1]);
            }
        }
        Tl += __shfl_xor_sync(0xffffffffu, Tl, 1);
        Tl += __shfl_xor_sync(0xffffffffu, Tl, 2);

#pragma unroll
        for (int mt = 0; mt < 8; mt++) {
#pragma unroll
            for (int cs = 0; cs < 2; cs++) {
                ov[mt][cs] += __shfl_xor_sync(0xffffffffu, ov[mt][cs], 1);
                ov[mt][cs] += __shfl_xor_sync(0xffffffffu, ov[mt][cs], 2);
            }
        }

        __half* po = outF + (size_t)n * 256;
#pragma unroll
        for (int t = 0; t < 2; t++) {
            int mt = 2 * tig + t;
            po[16 * mt + gid]     = __float2half_rn(ov[mt][0]);
            po[16 * mt + gid + 8] = __float2half_rn(ov[mt][1]);
        }
        __half2* gp = (__half2*)(po + 128 + 4 * lane);
        gp[0] = __floats2half2_rn(f4.x * ef[0] * Tl, f4.y * ef[1] * Tl);
        gp[1] = __floats2half2_rn(f4.z * ef[2] * Tl, f4.w * ef[3] * Tl);
    }
}

// ---------------------------------------------------------------------------
extern "C" void kernel_launch(void* const* d_in, const int* in_sizes, int n_in,
                              void* d_out, int out_size)
{
    const float* coords   = (const float*)d_in[0];
    const float* features = (const float*)d_in[1];
    const int*   nidx     = (const int*)d_in[2];
    const float* m1W1 = (const float*)d_in[3];  const float* m1b1 = (const float*)d_in[4];
    const float* m1W2 = (const float*)d_in[5];  const float* m1b2 = (const float*)d_in[6];
    const float* m2W1 = (const float*)d_in[7];  const float* m2b1 = (const float*)d_in[8];
    const float* m2W2 = (const float*)d_in[9];  const float* m2b2 = (const float*)d_in[10];
    const float* m3W1 = (const float*)d_in[11]; const float* m3b1 = (const float*)d_in[12];
    const float* m3W2 = (const float*)d_in[13]; const float* m3b2 = (const float*)d_in[14];
    const float* l1W1 = (const float*)d_in[15]; const float* l1b1 = (const float*)d_in[16];
    const float* l1W2 = (const float*)d_in[17]; const float* l1b2 = (const float*)d_in[18];
    const float* l2W1 = (const float*)d_in[19]; const float* l2b1 = (const float*)d_in[20];
    const float* l2W2 = (const float*)d_in[21]; const float* l2b2 = (const float*)d_in[22];
    const float* p1W1 = (const float*)d_in[23]; const float* p1b1 = (const float*)d_in[24];
    const float* p1W2 = (const float*)d_in[25]; const float* p1b2 = (const float*)d_in[26];
    const float* p2W1 = (const float*)d_in[27]; const float* p2b1 = (const float*)d_in[28];
    const float* p2W2 = (const float*)d_in[29]; const float* p2b2 = (const float*)d_in[30];
    float* out = (float*)d_out;

    int N = in_sizes[0] / 3;

    __half *hA, *hB, *hF, *hW, *hD;
    float* bufC;
    cudaGetSymbolAddress((void**)&hA, g_hA);
    cudaGetSymbolAddress((void**)&hB, g_hB);
    cudaGetSymbolAddress((void**)&bufC, g_bufC);
    cudaGetSymbolAddress((void**)&hF, g_hF);
    cudaGetSymbolAddress((void**)&hW, g_hW);
    cudaGetSymbolAddress((void**)&hD, g_hD);

    static cudaStream_t s2 = nullptr;
    static cudaEvent_t ev0 = nullptr, evW = nullptr, evF = nullptr, evM3 = nullptr;
    if (!s2) {
        cudaFuncSetAttribute(hgemm_kernel,
                             cudaFuncAttributeMaxDynamicSharedMemorySize,
                             HGEMM_SMEM);
        cudaFuncSetAttribute(mlp2_kernel,
                             cudaFuncAttributeMaxDynamicSharedMemorySize,
                             MLP2_SMEM);
        cudaStreamCreateWithFlags(&s2, cudaStreamNonBlocking);
        cudaEventCreateWithFlags(&ev0, cudaEventDisableTiming);
        cudaEventCreateWithFlags(&evW, cudaEventDisableTiming);
        cudaEventCreateWithFlags(&evF, cudaEventDisableTiming);
        cudaEventCreateWithFlags(&evM3, cudaEventDisableTiming);
    }

    // Weight layout in g_hW (halves):
    const int oM1W1 = 0;        // 128x128
    const int oM1W2 = 16384;    // 128x128
    const int oM2W1 = 32768;    // 384x256
    const int oM3W1 = 131072;   // 256x128
    const int oP1W1 = 163840;   // 256x256
    const int oP1W2 = 229376;   // 128x256
    const int oP2W1 = 262144;   // 256x256
    const int oP2W2 = 327680;   // 256x256
    const int oWCAT = 393216;   // 512x640  ([m2W2 | m3W2] per output row)

    WPackT wp;
    auto setw = [&](int i, const float* s, int Kd, int Od, int ld, int coff, int off) {
        wp.s[i] = s; wp.Kd[i] = Kd; wp.Od[i] = Od;
        wp.ld[i] = ld; wp.coff[i] = coff; wp.off[i] = off;
    };
    setw(0, m1W1, 128, 128, 128, 0, oM1W1);
    setw(1, m1W2, 128, 128, 128, 0, oM1W2);
    setw(2, m2W1, 256, 384, 256, 0, oM2W1);
    setw(3, m2W2, 384, 512, 640, 0, oWCAT);
    setw(4, m3W1, 128, 256, 128, 0, oM3W1);
    setw(5, m3W2, 256, 512, 640, 384, oWCAT);
    setw(6, p1W1, 256, 256, 256, 0, oP1W1);
    setw(7, p1W2, 256, 128, 256, 0, oP1W2);
    setw(8, p2W1, 256, 256, 256, 0, oP2W1);
    setw(9, p2W2, 256, 256, 256, 0, oP2W2);

    dim3 gblk(256), lblk(256);
    auto grid = [&](int M, int O) { return dim3((M + 127) / 128, O / 128); };
    dim3 mgrid((N + 127) / 128, 1);
    int lse_grid = (N + 63) / 64;
    int SB = HGEMM_SMEM;

    // ---- fork: weights round on s2, features round on legacy ----
    cudaEventRecord(ev0, 0);
    cudaStreamWaitEvent(s2, ev0, 0);
    round_weightsT_kernel<<<dim3(192, 10), 1024, 0, s2>>>(wp, hW);
    cudaEventRecord(evW, s2);

    round_feat_kernel<<<(N * 128 + 1023) / 1024, 1024>>>(features, hF, N * 128);
    cudaEventRecord(evF, 0);

    // ---- side stream: m3 hidden only (features -> 256 half) ----
    cudaStreamWaitEvent(s2, evF, 0);
    hgemm_kernel<<<grid(N, 256), gblk, SB, s2>>>(
        hF, nullptr, hW + oM3W1, m3b1, nullptr, nullptr, hD, N, 128, 0, 256, 9);
    cudaEventRecord(evM3, s2);

    // ---- main chain (legacy stream), waits for weights ----
    cudaStreamWaitEvent(0, evW, 0);
    // m1 fused: 128 -> relu 128 -> 128 (half)
    mlp2_kernel<<<mgrid, gblk, MLP2_SMEM>>>(
        hF, hW + oM1W1, m1b1, hW + oM1W2, m1b2, hB, N, 128, 128, 128);
    // lse1 -> (N,256) half
    lse_mma_kernel<<<lse_grid, lblk>>>(coords, nidx, hB, l1W1, l1b1, l1W2, l1b2, hA, N);
    // p1 fused: 256 -> relu 256 -> 128 (half)
    mlp2_kernel<<<mgrid, gblk, MLP2_SMEM>>>(
        hA, hW + oP1W1, p1b1, hW + oP1W2, p1b2, hB, N, 256, 256, 128);
    // lse2 -> (N,256) half
    lse_mma_kernel<<<lse_grid, lblk>>>(coords, nidx, hB, l2W1, l2b1, l2W2, l2b2, hA, N);
    // p2 fused: 256 -> relu 256 -> 256 (half)
    mlp2_kernel<<<mgrid, gblk, MLP2_SMEM>>>(
        hA, hW + oP2W1, p2b1, hW + oP2W2, p2b2, hB, N, 256, 256, 256);
    // m2 hidden: 256 -> 384 (relu, half)
    hgemm_kernel<<<grid(N, 384), gblk, SB>>>(
        hB, nullptr, hW + oM2W1, m2b1, nullptr, nullptr, hA, N, 256, 0, 384, 9);
    // FUSED final: leaky( [m2_hidden | m3_hidden] @ [m2W2; m3W2] + b2 + b3 )
    cudaStreamWaitEvent(0, evM3, 0);
    hgemm_kernel<<<grid(N, 512), gblk, SB>>>(
        hA, hD, hW + oWCAT, m2b2, m3b2, nullptr, out, N, 384, 256, 512, 2);
}